// round 1
// baseline (speedup 1.0000x reference)
#include <cuda_runtime.h>
#include <math.h>

// Problem dims
#define BB   2
#define SS   1024
#define DD   1024
#define HH   16
#define DKK  64
#define HDD  1024     // H*DK = H*DV
#define FF   4096
#define LL   4
#define MR   (BB*SS)  // 2048 rows

// -------------------- scratch (device globals; no allocation) --------------------
__device__ float g_x  [MR * DD];            // activations
__device__ float g_q  [MR * HDD];
__device__ float g_k  [MR * HDD];
__device__ float g_v  [MR * HDD];
__device__ float g_sc [(size_t)BB * HH * SS * SS];  // scores/attn, 128 MB
__device__ float g_ctx[MR * HDD];
__device__ float g_tmp[MR * DD];
__device__ float g_ffh[MR * FF];

// -------------------- block reductions --------------------
__device__ __forceinline__ float block_sum(float v, float* sh) {
    __syncthreads();  // protect sh reuse across calls
    #pragma unroll
    for (int o = 16; o > 0; o >>= 1) v += __shfl_xor_sync(0xffffffffu, v, o);
    int w = threadIdx.x >> 5;
    if ((threadIdx.x & 31) == 0) sh[w] = v;
    __syncthreads();
    float t = (threadIdx.x < 8) ? sh[threadIdx.x] : 0.0f;
    #pragma unroll
    for (int o = 4; o > 0; o >>= 1) t += __shfl_xor_sync(0xffffffffu, t, o);
    if (threadIdx.x == 0) sh[0] = t;
    __syncthreads();
    return sh[0];
}

__device__ __forceinline__ float block_max(float v, float* sh) {
    __syncthreads();
    #pragma unroll
    for (int o = 16; o > 0; o >>= 1) v = fmaxf(v, __shfl_xor_sync(0xffffffffu, v, o));
    int w = threadIdx.x >> 5;
    if ((threadIdx.x & 31) == 0) sh[w] = v;
    __syncthreads();
    float t = (threadIdx.x < 8) ? sh[threadIdx.x] : -3.0e38f;
    #pragma unroll
    for (int o = 4; o > 0; o >>= 1) t = fmaxf(t, __shfl_xor_sync(0xffffffffu, t, o));
    if (threadIdx.x == 0) sh[0] = t;
    __syncthreads();
    return sh[0];
}

// -------------------- embedding + sinusoidal posenc --------------------
__global__ __launch_bounds__(256) void embed_kernel(
    const int* __restrict__ tok, const float* __restrict__ emb, float* __restrict__ x)
{
    int row = blockIdx.x;          // 0..MR-1
    int s = row % SS;
    int t = tok[row];
    const float* e = emb + (long)t * DD;
    float* xo = x + (long)row * DD;
    for (int d = threadIdx.x; d < DD; d += 256) {
        int i = d >> 1;
        float freq = expf(-((float)(2 * i) / (float)DD) * 9.210340371976184f); // ln(10000)
        float a = (float)s * freq;
        float pe = (d & 1) ? cosf(a) : sinf(a);
        xo[d] = e[d] + pe;
    }
}

// -------------------- generic NN GEMM: C = act(A @ W + bias) --------------------
// Tile 64x64, K-step 16, 256 threads, 4x4 per thread. Dims must be multiples of 64/16.
__global__ __launch_bounds__(256) void gemm_nn(
    const float* __restrict__ A, int lda,
    const float* __restrict__ W, int ldb,
    const float* __restrict__ bias,
    float* __restrict__ C, int ldc,
    int K, int act)
{
    __shared__ float As[16][68];
    __shared__ float Bs[16][68];
    const int tid = threadIdx.x;
    const int tx = tid & 15, ty = tid >> 4;
    const int row0 = blockIdx.y * 64;
    const int col0 = blockIdx.x * 64;

    const int am = tid >> 4;   // 0..15
    const int ak = tid & 15;
    const int bn = tid & 63;
    const int bkk = tid >> 6;  // 0..3

    float acc[4][4] = {{0.f,0.f,0.f,0.f},{0.f,0.f,0.f,0.f},{0.f,0.f,0.f,0.f},{0.f,0.f,0.f,0.f}};

    for (int k0 = 0; k0 < K; k0 += 16) {
        #pragma unroll
        for (int p = 0; p < 4; p++) {
            As[ak][am + p * 16]  = A[(long)(row0 + am + p * 16) * lda + k0 + ak];
            Bs[bkk + p * 4][bn]  = W[(long)(k0 + bkk + p * 4) * ldb + col0 + bn];
        }
        __syncthreads();
        #pragma unroll
        for (int kk = 0; kk < 16; kk++) {
            float ar[4], br[4];
            #pragma unroll
            for (int i = 0; i < 4; i++) ar[i] = As[kk][ty * 4 + i];
            #pragma unroll
            for (int j = 0; j < 4; j++) br[j] = Bs[kk][tx * 4 + j];
            #pragma unroll
            for (int i = 0; i < 4; i++)
                #pragma unroll
                for (int j = 0; j < 4; j++)
                    acc[i][j] = fmaf(ar[i], br[j], acc[i][j]);
        }
        __syncthreads();
    }

    #pragma unroll
    for (int i = 0; i < 4; i++) {
        int r = row0 + ty * 4 + i;
        #pragma unroll
        for (int j = 0; j < 4; j++) {
            int c = col0 + tx * 4 + j;
            float v = acc[i][j];
            if (bias) v += bias[c];
            if (act == 1) v = 0.5f * v * (1.0f + erff(v * 0.70710678118654752f)); // exact GELU
            C[(long)r * ldc + c] = v;
        }
    }
}

// -------------------- attention scores: S = scale * Q @ K^T (per batch-head) --------------------
// DK=64 fits in one shared pass. Grid: (S/64, S/64, B*H).
__global__ __launch_bounds__(256) void attn_scores(
    const float* __restrict__ q, const float* __restrict__ k, float* __restrict__ sc)
{
    int z = blockIdx.z;            // b*H + h
    int b = z >> 4, h = z & 15;
    int q0 = blockIdx.y * 64;
    int k0 = blockIdx.x * 64;
    const float* Q  = q + (long)b * SS * HDD + h * DKK;
    const float* Kp = k + (long)b * SS * HDD + h * DKK;
    float* S = sc + (long)z * SS * SS;

    __shared__ float Qs[64][65];
    __shared__ float Ks[64][65];
    int tid = threadIdx.x;
    #pragma unroll
    for (int p = 0; p < 16; p++) {
        int idx = tid + p * 256;
        int m = idx >> 6, d = idx & 63;
        Qs[m][d] = Q[(long)(q0 + m) * HDD + d];
        Ks[m][d] = Kp[(long)(k0 + m) * HDD + d];
    }
    __syncthreads();

    int tx = tid & 15, ty = tid >> 4;
    float acc[4][4] = {{0.f,0.f,0.f,0.f},{0.f,0.f,0.f,0.f},{0.f,0.f,0.f,0.f},{0.f,0.f,0.f,0.f}};
    #pragma unroll 8
    for (int kk = 0; kk < 64; kk++) {
        float ar[4], br[4];
        #pragma unroll
        for (int i = 0; i < 4; i++) ar[i] = Qs[ty * 4 + i][kk];
        #pragma unroll
        for (int j = 0; j < 4; j++) br[j] = Ks[tx * 4 + j][kk];
        #pragma unroll
        for (int i = 0; i < 4; i++)
            #pragma unroll
            for (int j = 0; j < 4; j++)
                acc[i][j] = fmaf(ar[i], br[j], acc[i][j]);
    }
    const float scale = 0.125f;  // 1/sqrt(64)
    #pragma unroll
    for (int i = 0; i < 4; i++)
        #pragma unroll
        for (int j = 0; j < 4; j++)
            S[(long)(q0 + ty * 4 + i) * SS + (k0 + tx * 4 + j)] = acc[i][j] * scale;
}

// -------------------- masked softmax over each score row (in place) --------------------
__global__ __launch_bounds__(256) void softmax_mask(
    float* __restrict__ sc, const int* __restrict__ tok)
{
    long row = blockIdx.x;               // z*SS + qi, z = b*H+h
    int z = (int)(row >> 10);
    int b = z >> 4;
    float* S = sc + row * SS;
    const int* tb = tok + (long)b * SS;
    int tid = threadIdx.x;
    __shared__ float red[8];

    float v[4];
    float mx = -3.0e38f;
    #pragma unroll
    for (int j = 0; j < 4; j++) {
        int idx = tid + j * 256;
        float s = S[idx];
        if (tb[idx] == 0) s = -1e9f;     // PAD mask at key position
        v[j] = s;
        mx = fmaxf(mx, s);
    }
    mx = block_max(mx, red);
    float sum = 0.f;
    #pragma unroll
    for (int j = 0; j < 4; j++) { v[j] = expf(v[j] - mx); sum += v[j]; }
    sum = block_sum(sum, red);
    float inv = 1.0f / sum;
    #pragma unroll
    for (int j = 0; j < 4; j++) S[tid + j * 256] = v[j] * inv;
}

// -------------------- context: ctx = attn @ V (per batch-head), output [B,S,H*DV] --------------------
// Grid: (S/64, B*H)
__global__ __launch_bounds__(256) void attn_ctx(
    const float* __restrict__ sc, const float* __restrict__ v, float* __restrict__ ctx)
{
    int z = blockIdx.y;
    int b = z >> 4, h = z & 15;
    int q0 = blockIdx.x * 64;
    const float* A = sc + (long)z * SS * SS;
    const float* V = v   + (long)b * SS * HDD + h * DKK;
    float*       O = ctx + (long)b * SS * HDD + h * DKK;

    __shared__ float As[64][65];
    __shared__ float Vs[64][65];
    int tid = threadIdx.x;
    int tx = tid & 15, ty = tid >> 4;
    float acc[4][4] = {{0.f,0.f,0.f,0.f},{0.f,0.f,0.f,0.f},{0.f,0.f,0.f,0.f},{0.f,0.f,0.f,0.f}};

    for (int c0 = 0; c0 < SS; c0 += 64) {
        #pragma unroll
        for (int p = 0; p < 16; p++) {
            int idx = tid + p * 256;
            int m = idx >> 6, d = idx & 63;
            As[m][d] = A[(long)(q0 + m) * SS + c0 + d];
            Vs[m][d] = V[(long)(c0 + m) * HDD + d];
        }
        __syncthreads();
        #pragma unroll 8
        for (int kk = 0; kk < 64; kk++) {
            float ar[4], br[4];
            #pragma unroll
            for (int i = 0; i < 4; i++) ar[i] = As[ty * 4 + i][kk];
            #pragma unroll
            for (int j = 0; j < 4; j++) br[j] = Vs[kk][tx * 4 + j];
            #pragma unroll
            for (int i = 0; i < 4; i++)
                #pragma unroll
                for (int j = 0; j < 4; j++)
                    acc[i][j] = fmaf(ar[i], br[j], acc[i][j]);
        }
        __syncthreads();
    }
    #pragma unroll
    for (int i = 0; i < 4; i++)
        #pragma unroll
        for (int j = 0; j < 4; j++)
            O[(long)(q0 + ty * 4 + i) * HDD + (tx * 4 + j)] = acc[i][j];
}

// -------------------- fused residual add + LayerNorm --------------------
__global__ __launch_bounds__(256) void add_ln(
    const float* __restrict__ xin, const float* __restrict__ delta,
    const float* __restrict__ g, const float* __restrict__ bta,
    float* __restrict__ out)
{
    long row = blockIdx.x;
    const float* xr = xin   + row * DD;
    const float* dr = delta + row * DD;
    float* o = out + row * DD;
    int tid = threadIdx.x;
    __shared__ float red[8];

    float v[4];
    float s = 0.f;
    #pragma unroll
    for (int j = 0; j < 4; j++) {
        int c = tid + j * 256;
        v[j] = xr[c] + dr[c];
        s += v[j];
    }
    s = block_sum(s, red);
    float mu = s * (1.0f / 1024.0f);
    float var = 0.f;
    #pragma unroll
    for (int j = 0; j < 4; j++) { float t = v[j] - mu; var += t * t; }
    var = block_sum(var, red) * (1.0f / 1024.0f);
    float inv = rsqrtf(var + 1e-5f);
    #pragma unroll
    for (int j = 0; j < 4; j++) {
        int c = tid + j * 256;
        o[c] = (v[j] - mu) * inv * g[c] + bta[c];
    }
}

// -------------------- host orchestration --------------------
extern "C" void kernel_launch(void* const* d_in, const int* in_sizes, int n_in,
                              void* d_out, int out_size)
{
    (void)in_sizes; (void)n_in; (void)out_size;
    const int*   tok  = (const int*)  d_in[0];
    const float* emb  = (const float*)d_in[1];
    const float* Wq   = (const float*)d_in[2];
    const float* bq   = (const float*)d_in[3];
    const float* Wk   = (const float*)d_in[4];
    const float* bk   = (const float*)d_in[5];
    const float* Wv   = (const float*)d_in[6];
    const float* bv   = (const float*)d_in[7];
    const float* Wo   = (const float*)d_in[8];
    const float* bo   = (const float*)d_in[9];
    const float* ln1g = (const float*)d_in[10];
    const float* ln1b = (const float*)d_in[11];
    const float* W1   = (const float*)d_in[12];
    const float* W2   = (const float*)d_in[13];
    const float* ln2g = (const float*)d_in[14];
    const float* ln2b = (const float*)d_in[15];
    float* out = (float*)d_out;

    float *x, *q, *k, *v, *sc, *ctx, *tmp, *ffh;
    cudaGetSymbolAddress((void**)&x,   g_x);
    cudaGetSymbolAddress((void**)&q,   g_q);
    cudaGetSymbolAddress((void**)&k,   g_k);
    cudaGetSymbolAddress((void**)&v,   g_v);
    cudaGetSymbolAddress((void**)&sc,  g_sc);
    cudaGetSymbolAddress((void**)&ctx, g_ctx);
    cudaGetSymbolAddress((void**)&tmp, g_tmp);
    cudaGetSymbolAddress((void**)&ffh, g_ffh);

    embed_kernel<<<MR, 256>>>(tok, emb, x);

    dim3 gProj(HDD / 64, MR / 64);    // 16 x 32
    dim3 gF1(FF / 64, MR / 64);       // 64 x 32
    dim3 gF2(DD / 64, MR / 64);       // 16 x 32
    dim3 gSc(SS / 64, SS / 64, BB * HH);
    dim3 gCtx(SS / 64, BB * HH);

    for (int l = 0; l < LL; l++) {
        const float* wq = Wq + (long)l * DD * HDD;
        const float* wk = Wk + (long)l * DD * HDD;
        const float* wv = Wv + (long)l * DD * HDD;
        const float* wo = Wo + (long)l * HDD * DD;
        const float* w1 = W1 + (long)l * DD * FF;
        const float* w2 = W2 + (long)l * FF * DD;

        gemm_nn<<<gProj, 256>>>(x, DD, wq, HDD, bq + (long)l * HDD, q, HDD, DD, 0);
        gemm_nn<<<gProj, 256>>>(x, DD, wk, HDD, bk + (long)l * HDD, k, HDD, DD, 0);
        gemm_nn<<<gProj, 256>>>(x, DD, wv, HDD, bv + (long)l * HDD, v, HDD, DD, 0);

        attn_scores<<<gSc, 256>>>(q, k, sc);
        softmax_mask<<<BB * HH * SS, 256>>>(sc, tok);
        attn_ctx<<<gCtx, 256>>>(sc, v, ctx);

        gemm_nn<<<gProj, 256>>>(ctx, HDD, wo, DD, bo + (long)l * DD, tmp, DD, HDD, 0);
        add_ln<<<MR, 256>>>(x, tmp, ln1g + (long)l * DD, ln1b + (long)l * DD, x);

        gemm_nn<<<gF1, 256>>>(x, DD, w1, FF, (const float*)nullptr, ffh, FF, DD, 1);
        gemm_nn<<<gF2, 256>>>(ffh, FF, w2, DD, (const float*)nullptr, tmp, DD, FF, 0);

        float* dst = (l == LL - 1) ? out : x;
        add_ln<<<MR, 256>>>(x, tmp, ln2g + (long)l * DD, ln2b + (long)l * DD, dst);
    }
}

// round 3
// speedup vs baseline: 1.8908x; 1.8908x over previous
#include <cuda_runtime.h>
#include <cuda_bf16.h>
#include <math.h>
#include <stdint.h>

#define BB   2
#define SS   1024
#define DD   1024
#define HH   16
#define DKK  64
#define HDD  1024
#define FF   4096
#define LL   4
#define MR   (BB*SS)

// -------------------- scratch (device globals; no allocation) --------------------
__device__ float g_x  [MR * DD];
__device__ float g_q  [MR * HDD];
__device__ float g_k  [MR * HDD];
__device__ float g_v  [MR * HDD];
__device__ float g_sc [(size_t)BB * HH * SS * SS];
__device__ float g_ctx[MR * HDD];
__device__ float g_tmp[MR * DD];
__device__ float g_ffh[MR * FF];

__device__ __nv_bfloat16 g_ah[(size_t)MR * FF];
__device__ __nv_bfloat16 g_al[(size_t)MR * FF];
#define SZ_P ((size_t)HDD * DD)
#define SZ_F ((size_t)DD * FF)
#define WQT_OFF ((size_t)0)
#define WKT_OFF ((size_t)LL * SZ_P)
#define WVT_OFF ((size_t)2 * LL * SZ_P)
#define WOT_OFF ((size_t)3 * LL * SZ_P)
#define W1T_OFF ((size_t)4 * LL * SZ_P)
#define W2T_OFF ((size_t)(4 * LL * SZ_P) + (size_t)LL * SZ_F)
#define WT_TOTAL ((size_t)(4 * LL * SZ_P) + (size_t)2 * LL * SZ_F)
__device__ __nv_bfloat16 g_wh[WT_TOTAL];
__device__ __nv_bfloat16 g_wl[WT_TOTAL];

// ==================== helpers ====================
__device__ __forceinline__ uint32_t smem_to_u32(const void* p) {
    uint32_t a;
    asm("{ .reg .u64 t; cvta.to.shared.u64 t, %1; cvt.u32.u64 %0, t; }" : "=r"(a) : "l"(p));
    return a;
}

#define CP_ASYNC16(dst, src) \
    asm volatile("cp.async.cg.shared.global [%0], [%1], 16;" \
        :: "r"((uint32_t)(dst)), "l"(__cvta_generic_to_global(src)) : "memory")
#define CP_COMMIT() asm volatile("cp.async.commit_group;" ::: "memory")
#define CP_WAITG(n) asm volatile("cp.async.wait_group %0;" :: "n"(n) : "memory")

#define LDM_X4(r0, r1, r2, r3, addr) \
    asm volatile("ldmatrix.sync.aligned.m8n8.x4.shared.b16 {%0,%1,%2,%3}, [%4];" \
        : "=r"(r0), "=r"(r1), "=r"(r2), "=r"(r3) : "r"(addr))

#define MMA_BF16(acc, a, b0, b1) \
    asm volatile("mma.sync.aligned.m16n8k16.row.col.f32.bf16.bf16.f32 " \
        "{%0,%1,%2,%3},{%4,%5,%6,%7},{%8,%9},{%0,%1,%2,%3};" \
        : "+f"((acc)[0]), "+f"((acc)[1]), "+f"((acc)[2]), "+f"((acc)[3]) \
        : "r"((a)[0]), "r"((a)[1]), "r"((a)[2]), "r"((a)[3]), "r"(b0), "r"(b1))

// ==================== split & transpose-split ====================
__global__ __launch_bounds__(256) void split_kernel(
    const float* __restrict__ s, __nv_bfloat16* __restrict__ h, __nv_bfloat16* __restrict__ l)
{
    int i = blockIdx.x * 256 + threadIdx.x;
    float4 v = ((const float4*)s)[i];
    __nv_bfloat16 h0 = __float2bfloat16(v.x), h1 = __float2bfloat16(v.y);
    __nv_bfloat16 h2 = __float2bfloat16(v.z), h3 = __float2bfloat16(v.w);
    __nv_bfloat16 l0 = __float2bfloat16(v.x - __bfloat162float(h0));
    __nv_bfloat16 l1 = __float2bfloat16(v.y - __bfloat162float(h1));
    __nv_bfloat16 l2 = __float2bfloat16(v.z - __bfloat162float(h2));
    __nv_bfloat16 l3 = __float2bfloat16(v.w - __bfloat162float(h3));
    ((__nv_bfloat162*)h)[i*2]   = __nv_bfloat162(h0, h1);
    ((__nv_bfloat162*)h)[i*2+1] = __nv_bfloat162(h2, h3);
    ((__nv_bfloat162*)l)[i*2]   = __nv_bfloat162(l0, l1);
    ((__nv_bfloat162*)l)[i*2+1] = __nv_bfloat162(l2, l3);
}

// W [K,N] fp32 -> out [N,K] bf16 hi/lo
__global__ __launch_bounds__(256) void tsplit_kernel(
    const float* __restrict__ W, __nv_bfloat16* __restrict__ th, __nv_bfloat16* __restrict__ tl,
    int K, int N)
{
    __shared__ float t[32][33];
    int n0 = blockIdx.x * 32, k0 = blockIdx.y * 32;
    int tx = threadIdx.x & 31, ty = threadIdx.x >> 5;
    #pragma unroll
    for (int i = ty; i < 32; i += 8)
        t[i][tx] = W[(size_t)(k0 + i) * N + n0 + tx];
    __syncthreads();
    #pragma unroll
    for (int i = ty; i < 32; i += 8) {
        float v = t[tx][i];
        __nv_bfloat16 h = __float2bfloat16(v);
        __nv_bfloat16 l = __float2bfloat16(v - __bfloat162float(h));
        size_t o = (size_t)(n0 + i) * K + k0 + tx;
        th[o] = h; tl[o] = l;
    }
}

// ==================== split-bf16 HMMA GEMM ====================
// C[M,N] = act(Ah·Bh^T + Ah·Bl^T + Al·Bh^T + bias)
// A:[M,K] K-major bf16 (hi/lo), B:[N,K] K-major bf16 (hi/lo)
// CTA tile 128x128, KC=32, 8 warps of 32x64, double-buffered cp.async.
#define KC     32
#define SP     40                     // smem row stride in bf16 (80B, conflict-free)
#define STG_B  (128 * SP * 2)         // 10240 bytes per array per stage
#define GSM_BYTES (8 * STG_B)         // 81920

__global__ __launch_bounds__(256, 1) void gemm_mma(
    const __nv_bfloat16* __restrict__ Ah, const __nv_bfloat16* __restrict__ Al,
    const __nv_bfloat16* __restrict__ Bh, const __nv_bfloat16* __restrict__ Bl,
    const float* __restrict__ bias, float* __restrict__ C,
    int K, int N, int act)
{
    extern __shared__ __align__(128) char smem_raw[];
    const uint32_t sbase = smem_to_u32(smem_raw);

    const int tid  = threadIdx.x;
    const int lane = tid & 31;
    const int wid  = tid >> 5;
    const int wm   = wid & 3;        // m sub-block (32 rows)
    const int wn   = wid >> 2;       // n sub-block (64 cols)
    const int m0 = blockIdx.y * 128, n0 = blockIdx.x * 128;

    float acc[2][8][4];
    #pragma unroll
    for (int i = 0; i < 2; i++)
        #pragma unroll
        for (int j = 0; j < 8; j++)
            #pragma unroll
            for (int q2 = 0; q2 < 4; q2++) acc[i][j][q2] = 0.f;

    const int nc = K >> 5;   // K / 32

    // ---- fill helper (macro-expanded inline) ----
    // chunk id layout: 8 iters; arr = i>>1 (0=Ah,1=Al,2=Bh,3=Bl); 512 chunks/array
    #define FILL_STAGE(stg, kk) do { \
        const uint32_t so_ = sbase + (uint32_t)(stg) * 4 * STG_B; \
        _Pragma("unroll") \
        for (int i_ = 0; i_ < 8; i_++) { \
            const int arr_ = i_ >> 1; \
            int rem_ = ((i_ & 1) << 8) + tid; \
            int row_ = rem_ >> 2, seg_ = rem_ & 3; \
            const __nv_bfloat16* p_ = (arr_ == 0) ? Ah : (arr_ == 1) ? Al : (arr_ == 2) ? Bh : Bl; \
            int rb_ = (arr_ < 2) ? m0 : n0; \
            uint32_t dst_ = so_ + (uint32_t)arr_ * STG_B + row_ * (SP * 2) + seg_ * 16; \
            CP_ASYNC16(dst_, p_ + (size_t)(rb_ + row_) * K + (kk) + seg_ * 8); \
        } \
        CP_COMMIT(); \
    } while (0)

    FILL_STAGE(0, 0);

    const uint32_t lrow  = lane & 15;
    const uint32_t khalf = lane >> 4;
    const uint32_t a_row_off = (wm * 32 + lrow) * (SP * 2);
    const uint32_t b_row_off = (wn * 64 + lrow) * (SP * 2);

    for (int c = 0; c < nc; c++) {
        if (c + 1 < nc) {
            FILL_STAGE((c + 1) & 1, (c + 1) * KC);
            CP_WAITG(1);
        } else {
            CP_WAITG(0);
        }
        __syncthreads();

        const uint32_t so = sbase + (uint32_t)(c & 1) * 4 * STG_B;
        const uint32_t sAh = so;
        const uint32_t sAl = so + STG_B;
        const uint32_t sBh = so + 2 * STG_B;
        const uint32_t sBl = so + 3 * STG_B;

        #pragma unroll
        for (int ks = 0; ks < 2; ks++) {
            const uint32_t kofs = (ks * 16 + khalf * 8) * 2;
            uint32_t afh[2][4], afl[2][4];
            #pragma unroll
            for (int mb = 0; mb < 2; mb++) {
                uint32_t ad = a_row_off + mb * 16 * (SP * 2) + kofs;
                LDM_X4(afh[mb][0], afh[mb][1], afh[mb][2], afh[mb][3], sAh + ad);
                LDM_X4(afl[mb][0], afl[mb][1], afl[mb][2], afl[mb][3], sAl + ad);
            }
            uint32_t bfh[4][4], bfl[4][4];
            #pragma unroll
            for (int nb = 0; nb < 4; nb++) {
                uint32_t bd = b_row_off + nb * 16 * (SP * 2) + kofs;
                LDM_X4(bfh[nb][0], bfh[nb][1], bfh[nb][2], bfh[nb][3], sBh + bd);
                LDM_X4(bfl[nb][0], bfl[nb][1], bfl[nb][2], bfl[nb][3], sBl + bd);
            }
            #pragma unroll
            for (int mb = 0; mb < 2; mb++) {
                #pragma unroll
                for (int nf = 0; nf < 8; nf++) {
                    const int nb = nf >> 1, hi = nf & 1;
                    MMA_BF16(acc[mb][nf], afh[mb], bfh[nb][hi],     bfh[nb][2 + hi]);
                    MMA_BF16(acc[mb][nf], afh[mb], bfl[nb][hi],     bfl[nb][2 + hi]);
                    MMA_BF16(acc[mb][nf], afl[mb], bfh[nb][hi],     bfh[nb][2 + hi]);
                }
            }
        }
        __syncthreads();
    }
    #undef FILL_STAGE

    // ---- epilogue ----
    const int mrow = m0 + wm * 32 + (lane >> 2);
    const int ncol0 = n0 + wn * 64 + (lane & 3) * 2;
    #pragma unroll
    for (int mb = 0; mb < 2; mb++) {
        #pragma unroll
        for (int nf = 0; nf < 8; nf++) {
            int n = ncol0 + nf * 8;
            float b0v = bias ? bias[n]     : 0.f;
            float b1v = bias ? bias[n + 1] : 0.f;
            float v0 = acc[mb][nf][0] + b0v;
            float v1 = acc[mb][nf][1] + b1v;
            float v2 = acc[mb][nf][2] + b0v;
            float v3 = acc[mb][nf][3] + b1v;
            if (act) {
                v0 = 0.5f * v0 * (1.0f + erff(v0 * 0.70710678118654752f));
                v1 = 0.5f * v1 * (1.0f + erff(v1 * 0.70710678118654752f));
                v2 = 0.5f * v2 * (1.0f + erff(v2 * 0.70710678118654752f));
                v3 = 0.5f * v3 * (1.0f + erff(v3 * 0.70710678118654752f));
            }
            int m = mrow + mb * 16;
            *(float2*)(C + (size_t)m * N + n)       = make_float2(v0, v1);
            *(float2*)(C + (size_t)(m + 8) * N + n) = make_float2(v2, v3);
        }
    }
}

// ==================== fp32 SIMT kernels ====================
__device__ __forceinline__ float block_sum(float v, float* sh) {
    __syncthreads();
    #pragma unroll
    for (int o = 16; o > 0; o >>= 1) v += __shfl_xor_sync(0xffffffffu, v, o);
    int w = threadIdx.x >> 5;
    if ((threadIdx.x & 31) == 0) sh[w] = v;
    __syncthreads();
    float t = (threadIdx.x < 8) ? sh[threadIdx.x] : 0.0f;
    #pragma unroll
    for (int o = 4; o > 0; o >>= 1) t += __shfl_xor_sync(0xffffffffu, t, o);
    if (threadIdx.x == 0) sh[0] = t;
    __syncthreads();
    return sh[0];
}
__device__ __forceinline__ float block_max(float v, float* sh) {
    __syncthreads();
    #pragma unroll
    for (int o = 16; o > 0; o >>= 1) v = fmaxf(v, __shfl_xor_sync(0xffffffffu, v, o));
    int w = threadIdx.x >> 5;
    if ((threadIdx.x & 31) == 0) sh[w] = v;
    __syncthreads();
    float t = (threadIdx.x < 8) ? sh[threadIdx.x] : -3.0e38f;
    #pragma unroll
    for (int o = 4; o > 0; o >>= 1) t = fmaxf(t, __shfl_xor_sync(0xffffffffu, t, o));
    if (threadIdx.x == 0) sh[0] = t;
    __syncthreads();
    return sh[0];
}

__global__ __launch_bounds__(256) void embed_kernel(
    const int* __restrict__ tok, const float* __restrict__ emb, float* __restrict__ x)
{
    int row = blockIdx.x;
    int s = row % SS;
    int t = tok[row];
    const float* e = emb + (size_t)t * DD;
    float* xo = x + (size_t)row * DD;
    for (int d = threadIdx.x; d < DD; d += 256) {
        int i = d >> 1;
        float freq = expf(-((float)(2 * i) / (float)DD) * 9.210340371976184f);
        float a = (float)s * freq;
        float pe = (d & 1) ? cosf(a) : sinf(a);
        xo[d] = e[d] + pe;
    }
}

__global__ __launch_bounds__(256) void attn_scores(
    const float* __restrict__ q, const float* __restrict__ k, float* __restrict__ sc)
{
    int z = blockIdx.z;
    int b = z >> 4, h = z & 15;
    int q0 = blockIdx.y * 64;
    int k0 = blockIdx.x * 64;
    const float* Q  = q + (size_t)b * SS * HDD + h * DKK;
    const float* Kp = k + (size_t)b * SS * HDD + h * DKK;
    float* S = sc + (size_t)z * SS * SS;

    __shared__ float Qs[64][65];
    __shared__ float Ks[64][65];
    int tid = threadIdx.x;
    #pragma unroll
    for (int p = 0; p < 16; p++) {
        int idx = tid + p * 256;
        int m = idx >> 6, d = idx & 63;
        Qs[m][d] = Q[(size_t)(q0 + m) * HDD + d];
        Ks[m][d] = Kp[(size_t)(k0 + m) * HDD + d];
    }
    __syncthreads();

    int tx = tid & 15, ty = tid >> 4;
    float acc[4][4] = {{0.f,0.f,0.f,0.f},{0.f,0.f,0.f,0.f},{0.f,0.f,0.f,0.f},{0.f,0.f,0.f,0.f}};
    #pragma unroll 8
    for (int kk = 0; kk < 64; kk++) {
        float ar[4], br[4];
        #pragma unroll
        for (int i = 0; i < 4; i++) ar[i] = Qs[ty * 4 + i][kk];
        #pragma unroll
        for (int j = 0; j < 4; j++) br[j] = Ks[tx * 4 + j][kk];
        #pragma unroll
        for (int i = 0; i < 4; i++)
            #pragma unroll
            for (int j = 0; j < 4; j++)
                acc[i][j] = fmaf(ar[i], br[j], acc[i][j]);
    }
    const float scale = 0.125f;
    #pragma unroll
    for (int i = 0; i < 4; i++)
        #pragma unroll
        for (int j = 0; j < 4; j++)
            S[(size_t)(q0 + ty * 4 + i) * SS + (k0 + tx * 4 + j)] = acc[i][j] * scale;
}

__global__ __launch_bounds__(256) void softmax_mask(
    float* __restrict__ sc, const int* __restrict__ tok)
{
    size_t row = blockIdx.x;
    int z = (int)(row >> 10);
    int b = z >> 4;
    float* S = sc + row * SS;
    const int* tb = tok + (size_t)b * SS;
    int tid = threadIdx.x;
    __shared__ float red[8];

    float v[4];
    float mx = -3.0e38f;
    #pragma unroll
    for (int j = 0; j < 4; j++) {
        int idx = tid + j * 256;
        float s = S[idx];
        if (tb[idx] == 0) s = -1e9f;
        v[j] = s;
        mx = fmaxf(mx, s);
    }
    mx = block_max(mx, red);
    float sum = 0.f;
    #pragma unroll
    for (int j = 0; j < 4; j++) { v[j] = expf(v[j] - mx); sum += v[j]; }
    sum = block_sum(sum, red);
    float inv = 1.0f / sum;
    #pragma unroll
    for (int j = 0; j < 4; j++) S[tid + j * 256] = v[j] * inv;
}

__global__ __launch_bounds__(256) void attn_ctx(
    const float* __restrict__ sc, const float* __restrict__ v, float* __restrict__ ctx)
{
    int z = blockIdx.y;
    int b = z >> 4, h = z & 15;
    int q0 = blockIdx.x * 64;
    const float* A = sc + (size_t)z * SS * SS;
    const float* V = v   + (size_t)b * SS * HDD + h * DKK;
    float*       O = ctx + (size_t)b * SS * HDD + h * DKK;

    __shared__ float As[64][65];
    __shared__ float Vs[64][65];
    int tid = threadIdx.x;
    int tx = tid & 15, ty = tid >> 4;
    float acc[4][4] = {{0.f,0.f,0.f,0.f},{0.f,0.f,0.f,0.f},{0.f,0.f,0.f,0.f},{0.f,0.f,0.f,0.f}};

    for (int c0 = 0; c0 < SS; c0 += 64) {
        #pragma unroll
        for (int p = 0; p < 16; p++) {
            int idx = tid + p * 256;
            int m = idx >> 6, d = idx & 63;
            As[m][d] = A[(size_t)(q0 + m) * SS + c0 + d];
            Vs[m][d] = V[(size_t)(c0 + m) * HDD + d];
        }
        __syncthreads();
        #pragma unroll 8
        for (int kk = 0; kk < 64; kk++) {
            float ar[4], br[4];
            #pragma unroll
            for (int i = 0; i < 4; i++) ar[i] = As[ty * 4 + i][kk];
            #pragma unroll
            for (int j = 0; j < 4; j++) br[j] = Vs[kk][tx * 4 + j];
            #pragma unroll
            for (int i = 0; i < 4; i++)
                #pragma unroll
                for (int j = 0; j < 4; j++)
                    acc[i][j] = fmaf(ar[i], br[j], acc[i][j]);
        }
        __syncthreads();
    }
    #pragma unroll
    for (int i = 0; i < 4; i++)
        #pragma unroll
        for (int j = 0; j < 4; j++)
            O[(size_t)(q0 + ty * 4 + i) * HDD + (tx * 4 + j)] = acc[i][j];
}

__global__ __launch_bounds__(256) void add_ln(
    const float* __restrict__ xin, const float* __restrict__ delta,
    const float* __restrict__ g, const float* __restrict__ bta,
    float* __restrict__ out)
{
    size_t row = blockIdx.x;
    const float* xr = xin   + row * DD;
    const float* dr = delta + row * DD;
    float* o = out + row * DD;
    int tid = threadIdx.x;
    __shared__ float red[8];

    float v[4];
    float s = 0.f;
    #pragma unroll
    for (int j = 0; j < 4; j++) {
        int c = tid + j * 256;
        v[j] = xr[c] + dr[c];
        s += v[j];
    }
    s = block_sum(s, red);
    float mu = s * (1.0f / 1024.0f);
    float var = 0.f;
    #pragma unroll
    for (int j = 0; j < 4; j++) { float t = v[j] - mu; var += t * t; }
    var = block_sum(var, red) * (1.0f / 1024.0f);
    float inv = rsqrtf(var + 1e-5f);
    #pragma unroll
    for (int j = 0; j < 4; j++) {
        int c = tid + j * 256;
        o[c] = (v[j] - mu) * inv * g[c] + bta[c];
    }
}

// ==================== host orchestration ====================
extern "C" void kernel_launch(void* const* d_in, const int* in_sizes, int n_in,
                              void* d_out, int out_size)
{
    (void)in_sizes; (void)n_in; (void)out_size;
    const int*   tok  = (const int*)  d_in[0];
    const float* emb  = (const float*)d_in[1];
    const float* Wq   = (const float*)d_in[2];
    const float* bq   = (const float*)d_in[3];
    const float* Wk   = (const float*)d_in[4];
    const float* bk   = (const float*)d_in[5];
    const float* Wv   = (const float*)d_in[6];
    const float* bv   = (const float*)d_in[7];
    const float* Wo   = (const float*)d_in[8];
    const float* bo   = (const float*)d_in[9];
    const float* ln1g = (const float*)d_in[10];
    const float* ln1b = (const float*)d_in[11];
    const float* W1   = (const float*)d_in[12];
    const float* W2   = (const float*)d_in[13];
    const float* ln2g = (const float*)d_in[14];
    const float* ln2b = (const float*)d_in[15];
    float* out = (float*)d_out;

    float *x, *q, *k, *v, *sc, *ctx, *tmp, *ffh;
    __nv_bfloat16 *ah, *al, *wh, *wl;
    cudaGetSymbolAddress((void**)&x,   g_x);
    cudaGetSymbolAddress((void**)&q,   g_q);
    cudaGetSymbolAddress((void**)&k,   g_k);
    cudaGetSymbolAddress((void**)&v,   g_v);
    cudaGetSymbolAddress((void**)&sc,  g_sc);
    cudaGetSymbolAddress((void**)&ctx, g_ctx);
    cudaGetSymbolAddress((void**)&tmp, g_tmp);
    cudaGetSymbolAddress((void**)&ffh, g_ffh);
    cudaGetSymbolAddress((void**)&ah,  g_ah);
    cudaGetSymbolAddress((void**)&al,  g_al);
    cudaGetSymbolAddress((void**)&wh,  g_wh);
    cudaGetSymbolAddress((void**)&wl,  g_wl);

    static int attr_done = 0;
    if (!attr_done) {
        cudaFuncSetAttribute(gemm_mma, cudaFuncAttributeMaxDynamicSharedMemorySize, GSM_BYTES);
        attr_done = 1;
    }

    // ---- transpose-split all weights ----
    dim3 tsB(256);
    for (int l = 0; l < LL; l++) {
        tsplit_kernel<<<dim3(HDD/32, DD/32), tsB>>>(Wq + (size_t)l*DD*HDD, wh + WQT_OFF + l*SZ_P, wl + WQT_OFF + l*SZ_P, DD, HDD);
        tsplit_kernel<<<dim3(HDD/32, DD/32), tsB>>>(Wk + (size_t)l*DD*HDD, wh + WKT_OFF + l*SZ_P, wl + WKT_OFF + l*SZ_P, DD, HDD);
        tsplit_kernel<<<dim3(HDD/32, DD/32), tsB>>>(Wv + (size_t)l*DD*HDD, wh + WVT_OFF + l*SZ_P, wl + WVT_OFF + l*SZ_P, DD, HDD);
        tsplit_kernel<<<dim3(DD/32, HDD/32), tsB>>>(Wo + (size_t)l*HDD*DD, wh + WOT_OFF + l*SZ_P, wl + WOT_OFF + l*SZ_P, HDD, DD);
        tsplit_kernel<<<dim3(FF/32,  DD/32), tsB>>>(W1 + (size_t)l*DD*FF,  wh + W1T_OFF + l*SZ_F, wl + W1T_OFF + l*SZ_F, DD, FF);
        tsplit_kernel<<<dim3(DD/32,  FF/32), tsB>>>(W2 + (size_t)l*FF*DD,  wh + W2T_OFF + l*SZ_F, wl + W2T_OFF + l*SZ_F, FF, DD);
    }

    embed_kernel<<<MR, 256>>>(tok, emb, x);

    const int spl_xD = (MR * DD) / 4 / 256;
    const int spl_xF = (MR * FF) / 4 / 256;
    dim3 gP(HDD/128, MR/128);
    dim3 gF1(FF/128, MR/128);
    dim3 gF2(DD/128, MR/128);
    dim3 gSc(SS/64, SS/64, BB*HH);
    dim3 gCtx(SS/64, BB*HH);

    for (int l = 0; l < LL; l++) {
        const __nv_bfloat16* wqh = wh + WQT_OFF + l*SZ_P; const __nv_bfloat16* wql = wl + WQT_OFF + l*SZ_P;
        const __nv_bfloat16* wkh = wh + WKT_OFF + l*SZ_P; const __nv_bfloat16* wkl = wl + WKT_OFF + l*SZ_P;
        const __nv_bfloat16* wvh = wh + WVT_OFF + l*SZ_P; const __nv_bfloat16* wvl = wl + WVT_OFF + l*SZ_P;
        const __nv_bfloat16* woh = wh + WOT_OFF + l*SZ_P; const __nv_bfloat16* wol = wl + WOT_OFF + l*SZ_P;
        const __nv_bfloat16* w1h = wh + W1T_OFF + l*SZ_F; const __nv_bfloat16* w1l = wl + W1T_OFF + l*SZ_F;
        const __nv_bfloat16* w2h = wh + W2T_OFF + l*SZ_F; const __nv_bfloat16* w2l = wl + W2T_OFF + l*SZ_F;

        split_kernel<<<spl_xD, 256>>>(x, ah, al);
        gemm_mma<<<gP, 256, GSM_BYTES>>>(ah, al, wqh, wql, bq + (size_t)l*HDD, q, DD, HDD, 0);
        gemm_mma<<<gP, 256, GSM_BYTES>>>(ah, al, wkh, wkl, bk + (size_t)l*HDD, k, DD, HDD, 0);
        gemm_mma<<<gP, 256, GSM_BYTES>>>(ah, al, wvh, wvl, bv + (size_t)l*HDD, v, DD, HDD, 0);

        attn_scores<<<gSc, 256>>>(q, k, sc);
        softmax_mask<<<BB*HH*SS, 256>>>(sc, tok);
        attn_ctx<<<gCtx, 256>>>(sc, v, ctx);

        split_kernel<<<spl_xD, 256>>>(ctx, ah, al);
        gemm_mma<<<gF2, 256, GSM_BYTES>>>(ah, al, woh, wol, bo + (size_t)l*DD, tmp, HDD, DD, 0);
        add_ln<<<MR, 256>>>(x, tmp, ln1g + (size_t)l*DD, ln1b + (size_t)l*DD, x);

        split_kernel<<<spl_xD, 256>>>(x, ah, al);
        gemm_mma<<<gF1, 256, GSM_BYTES>>>(ah, al, w1h, w1l, (const float*)nullptr, ffh, DD, FF, 1);
        split_kernel<<<spl_xF, 256>>>(ffh, ah, al);
        gemm_mma<<<gF2, 256, GSM_BYTES>>>(ah, al, w2h, w2l, (const float*)nullptr, tmp, FF, DD, 0);

        float* dst = (l == LL - 1) ? out : x;
        add_ln<<<MR, 256>>>(x, tmp, ln2g + (size_t)l*DD, ln2b + (size_t)l*DD, dst);
    }
}

// round 4
// speedup vs baseline: 2.6403x; 1.3964x over previous
#include <cuda_runtime.h>
#include <cuda_bf16.h>
#include <math.h>
#include <stdint.h>

#define BB   2
#define SS   1024
#define DD   1024
#define HH   16
#define DKK  64
#define HDD  1024
#define FF   4096
#define LL   4
#define MR   (BB*SS)

// -------------------- scratch (device globals; no allocation) --------------------
__device__ float g_x  [MR * DD];
__device__ float g_v  [MR * HDD];
__device__ float g_tmp[MR * DD];
__device__ __nv_bfloat16 g_xh[MR * DD],  g_xl[MR * DD];
__device__ __nv_bfloat16 g_qh[MR * HDD], g_ql[MR * HDD];
__device__ __nv_bfloat16 g_kh[MR * HDD], g_kl[MR * HDD];
__device__ __nv_bfloat16 g_vth[MR * HDD], g_vtl[MR * HDD];
__device__ __nv_bfloat16 g_ch[MR * HDD], g_cl[MR * HDD];
__device__ __nv_bfloat16 g_fh[(size_t)MR * FF], g_fl[(size_t)MR * FF];

#define SZ_P ((size_t)HDD * DD)
#define SZ_F ((size_t)DD * FF)
#define WQT_OFF ((size_t)0)
#define WKT_OFF ((size_t)LL * SZ_P)
#define WVT_OFF ((size_t)2 * LL * SZ_P)
#define WOT_OFF ((size_t)3 * LL * SZ_P)
#define W1T_OFF ((size_t)4 * LL * SZ_P)
#define W2T_OFF ((size_t)(4 * LL * SZ_P) + (size_t)LL * SZ_F)
#define WT_TOTAL ((size_t)(4 * LL * SZ_P) + (size_t)2 * LL * SZ_F)
__device__ __nv_bfloat16 g_wh[WT_TOTAL];
__device__ __nv_bfloat16 g_wl[WT_TOTAL];

// ==================== helpers ====================
__device__ __forceinline__ uint32_t smem_to_u32(const void* p) {
    uint32_t a;
    asm("{ .reg .u64 t; cvta.to.shared.u64 t, %1; cvt.u32.u64 %0, t; }" : "=r"(a) : "l"(p));
    return a;
}
#define CP_ASYNC16(dst, src) \
    asm volatile("cp.async.cg.shared.global [%0], [%1], 16;" \
        :: "r"((uint32_t)(dst)), "l"(__cvta_generic_to_global(src)) : "memory")
#define CP_COMMIT() asm volatile("cp.async.commit_group;" ::: "memory")
#define CP_WAITG(n) asm volatile("cp.async.wait_group %0;" :: "n"(n) : "memory")
#define LDM_X4(r0, r1, r2, r3, addr) \
    asm volatile("ldmatrix.sync.aligned.m8n8.x4.shared.b16 {%0,%1,%2,%3}, [%4];" \
        : "=r"(r0), "=r"(r1), "=r"(r2), "=r"(r3) : "r"(addr))
#define MMA_BF16(acc, a, b0, b1) \
    asm volatile("mma.sync.aligned.m16n8k16.row.col.f32.bf16.bf16.f32 " \
        "{%0,%1,%2,%3},{%4,%5,%6,%7},{%8,%9},{%0,%1,%2,%3};" \
        : "+f"((acc)[0]), "+f"((acc)[1]), "+f"((acc)[2]), "+f"((acc)[3]) \
        : "r"((a)[0]), "r"((a)[1]), "r"((a)[2]), "r"((a)[3]), "r"(b0), "r"(b1))

__device__ __forceinline__ float bhi(float v) { return __bfloat162float(__float2bfloat16(v)); }
__device__ __forceinline__ uint32_t pk2(float a, float b) {
    __nv_bfloat162 t;
    t.x = __float2bfloat16(a); t.y = __float2bfloat16(b);
    return *reinterpret_cast<uint32_t*>(&t);
}

// ==================== weight transpose-split ====================
__global__ __launch_bounds__(256) void tsplit_kernel(
    const float* __restrict__ W, __nv_bfloat16* __restrict__ th, __nv_bfloat16* __restrict__ tl,
    int K, int N)
{
    __shared__ float t[32][33];
    int n0 = blockIdx.x * 32, k0 = blockIdx.y * 32;
    int tx = threadIdx.x & 31, ty = threadIdx.x >> 5;
    #pragma unroll
    for (int i = ty; i < 32; i += 8)
        t[i][tx] = W[(size_t)(k0 + i) * N + n0 + tx];
    __syncthreads();
    #pragma unroll
    for (int i = ty; i < 32; i += 8) {
        float v = t[tx][i];
        __nv_bfloat16 h = __float2bfloat16(v);
        __nv_bfloat16 l = __float2bfloat16(v - __bfloat162float(h));
        size_t o = (size_t)(n0 + i) * K + k0 + tx;
        th[o] = h; tl[o] = l;
    }
}

// V [MR][HDD] fp32 -> Vt hi/lo [(b*16+h)*64 + d][SS] bf16
__global__ __launch_bounds__(256) void vtsplit(
    const float* __restrict__ v, __nv_bfloat16* __restrict__ th, __nv_bfloat16* __restrict__ tl)
{
    __shared__ float t[32][33];
    int z = blockIdx.z; int b = z >> 4, h = z & 15;
    int d0 = blockIdx.x * 32, s0 = blockIdx.y * 32;
    int tx = threadIdx.x & 31, ty = threadIdx.x >> 5;
    #pragma unroll
    for (int i = ty; i < 32; i += 8)
        t[i][tx] = v[(size_t)(b * SS + s0 + i) * HDD + h * 64 + d0 + tx];
    __syncthreads();
    #pragma unroll
    for (int i = ty; i < 32; i += 8) {
        float val = t[tx][i];
        __nv_bfloat16 hh = __float2bfloat16(val);
        __nv_bfloat16 ll = __float2bfloat16(val - __bfloat162float(hh));
        size_t o = ((size_t)z * 64 + d0 + i) * SS + s0 + tx;
        th[o] = hh; tl[o] = ll;
    }
}

// ==================== split-bf16 HMMA GEMM ====================
#define KC     32
#define SP     40
#define STG_B  (128 * SP * 2)
#define GSM_BYTES (8 * STG_B)

__global__ __launch_bounds__(256, 1) void gemm_mma(
    const __nv_bfloat16* __restrict__ Ah, const __nv_bfloat16* __restrict__ Al,
    const __nv_bfloat16* __restrict__ Bh, const __nv_bfloat16* __restrict__ Bl,
    const float* __restrict__ bias, float* __restrict__ C,
    __nv_bfloat16* __restrict__ Chi, __nv_bfloat16* __restrict__ Clo,
    int K, int N, int act)
{
    extern __shared__ __align__(128) char smem_raw[];
    const uint32_t sbase = smem_to_u32(smem_raw);

    const int tid  = threadIdx.x;
    const int lane = tid & 31;
    const int wid  = tid >> 5;
    const int wm   = wid & 3;
    const int wn   = wid >> 2;
    const int m0 = blockIdx.y * 128, n0 = blockIdx.x * 128;

    float acc[2][8][4];
    #pragma unroll
    for (int i = 0; i < 2; i++)
        #pragma unroll
        for (int j = 0; j < 8; j++)
            #pragma unroll
            for (int q2 = 0; q2 < 4; q2++) acc[i][j][q2] = 0.f;

    const int nc = K >> 5;

    #define FILL_STAGE(stg, kk) do { \
        const uint32_t so_ = sbase + (uint32_t)(stg) * 4 * STG_B; \
        _Pragma("unroll") \
        for (int i_ = 0; i_ < 8; i_++) { \
            const int arr_ = i_ >> 1; \
            int rem_ = ((i_ & 1) << 8) + tid; \
            int row_ = rem_ >> 2, seg_ = rem_ & 3; \
            const __nv_bfloat16* p_ = (arr_ == 0) ? Ah : (arr_ == 1) ? Al : (arr_ == 2) ? Bh : Bl; \
            int rb_ = (arr_ < 2) ? m0 : n0; \
            uint32_t dst_ = so_ + (uint32_t)arr_ * STG_B + row_ * (SP * 2) + seg_ * 16; \
            CP_ASYNC16(dst_, p_ + (size_t)(rb_ + row_) * K + (kk) + seg_ * 8); \
        } \
        CP_COMMIT(); \
    } while (0)

    FILL_STAGE(0, 0);

    const uint32_t lrow  = lane & 15;
    const uint32_t khalf = lane >> 4;
    const uint32_t a_row_off = (wm * 32 + lrow) * (SP * 2);
    const uint32_t b_row_off = (wn * 64 + lrow) * (SP * 2);

    for (int c = 0; c < nc; c++) {
        if (c + 1 < nc) { FILL_STAGE((c + 1) & 1, (c + 1) * KC); CP_WAITG(1); }
        else           { CP_WAITG(0); }
        __syncthreads();

        const uint32_t so = sbase + (uint32_t)(c & 1) * 4 * STG_B;
        const uint32_t sAh = so, sAl = so + STG_B, sBh = so + 2 * STG_B, sBl = so + 3 * STG_B;

        #pragma unroll
        for (int ks = 0; ks < 2; ks++) {
            const uint32_t kofs = (ks * 16 + khalf * 8) * 2;
            uint32_t afh[2][4], afl[2][4];
            #pragma unroll
            for (int mb = 0; mb < 2; mb++) {
                uint32_t ad = a_row_off + mb * 16 * (SP * 2) + kofs;
                LDM_X4(afh[mb][0], afh[mb][1], afh[mb][2], afh[mb][3], sAh + ad);
                LDM_X4(afl[mb][0], afl[mb][1], afl[mb][2], afl[mb][3], sAl + ad);
            }
            uint32_t bfh[4][4], bfl[4][4];
            #pragma unroll
            for (int nb = 0; nb < 4; nb++) {
                uint32_t bd = b_row_off + nb * 16 * (SP * 2) + kofs;
                LDM_X4(bfh[nb][0], bfh[nb][1], bfh[nb][2], bfh[nb][3], sBh + bd);
                LDM_X4(bfl[nb][0], bfl[nb][1], bfl[nb][2], bfl[nb][3], sBl + bd);
            }
            #pragma unroll
            for (int mb = 0; mb < 2; mb++) {
                #pragma unroll
                for (int nf = 0; nf < 8; nf++) {
                    const int nb = nf >> 1, hi = nf & 1;
                    MMA_BF16(acc[mb][nf], afh[mb], bfh[nb][hi], bfh[nb][2 + hi]);
                    MMA_BF16(acc[mb][nf], afh[mb], bfl[nb][hi], bfl[nb][2 + hi]);
                    MMA_BF16(acc[mb][nf], afl[mb], bfh[nb][hi], bfh[nb][2 + hi]);
                }
            }
        }
        __syncthreads();
    }
    #undef FILL_STAGE

    const int mrow = m0 + wm * 32 + (lane >> 2);
    const int ncol0 = n0 + wn * 64 + (lane & 3) * 2;
    #pragma unroll
    for (int mb = 0; mb < 2; mb++) {
        #pragma unroll
        for (int nf = 0; nf < 8; nf++) {
            int n = ncol0 + nf * 8;
            float b0v = bias ? bias[n]     : 0.f;
            float b1v = bias ? bias[n + 1] : 0.f;
            float v0 = acc[mb][nf][0] + b0v;
            float v1 = acc[mb][nf][1] + b1v;
            float v2 = acc[mb][nf][2] + b0v;
            float v3 = acc[mb][nf][3] + b1v;
            if (act) {
                v0 = 0.5f * v0 * (1.0f + erff(v0 * 0.70710678118654752f));
                v1 = 0.5f * v1 * (1.0f + erff(v1 * 0.70710678118654752f));
                v2 = 0.5f * v2 * (1.0f + erff(v2 * 0.70710678118654752f));
                v3 = 0.5f * v3 * (1.0f + erff(v3 * 0.70710678118654752f));
            }
            int m = mrow + mb * 16;
            if (C) {
                *(float2*)(C + (size_t)m * N + n)       = make_float2(v0, v1);
                *(float2*)(C + (size_t)(m + 8) * N + n) = make_float2(v2, v3);
            }
            if (Chi) {
                *(uint32_t*)(Chi + (size_t)m * N + n)       = pk2(v0, v1);
                *(uint32_t*)(Chi + (size_t)(m + 8) * N + n) = pk2(v2, v3);
                *(uint32_t*)(Clo + (size_t)m * N + n)       = pk2(v0 - bhi(v0), v1 - bhi(v1));
                *(uint32_t*)(Clo + (size_t)(m + 8) * N + n) = pk2(v2 - bhi(v2), v3 - bhi(v3));
            }
        }
    }
}

// ==================== flash attention (HMMA, split precision) ====================
// Q tile 128 x 64, K/V tiles 128 keys, online softmax, 8 warps.
#define FA_SQH 0
#define FA_SQL 18432
#define FA_SKH 36864
#define FA_SKL 55296
#define FA_SVH 73728
#define FA_SVL 91136
#define FA_MSK 108544
#define FA_SMEM (108544 + 512)

__global__ __launch_bounds__(256, 1) void flash_attn(
    const __nv_bfloat16* __restrict__ qh, const __nv_bfloat16* __restrict__ ql,
    const __nv_bfloat16* __restrict__ kh, const __nv_bfloat16* __restrict__ kl,
    const __nv_bfloat16* __restrict__ vth, const __nv_bfloat16* __restrict__ vtl,
    const int* __restrict__ tok,
    __nv_bfloat16* __restrict__ ch, __nv_bfloat16* __restrict__ cl)
{
    extern __shared__ __align__(128) char smem_raw[];
    const uint32_t base = smem_to_u32(smem_raw);
    const uint32_t sQh = base + FA_SQH, sQl = base + FA_SQL;
    const uint32_t sKh = base + FA_SKH, sKl = base + FA_SKL;
    const uint32_t sVh = base + FA_SVH, sVl = base + FA_SVL;
    float* maskf = (float*)(smem_raw + FA_MSK);

    const int tid = threadIdx.x, lane = tid & 31, wid = tid >> 5;
    const int q0 = blockIdx.x * 128;
    const int z = blockIdx.y, b = z >> 4, h = z & 15;
    const uint32_t lrow = lane & 15, khalf = lane >> 4;
    const int cpos = (lane & 3) * 2;

    // Q tile (hi/lo)
    #pragma unroll
    for (int i = 0; i < 4; i++) {
        int idx = tid + i * 256;
        int row = idx >> 3, seg = idx & 7;
        size_t src = (size_t)(b * SS + q0 + row) * HDD + h * 64 + seg * 8;
        CP_ASYNC16(sQh + row * 144 + seg * 16, qh + src);
        CP_ASYNC16(sQl + row * 144 + seg * 16, ql + src);
    }
    CP_COMMIT();

    float m0 = -3.0e38f, m1 = -3.0e38f, l0 = 0.f, l1 = 0.f;
    float O[8][4];
    #pragma unroll
    for (int i = 0; i < 8; i++)
        #pragma unroll
        for (int j = 0; j < 4; j++) O[i][j] = 0.f;

    uint32_t qfh[4][4], qfl[4][4];

    for (int kt = 0; kt < 8; kt++) {
        const int k0 = kt * 128;
        #pragma unroll
        for (int i = 0; i < 4; i++) {
            int idx = tid + i * 256;
            int row = idx >> 3, seg = idx & 7;
            size_t src = (size_t)(b * SS + k0 + row) * HDD + h * 64 + seg * 8;
            CP_ASYNC16(sKh + row * 144 + seg * 16, kh + src);
            CP_ASYNC16(sKl + row * 144 + seg * 16, kl + src);
        }
        #pragma unroll
        for (int i = 0; i < 4; i++) {
            int idx = tid + i * 256;
            int row = idx >> 4, seg = idx & 15;
            size_t src = ((size_t)z * 64 + row) * SS + k0 + seg * 8;
            CP_ASYNC16(sVh + row * 272 + seg * 16, vth + src);
            CP_ASYNC16(sVl + row * 272 + seg * 16, vtl + src);
        }
        CP_COMMIT();
        if (tid < 128) maskf[tid] = (tok[b * SS + k0 + tid] == 0) ? -1e9f : 0.f;
        CP_WAITG(0);
        __syncthreads();

        if (kt == 0) {
            #pragma unroll
            for (int ks = 0; ks < 4; ks++) {
                uint32_t ad = (wid * 16 + lrow) * 144 + (ks * 16 + khalf * 8) * 2;
                LDM_X4(qfh[ks][0], qfh[ks][1], qfh[ks][2], qfh[ks][3], sQh + ad);
                LDM_X4(qfl[ks][0], qfl[ks][1], qfl[ks][2], qfl[ks][3], sQl + ad);
            }
        }

        // ---- S = Q K^T (split, 3 passes) ----
        float Sv[16][4];
        #pragma unroll
        for (int i = 0; i < 16; i++)
            #pragma unroll
            for (int j = 0; j < 4; j++) Sv[i][j] = 0.f;

        #pragma unroll
        for (int ks = 0; ks < 4; ks++) {
            #pragma unroll
            for (int ng = 0; ng < 8; ng++) {
                uint32_t bd = (ng * 16 + lrow) * 144 + (ks * 16 + khalf * 8) * 2;
                uint32_t bh_[4], bl_[4];
                LDM_X4(bh_[0], bh_[1], bh_[2], bh_[3], sKh + bd);
                LDM_X4(bl_[0], bl_[1], bl_[2], bl_[3], sKl + bd);
                MMA_BF16(Sv[2*ng],   qfh[ks], bh_[0], bh_[2]);
                MMA_BF16(Sv[2*ng],   qfh[ks], bl_[0], bl_[2]);
                MMA_BF16(Sv[2*ng],   qfl[ks], bh_[0], bh_[2]);
                MMA_BF16(Sv[2*ng+1], qfh[ks], bh_[1], bh_[3]);
                MMA_BF16(Sv[2*ng+1], qfh[ks], bl_[1], bl_[3]);
                MMA_BF16(Sv[2*ng+1], qfl[ks], bh_[1], bh_[3]);
            }
        }

        // ---- scale + mask + online softmax ----
        float mt0 = -3.0e38f, mt1 = -3.0e38f;
        #pragma unroll
        for (int nb = 0; nb < 16; nb++) {
            float mk0 = maskf[nb * 8 + cpos], mk1 = maskf[nb * 8 + cpos + 1];
            Sv[nb][0] = Sv[nb][0] * 0.125f + mk0;
            Sv[nb][1] = Sv[nb][1] * 0.125f + mk1;
            Sv[nb][2] = Sv[nb][2] * 0.125f + mk0;
            Sv[nb][3] = Sv[nb][3] * 0.125f + mk1;
            mt0 = fmaxf(mt0, fmaxf(Sv[nb][0], Sv[nb][1]));
            mt1 = fmaxf(mt1, fmaxf(Sv[nb][2], Sv[nb][3]));
        }
        mt0 = fmaxf(mt0, __shfl_xor_sync(0xffffffffu, mt0, 1));
        mt0 = fmaxf(mt0, __shfl_xor_sync(0xffffffffu, mt0, 2));
        mt1 = fmaxf(mt1, __shfl_xor_sync(0xffffffffu, mt1, 1));
        mt1 = fmaxf(mt1, __shfl_xor_sync(0xffffffffu, mt1, 2));

        float mn0 = fmaxf(m0, mt0), mn1 = fmaxf(m1, mt1);
        float al0 = __expf(m0 - mn0), al1 = __expf(m1 - mn1);
        float su0 = 0.f, su1 = 0.f;
        #pragma unroll
        for (int nb = 0; nb < 16; nb++) {
            Sv[nb][0] = __expf(Sv[nb][0] - mn0);
            Sv[nb][1] = __expf(Sv[nb][1] - mn0);
            Sv[nb][2] = __expf(Sv[nb][2] - mn1);
            Sv[nb][3] = __expf(Sv[nb][3] - mn1);
            su0 += Sv[nb][0] + Sv[nb][1];
            su1 += Sv[nb][2] + Sv[nb][3];
        }
        su0 += __shfl_xor_sync(0xffffffffu, su0, 1);
        su0 += __shfl_xor_sync(0xffffffffu, su0, 2);
        su1 += __shfl_xor_sync(0xffffffffu, su1, 1);
        su1 += __shfl_xor_sync(0xffffffffu, su1, 2);

        l0 = l0 * al0 + su0;
        l1 = l1 * al1 + su1;
        m0 = mn0; m1 = mn1;
        #pragma unroll
        for (int nf = 0; nf < 8; nf++) {
            O[nf][0] *= al0; O[nf][1] *= al0;
            O[nf][2] *= al1; O[nf][3] *= al1;
        }

        // ---- O += P V (split, 3 passes); P fragments straight from Sv ----
        #pragma unroll
        for (int j = 0; j < 8; j++) {
            float v00 = Sv[2*j][0],  v01 = Sv[2*j][1],  v02 = Sv[2*j][2],  v03 = Sv[2*j][3];
            float v10 = Sv[2*j+1][0],v11 = Sv[2*j+1][1],v12 = Sv[2*j+1][2],v13 = Sv[2*j+1][3];
            uint32_t pa_h[4], pa_l[4];
            pa_h[0] = pk2(v00, v01); pa_l[0] = pk2(v00 - bhi(v00), v01 - bhi(v01));
            pa_h[1] = pk2(v02, v03); pa_l[1] = pk2(v02 - bhi(v02), v03 - bhi(v03));
            pa_h[2] = pk2(v10, v11); pa_l[2] = pk2(v10 - bhi(v10), v11 - bhi(v11));
            pa_h[3] = pk2(v12, v13); pa_l[3] = pk2(v12 - bhi(v12), v13 - bhi(v13));
            #pragma unroll
            for (int ng = 0; ng < 4; ng++) {
                uint32_t bd = (ng * 16 + lrow) * 272 + (j * 16 + khalf * 8) * 2;
                uint32_t vh_[4], vl_[4];
                LDM_X4(vh_[0], vh_[1], vh_[2], vh_[3], sVh + bd);
                LDM_X4(vl_[0], vl_[1], vl_[2], vl_[3], sVl + bd);
                MMA_BF16(O[2*ng],   pa_h, vh_[0], vh_[2]);
                MMA_BF16(O[2*ng],   pa_h, vl_[0], vl_[2]);
                MMA_BF16(O[2*ng],   pa_l, vh_[0], vh_[2]);
                MMA_BF16(O[2*ng+1], pa_h, vh_[1], vh_[3]);
                MMA_BF16(O[2*ng+1], pa_h, vl_[1], vl_[3]);
                MMA_BF16(O[2*ng+1], pa_l, vh_[1], vh_[3]);
            }
        }
        __syncthreads();
    }

    // ---- normalize + write ctx hi/lo ----
    float i0 = 1.f / l0, i1 = 1.f / l1;
    const int rgl = b * SS + q0 + wid * 16 + (lane >> 2);
    #pragma unroll
    for (int nf = 0; nf < 8; nf++) {
        int col = h * 64 + nf * 8 + cpos;
        float a0 = O[nf][0] * i0, a1 = O[nf][1] * i0;
        float a2 = O[nf][2] * i1, a3 = O[nf][3] * i1;
        size_t o0 = (size_t)rgl * HDD + col;
        size_t o1 = (size_t)(rgl + 8) * HDD + col;
        *(uint32_t*)(ch + o0) = pk2(a0, a1);
        *(uint32_t*)(ch + o1) = pk2(a2, a3);
        *(uint32_t*)(cl + o0) = pk2(a0 - bhi(a0), a1 - bhi(a1));
        *(uint32_t*)(cl + o1) = pk2(a2 - bhi(a2), a3 - bhi(a3));
    }
}

// ==================== embed + add_ln (emit fp32 and hi/lo) ====================
__global__ __launch_bounds__(256) void embed_kernel(
    const int* __restrict__ tok, const float* __restrict__ emb,
    float* __restrict__ x, __nv_bfloat16* __restrict__ xh, __nv_bfloat16* __restrict__ xl)
{
    int row = blockIdx.x;
    int s = row % SS;
    int t = tok[row];
    const float* e = emb + (size_t)t * DD;
    for (int d = threadIdx.x; d < DD; d += 256) {
        int i = d >> 1;
        float freq = expf(-((float)(2 * i) / (float)DD) * 9.210340371976184f);
        float a = (float)s * freq;
        float pe = (d & 1) ? cosf(a) : sinf(a);
        float v = e[d] + pe;
        size_t o = (size_t)row * DD + d;
        x[o] = v;
        __nv_bfloat16 hh = __float2bfloat16(v);
        xh[o] = hh;
        xl[o] = __float2bfloat16(v - __bfloat162float(hh));
    }
}

__device__ __forceinline__ float block_sum(float v, float* sh) {
    __syncthreads();
    #pragma unroll
    for (int o = 16; o > 0; o >>= 1) v += __shfl_xor_sync(0xffffffffu, v, o);
    int w = threadIdx.x >> 5;
    if ((threadIdx.x & 31) == 0) sh[w] = v;
    __syncthreads();
    float t = (threadIdx.x < 8) ? sh[threadIdx.x] : 0.0f;
    #pragma unroll
    for (int o = 4; o > 0; o >>= 1) t += __shfl_xor_sync(0xffffffffu, t, o);
    if (threadIdx.x == 0) sh[0] = t;
    __syncthreads();
    return sh[0];
}

__global__ __launch_bounds__(256) void add_ln(
    const float* __restrict__ xin, const float* __restrict__ delta,
    const float* __restrict__ g, const float* __restrict__ bta,
    float* __restrict__ out, __nv_bfloat16* __restrict__ oh, __nv_bfloat16* __restrict__ ol)
{
    size_t row = blockIdx.x;
    const float* xr = xin   + row * DD;
    const float* dr = delta + row * DD;
    int tid = threadIdx.x;
    __shared__ float red[8];

    float v[4];
    float s = 0.f;
    #pragma unroll
    for (int j = 0; j < 4; j++) {
        int c = tid + j * 256;
        v[j] = xr[c] + dr[c];
        s += v[j];
    }
    s = block_sum(s, red);
    float mu = s * (1.0f / 1024.0f);
    float var = 0.f;
    #pragma unroll
    for (int j = 0; j < 4; j++) { float t = v[j] - mu; var += t * t; }
    var = block_sum(var, red) * (1.0f / 1024.0f);
    float inv = rsqrtf(var + 1e-5f);
    #pragma unroll
    for (int j = 0; j < 4; j++) {
        int c = tid + j * 256;
        float o = (v[j] - mu) * inv * g[c] + bta[c];
        size_t idx = row * DD + c;
        out[idx] = o;
        __nv_bfloat16 hh = __float2bfloat16(o);
        oh[idx] = hh;
        ol[idx] = __float2bfloat16(o - __bfloat162float(hh));
    }
}

// ==================== host orchestration ====================
extern "C" void kernel_launch(void* const* d_in, const int* in_sizes, int n_in,
                              void* d_out, int out_size)
{
    (void)in_sizes; (void)n_in; (void)out_size;
    const int*   tok  = (const int*)  d_in[0];
    const float* emb  = (const float*)d_in[1];
    const float* Wq   = (const float*)d_in[2];
    const float* bq   = (const float*)d_in[3];
    const float* Wk   = (const float*)d_in[4];
    const float* bk   = (const float*)d_in[5];
    const float* Wv   = (const float*)d_in[6];
    const float* bv   = (const float*)d_in[7];
    const float* Wo   = (const float*)d_in[8];
    const float* bo   = (const float*)d_in[9];
    const float* ln1g = (const float*)d_in[10];
    const float* ln1b = (const float*)d_in[11];
    const float* W1   = (const float*)d_in[12];
    const float* W2   = (const float*)d_in[13];
    const float* ln2g = (const float*)d_in[14];
    const float* ln2b = (const float*)d_in[15];
    float* out = (float*)d_out;

    float *x, *v, *tmp;
    __nv_bfloat16 *xh, *xl, *qh, *ql, *kh, *kl, *vth, *vtl, *ch, *cl, *fh, *fl, *wh, *wl;
    cudaGetSymbolAddress((void**)&x,   g_x);
    cudaGetSymbolAddress((void**)&v,   g_v);
    cudaGetSymbolAddress((void**)&tmp, g_tmp);
    cudaGetSymbolAddress((void**)&xh,  g_xh);  cudaGetSymbolAddress((void**)&xl, g_xl);
    cudaGetSymbolAddress((void**)&qh,  g_qh);  cudaGetSymbolAddress((void**)&ql, g_ql);
    cudaGetSymbolAddress((void**)&kh,  g_kh);  cudaGetSymbolAddress((void**)&kl, g_kl);
    cudaGetSymbolAddress((void**)&vth, g_vth); cudaGetSymbolAddress((void**)&vtl, g_vtl);
    cudaGetSymbolAddress((void**)&ch,  g_ch);  cudaGetSymbolAddress((void**)&cl, g_cl);
    cudaGetSymbolAddress((void**)&fh,  g_fh);  cudaGetSymbolAddress((void**)&fl, g_fl);
    cudaGetSymbolAddress((void**)&wh,  g_wh);  cudaGetSymbolAddress((void**)&wl, g_wl);

    static int attr_done = 0;
    if (!attr_done) {
        cudaFuncSetAttribute(gemm_mma, cudaFuncAttributeMaxDynamicSharedMemorySize, GSM_BYTES);
        cudaFuncSetAttribute(flash_attn, cudaFuncAttributeMaxDynamicSharedMemorySize, FA_SMEM);
        attr_done = 1;
    }

    // ---- transpose-split weights ----
    dim3 tsB(256);
    for (int l = 0; l < LL; l++) {
        tsplit_kernel<<<dim3(HDD/32, DD/32), tsB>>>(Wq + (size_t)l*DD*HDD, wh + WQT_OFF + l*SZ_P, wl + WQT_OFF + l*SZ_P, DD, HDD);
        tsplit_kernel<<<dim3(HDD/32, DD/32), tsB>>>(Wk + (size_t)l*DD*HDD, wh + WKT_OFF + l*SZ_P, wl + WKT_OFF + l*SZ_P, DD, HDD);
        tsplit_kernel<<<dim3(HDD/32, DD/32), tsB>>>(Wv + (size_t)l*DD*HDD, wh + WVT_OFF + l*SZ_P, wl + WVT_OFF + l*SZ_P, DD, HDD);
        tsplit_kernel<<<dim3(DD/32, HDD/32), tsB>>>(Wo + (size_t)l*HDD*DD, wh + WOT_OFF + l*SZ_P, wl + WOT_OFF + l*SZ_P, HDD, DD);
        tsplit_kernel<<<dim3(FF/32,  DD/32), tsB>>>(W1 + (size_t)l*DD*FF,  wh + W1T_OFF + l*SZ_F, wl + W1T_OFF + l*SZ_F, DD, FF);
        tsplit_kernel<<<dim3(DD/32,  FF/32), tsB>>>(W2 + (size_t)l*FF*DD,  wh + W2T_OFF + l*SZ_F, wl + W2T_OFF + l*SZ_F, FF, DD);
    }

    embed_kernel<<<MR, 256>>>(tok, emb, x, xh, xl);

    dim3 gP(HDD/128, MR/128);
    dim3 gF1(FF/128, MR/128);
    dim3 gF2(DD/128, MR/128);
    dim3 gVT(2, 32, 32);
    dim3 gFA(SS/128, BB*HH);

    for (int l = 0; l < LL; l++) {
        const __nv_bfloat16* wqh = wh + WQT_OFF + l*SZ_P; const __nv_bfloat16* wql = wl + WQT_OFF + l*SZ_P;
        const __nv_bfloat16* wkh = wh + WKT_OFF + l*SZ_P; const __nv_bfloat16* wkl = wl + WKT_OFF + l*SZ_P;
        const __nv_bfloat16* wvh = wh + WVT_OFF + l*SZ_P; const __nv_bfloat16* wvl = wl + WVT_OFF + l*SZ_P;
        const __nv_bfloat16* woh = wh + WOT_OFF + l*SZ_P; const __nv_bfloat16* wol = wl + WOT_OFF + l*SZ_P;
        const __nv_bfloat16* w1h = wh + W1T_OFF + l*SZ_F; const __nv_bfloat16* w1l = wl + W1T_OFF + l*SZ_F;
        const __nv_bfloat16* w2h = wh + W2T_OFF + l*SZ_F; const __nv_bfloat16* w2l = wl + W2T_OFF + l*SZ_F;

        gemm_mma<<<gP, 256, GSM_BYTES>>>(xh, xl, wqh, wql, bq + (size_t)l*HDD,
                                         (float*)nullptr, qh, ql, DD, HDD, 0);
        gemm_mma<<<gP, 256, GSM_BYTES>>>(xh, xl, wkh, wkl, bk + (size_t)l*HDD,
                                         (float*)nullptr, kh, kl, DD, HDD, 0);
        gemm_mma<<<gP, 256, GSM_BYTES>>>(xh, xl, wvh, wvl, bv + (size_t)l*HDD,
                                         v, (__nv_bfloat16*)nullptr, (__nv_bfloat16*)nullptr, DD, HDD, 0);
        vtsplit<<<gVT, 256>>>(v, vth, vtl);

        flash_attn<<<gFA, 256, FA_SMEM>>>(qh, ql, kh, kl, vth, vtl, tok, ch, cl);

        gemm_mma<<<gF2, 256, GSM_BYTES>>>(ch, cl, woh, wol, bo + (size_t)l*DD,
                                          tmp, (__nv_bfloat16*)nullptr, (__nv_bfloat16*)nullptr, HDD, DD, 0);
        add_ln<<<MR, 256>>>(x, tmp, ln1g + (size_t)l*DD, ln1b + (size_t)l*DD, x, xh, xl);

        gemm_mma<<<gF1, 256, GSM_BYTES>>>(xh, xl, w1h, w1l, (const float*)nullptr,
                                          (float*)nullptr, fh, fl, DD, FF, 1);
        gemm_mma<<<gF2, 256, GSM_BYTES>>>(fh, fl, w2h, w2l, (const float*)nullptr,
                                          tmp, (__nv_bfloat16*)nullptr, (__nv_bfloat16*)nullptr, FF, DD, 0);

        float* dst = (l == LL - 1) ? out : x;
        add_ln<<<MR, 256>>>(x, tmp, ln2g + (size_t)l*DD, ln2b + (size_t)l*DD, dst, xh, xl);
    }
}

// round 5
// speedup vs baseline: 2.7405x; 1.0380x over previous
#include <cuda_runtime.h>
#include <cuda_bf16.h>
#include <math.h>
#include <stdint.h>

#define BB   2
#define SS   1024
#define DD   1024
#define HH   16
#define DKK  64
#define HDD  1024
#define FF   4096
#define LL   4
#define MR   (BB*SS)

// -------------------- scratch (device globals; no allocation) --------------------
__device__ float g_x  [MR * DD];
__device__ float g_v  [MR * HDD];
__device__ float g_tmp[MR * DD];
__device__ __nv_bfloat16 g_xh[MR * DD],  g_xl[MR * DD];
__device__ __nv_bfloat16 g_qh[MR * HDD], g_ql[MR * HDD];
__device__ __nv_bfloat16 g_kh[MR * HDD], g_kl[MR * HDD];
__device__ __nv_bfloat16 g_vth[MR * HDD], g_vtl[MR * HDD];
__device__ __nv_bfloat16 g_ch[MR * HDD], g_cl[MR * HDD];
__device__ __nv_bfloat16 g_fh[(size_t)MR * FF], g_fl[(size_t)MR * FF];

#define SZ_P ((size_t)HDD * DD)
#define SZ_F ((size_t)DD * FF)
#define WQT_OFF ((size_t)0)
#define WKT_OFF ((size_t)LL * SZ_P)
#define WVT_OFF ((size_t)2 * LL * SZ_P)
#define WOT_OFF ((size_t)3 * LL * SZ_P)
#define W1T_OFF ((size_t)4 * LL * SZ_P)
#define W2T_OFF ((size_t)(4 * LL * SZ_P) + (size_t)LL * SZ_F)
#define WT_TOTAL ((size_t)(4 * LL * SZ_P) + (size_t)2 * LL * SZ_F)
__device__ __nv_bfloat16 g_wh[WT_TOTAL];
__device__ __nv_bfloat16 g_wl[WT_TOTAL];

// ==================== helpers ====================
__device__ __forceinline__ uint32_t smem_to_u32(const void* p) {
    uint32_t a;
    asm("{ .reg .u64 t; cvta.to.shared.u64 t, %1; cvt.u32.u64 %0, t; }" : "=r"(a) : "l"(p));
    return a;
}
#define CP_ASYNC16(dst, src) \
    asm volatile("cp.async.cg.shared.global [%0], [%1], 16;" \
        :: "r"((uint32_t)(dst)), "l"(__cvta_generic_to_global(src)) : "memory")
#define CP_COMMIT() asm volatile("cp.async.commit_group;" ::: "memory")
#define CP_WAITG(n) asm volatile("cp.async.wait_group %0;" :: "n"(n) : "memory")
#define LDM_X4(r0, r1, r2, r3, addr) \
    asm volatile("ldmatrix.sync.aligned.m8n8.x4.shared.b16 {%0,%1,%2,%3}, [%4];" \
        : "=r"(r0), "=r"(r1), "=r"(r2), "=r"(r3) : "r"(addr))
#define MMA_BF16(acc, a, b0, b1) \
    asm volatile("mma.sync.aligned.m16n8k16.row.col.f32.bf16.bf16.f32 " \
        "{%0,%1,%2,%3},{%4,%5,%6,%7},{%8,%9},{%0,%1,%2,%3};" \
        : "+f"((acc)[0]), "+f"((acc)[1]), "+f"((acc)[2]), "+f"((acc)[3]) \
        : "r"((a)[0]), "r"((a)[1]), "r"((a)[2]), "r"((a)[3]), "r"(b0), "r"(b1))

__device__ __forceinline__ float bhi(float v) { return __bfloat162float(__float2bfloat16(v)); }
__device__ __forceinline__ uint32_t pk2(float a, float b) {
    __nv_bfloat162 t;
    t.x = __float2bfloat16(a); t.y = __float2bfloat16(b);
    return *reinterpret_cast<uint32_t*>(&t);
}
// exact-GELU via A&S 7.1.26 erf (max |err| 1.5e-7)
__device__ __forceinline__ float gelu_f(float v) {
    float x = v * 0.70710678118654752f;
    float ax = fabsf(x);
    float t = __fdividef(1.0f, fmaf(0.3275911f, ax, 1.0f));
    float p = t * fmaf(t, fmaf(t, fmaf(t, fmaf(t, 1.061405429f, -1.453152027f),
                               1.421413741f), -0.284496736f), 0.254829592f);
    float erfv = 1.0f - p * __expf(-ax * ax);
    erfv = copysignf(erfv, x);
    return 0.5f * v * (1.0f + erfv);
}

// ==================== weight transpose-split ====================
__global__ __launch_bounds__(256) void tsplit_kernel(
    const float* __restrict__ W, __nv_bfloat16* __restrict__ th, __nv_bfloat16* __restrict__ tl,
    int K, int N)
{
    __shared__ float t[32][33];
    int n0 = blockIdx.x * 32, k0 = blockIdx.y * 32;
    int tx = threadIdx.x & 31, ty = threadIdx.x >> 5;
    #pragma unroll
    for (int i = ty; i < 32; i += 8)
        t[i][tx] = W[(size_t)(k0 + i) * N + n0 + tx];
    __syncthreads();
    #pragma unroll
    for (int i = ty; i < 32; i += 8) {
        float v = t[tx][i];
        __nv_bfloat16 h = __float2bfloat16(v);
        __nv_bfloat16 l = __float2bfloat16(v - __bfloat162float(h));
        size_t o = (size_t)(n0 + i) * K + k0 + tx;
        th[o] = h; tl[o] = l;
    }
}

// V [MR][HDD] fp32 -> Vt hi/lo [(b*16+h)*64 + d][SS] bf16
__global__ __launch_bounds__(256) void vtsplit(
    const float* __restrict__ v, __nv_bfloat16* __restrict__ th, __nv_bfloat16* __restrict__ tl)
{
    __shared__ float t[32][33];
    int z = blockIdx.z; int b = z >> 4, h = z & 15;
    int d0 = blockIdx.x * 32, s0 = blockIdx.y * 32;
    int tx = threadIdx.x & 31, ty = threadIdx.x >> 5;
    #pragma unroll
    for (int i = ty; i < 32; i += 8)
        t[i][tx] = v[(size_t)(b * SS + s0 + i) * HDD + h * 64 + d0 + tx];
    __syncthreads();
    #pragma unroll
    for (int i = ty; i < 32; i += 8) {
        float val = t[tx][i];
        __nv_bfloat16 hh = __float2bfloat16(val);
        __nv_bfloat16 ll = __float2bfloat16(val - __bfloat162float(hh));
        size_t o = ((size_t)z * 64 + d0 + i) * SS + s0 + tx;
        th[o] = hh; tl[o] = ll;
    }
}

// ==================== split-bf16 HMMA GEMM (2 CTAs/SM) ====================
#define KC     32
#define SP     40
#define STG_B  (128 * SP * 2)
#define GSM_BYTES (8 * STG_B)

__global__ __launch_bounds__(256, 2) void gemm_mma(
    const __nv_bfloat16* __restrict__ Ah, const __nv_bfloat16* __restrict__ Al,
    const __nv_bfloat16* __restrict__ Bh, const __nv_bfloat16* __restrict__ Bl,
    const float* __restrict__ bias, float* __restrict__ C,
    __nv_bfloat16* __restrict__ Chi, __nv_bfloat16* __restrict__ Clo,
    int K, int N, int act)
{
    extern __shared__ __align__(128) char smem_raw[];
    const uint32_t sbase = smem_to_u32(smem_raw);

    const int tid  = threadIdx.x;
    const int lane = tid & 31;
    const int wid  = tid >> 5;
    const int wm   = wid & 3;
    const int wn   = wid >> 2;
    const int m0 = blockIdx.y * 128, n0 = blockIdx.x * 128;

    float acc[2][8][4];
    #pragma unroll
    for (int i = 0; i < 2; i++)
        #pragma unroll
        for (int j = 0; j < 8; j++)
            #pragma unroll
            for (int q2 = 0; q2 < 4; q2++) acc[i][j][q2] = 0.f;

    const int nc = K >> 5;

    #define FILL_STAGE(stg, kk) do { \
        const uint32_t so_ = sbase + (uint32_t)(stg) * 4 * STG_B; \
        _Pragma("unroll") \
        for (int i_ = 0; i_ < 8; i_++) { \
            const int arr_ = i_ >> 1; \
            int rem_ = ((i_ & 1) << 8) + tid; \
            int row_ = rem_ >> 2, seg_ = rem_ & 3; \
            const __nv_bfloat16* p_ = (arr_ == 0) ? Ah : (arr_ == 1) ? Al : (arr_ == 2) ? Bh : Bl; \
            int rb_ = (arr_ < 2) ? m0 : n0; \
            uint32_t dst_ = so_ + (uint32_t)arr_ * STG_B + row_ * (SP * 2) + seg_ * 16; \
            CP_ASYNC16(dst_, p_ + (size_t)(rb_ + row_) * K + (kk) + seg_ * 8); \
        } \
        CP_COMMIT(); \
    } while (0)

    FILL_STAGE(0, 0);

    const uint32_t lrow  = lane & 15;
    const uint32_t khalf = lane >> 4;
    const uint32_t a_row_off = (wm * 32 + lrow) * (SP * 2);
    const uint32_t b_row_off = (wn * 64 + lrow) * (SP * 2);

    for (int c = 0; c < nc; c++) {
        if (c + 1 < nc) { FILL_STAGE((c + 1) & 1, (c + 1) * KC); CP_WAITG(1); }
        else           { CP_WAITG(0); }
        __syncthreads();

        const uint32_t so = sbase + (uint32_t)(c & 1) * 4 * STG_B;
        const uint32_t sAh = so, sAl = so + STG_B, sBh = so + 2 * STG_B, sBl = so + 3 * STG_B;

        #pragma unroll
        for (int ks = 0; ks < 2; ks++) {
            const uint32_t kofs = (ks * 16 + khalf * 8) * 2;
            uint32_t afh[2][4], afl[2][4];
            #pragma unroll
            for (int mb = 0; mb < 2; mb++) {
                uint32_t ad = a_row_off + mb * 16 * (SP * 2) + kofs;
                LDM_X4(afh[mb][0], afh[mb][1], afh[mb][2], afh[mb][3], sAh + ad);
                LDM_X4(afl[mb][0], afl[mb][1], afl[mb][2], afl[mb][3], sAl + ad);
            }
            // per-nb: load B frags, use immediately (low live range -> 2 CTAs/SM)
            #pragma unroll
            for (int nb = 0; nb < 4; nb++) {
                uint32_t bd = b_row_off + nb * 16 * (SP * 2) + kofs;
                uint32_t bfh_[4], bfl_[4];
                LDM_X4(bfh_[0], bfh_[1], bfh_[2], bfh_[3], sBh + bd);
                LDM_X4(bfl_[0], bfl_[1], bfl_[2], bfl_[3], sBl + bd);
                #pragma unroll
                for (int mb = 0; mb < 2; mb++) {
                    #pragma unroll
                    for (int hi = 0; hi < 2; hi++) {
                        float* a4 = acc[mb][nb * 2 + hi];
                        MMA_BF16(a4, afh[mb], bfh_[hi], bfh_[2 + hi]);
                        MMA_BF16(a4, afh[mb], bfl_[hi], bfl_[2 + hi]);
                        MMA_BF16(a4, afl[mb], bfh_[hi], bfh_[2 + hi]);
                    }
                }
            }
        }
        __syncthreads();
    }
    #undef FILL_STAGE

    const int mrow = m0 + wm * 32 + (lane >> 2);
    const int ncol0 = n0 + wn * 64 + (lane & 3) * 2;
    #pragma unroll
    for (int mb = 0; mb < 2; mb++) {
        #pragma unroll
        for (int nf = 0; nf < 8; nf++) {
            int n = ncol0 + nf * 8;
            float b0v = bias ? bias[n]     : 0.f;
            float b1v = bias ? bias[n + 1] : 0.f;
            float v0 = acc[mb][nf][0] + b0v;
            float v1 = acc[mb][nf][1] + b1v;
            float v2 = acc[mb][nf][2] + b0v;
            float v3 = acc[mb][nf][3] + b1v;
            if (act) {
                v0 = gelu_f(v0); v1 = gelu_f(v1);
                v2 = gelu_f(v2); v3 = gelu_f(v3);
            }
            int m = mrow + mb * 16;
            if (C) {
                *(float2*)(C + (size_t)m * N + n)       = make_float2(v0, v1);
                *(float2*)(C + (size_t)(m + 8) * N + n) = make_float2(v2, v3);
            }
            if (Chi) {
                *(uint32_t*)(Chi + (size_t)m * N + n)       = pk2(v0, v1);
                *(uint32_t*)(Chi + (size_t)(m + 8) * N + n) = pk2(v2, v3);
                *(uint32_t*)(Clo + (size_t)m * N + n)       = pk2(v0 - bhi(v0), v1 - bhi(v1));
                *(uint32_t*)(Clo + (size_t)(m + 8) * N + n) = pk2(v2 - bhi(v2), v3 - bhi(v3));
            }
        }
    }
}

// ==================== flash attention (HMMA, split, double-buffered K/V) ====================
#define FA_QH   0
#define FA_QL   18432
#define FA_STG0 36864
#define FA_KH   0
#define FA_KL   18432
#define FA_VH   36864
#define FA_VL   54272
#define FA_MSK  71680
#define FA_STGSZ 72192
#define FA_SMEM (36864 + 2 * 72192)   // 181248

__global__ __launch_bounds__(256, 1) void flash_attn(
    const __nv_bfloat16* __restrict__ qh, const __nv_bfloat16* __restrict__ ql,
    const __nv_bfloat16* __restrict__ kh, const __nv_bfloat16* __restrict__ kl,
    const __nv_bfloat16* __restrict__ vth, const __nv_bfloat16* __restrict__ vtl,
    const int* __restrict__ tok,
    __nv_bfloat16* __restrict__ ch, __nv_bfloat16* __restrict__ cl)
{
    extern __shared__ __align__(128) char smem_raw[];
    const uint32_t base = smem_to_u32(smem_raw);
    const uint32_t sQh = base + FA_QH, sQl = base + FA_QL;

    const int tid = threadIdx.x, lane = tid & 31, wid = tid >> 5;
    const int q0 = blockIdx.x * 128;
    const int z = blockIdx.y, b = z >> 4, h = z & 15;
    const uint32_t lrow = lane & 15, khalf = lane >> 4;
    const int cpos = (lane & 3) * 2;

    // Q tile (hi/lo), its own group
    #pragma unroll
    for (int i = 0; i < 4; i++) {
        int idx = tid + i * 256;
        int row = idx >> 3, seg = idx & 7;
        size_t src = (size_t)(b * SS + q0 + row) * HDD + h * 64 + seg * 8;
        CP_ASYNC16(sQh + row * 144 + seg * 16, qh + src);
        CP_ASYNC16(sQl + row * 144 + seg * 16, ql + src);
    }
    CP_COMMIT();

    #define FA_FILL(kt_) do { \
        const int stg_ = (kt_) & 1; \
        const uint32_t sb_ = base + FA_STG0 + stg_ * FA_STGSZ; \
        const int k0_ = (kt_) * 128; \
        _Pragma("unroll") \
        for (int i_ = 0; i_ < 4; i_++) { \
            int idx_ = tid + i_ * 256; \
            int row_ = idx_ >> 3, seg_ = idx_ & 7; \
            size_t src_ = (size_t)(b * SS + k0_ + row_) * HDD + h * 64 + seg_ * 8; \
            CP_ASYNC16(sb_ + FA_KH + row_ * 144 + seg_ * 16, kh + src_); \
            CP_ASYNC16(sb_ + FA_KL + row_ * 144 + seg_ * 16, kl + src_); \
        } \
        _Pragma("unroll") \
        for (int i_ = 0; i_ < 4; i_++) { \
            int idx_ = tid + i_ * 256; \
            int row_ = idx_ >> 4, seg_ = idx_ & 15; \
            size_t src_ = ((size_t)z * 64 + row_) * SS + k0_ + seg_ * 8; \
            CP_ASYNC16(sb_ + FA_VH + row_ * 272 + seg_ * 16, vth + src_); \
            CP_ASYNC16(sb_ + FA_VL + row_ * 272 + seg_ * 16, vtl + src_); \
        } \
        CP_COMMIT(); \
        if (tid < 128) \
            ((float*)(smem_raw + FA_STG0 + stg_ * FA_STGSZ + FA_MSK))[tid] = \
                (tok[b * SS + k0_ + tid] == 0) ? -1e9f : 0.f; \
    } while (0)

    FA_FILL(0);

    float m0 = -3.0e38f, m1 = -3.0e38f, l0 = 0.f, l1 = 0.f;
    float O[8][4];
    #pragma unroll
    for (int i = 0; i < 8; i++)
        #pragma unroll
        for (int j = 0; j < 4; j++) O[i][j] = 0.f;

    uint32_t qfh[4][4], qfl[4][4];

    for (int kt = 0; kt < 8; kt++) {
        if (kt + 1 < 8) { FA_FILL(kt + 1); CP_WAITG(1); }
        else            { CP_WAITG(0); }
        __syncthreads();

        const uint32_t sb = base + FA_STG0 + (uint32_t)(kt & 1) * FA_STGSZ;
        const uint32_t sKh = sb + FA_KH, sKl = sb + FA_KL;
        const uint32_t sVh = sb + FA_VH, sVl = sb + FA_VL;
        const float* maskf = (const float*)(smem_raw + FA_STG0 + (kt & 1) * FA_STGSZ + FA_MSK);

        if (kt == 0) {
            #pragma unroll
            for (int ks = 0; ks < 4; ks++) {
                uint32_t ad = (wid * 16 + lrow) * 144 + (ks * 16 + khalf * 8) * 2;
                LDM_X4(qfh[ks][0], qfh[ks][1], qfh[ks][2], qfh[ks][3], sQh + ad);
                LDM_X4(qfl[ks][0], qfl[ks][1], qfl[ks][2], qfl[ks][3], sQl + ad);
            }
        }

        // ---- S = Q K^T (split, 3 passes) ----
        float Sv[16][4];
        #pragma unroll
        for (int i = 0; i < 16; i++)
            #pragma unroll
            for (int j = 0; j < 4; j++) Sv[i][j] = 0.f;

        #pragma unroll
        for (int ks = 0; ks < 4; ks++) {
            #pragma unroll
            for (int ng = 0; ng < 8; ng++) {
                uint32_t bd = (ng * 16 + lrow) * 144 + (ks * 16 + khalf * 8) * 2;
                uint32_t bh_[4], bl_[4];
                LDM_X4(bh_[0], bh_[1], bh_[2], bh_[3], sKh + bd);
                LDM_X4(bl_[0], bl_[1], bl_[2], bl_[3], sKl + bd);
                MMA_BF16(Sv[2*ng],   qfh[ks], bh_[0], bh_[2]);
                MMA_BF16(Sv[2*ng],   qfh[ks], bl_[0], bl_[2]);
                MMA_BF16(Sv[2*ng],   qfl[ks], bh_[0], bh_[2]);
                MMA_BF16(Sv[2*ng+1], qfh[ks], bh_[1], bh_[3]);
                MMA_BF16(Sv[2*ng+1], qfh[ks], bl_[1], bl_[3]);
                MMA_BF16(Sv[2*ng+1], qfl[ks], bh_[1], bh_[3]);
            }
        }

        // ---- scale + mask + online softmax ----
        float mt0 = -3.0e38f, mt1 = -3.0e38f;
        #pragma unroll
        for (int nb = 0; nb < 16; nb++) {
            float mk0 = maskf[nb * 8 + cpos], mk1 = maskf[nb * 8 + cpos + 1];
            Sv[nb][0] = Sv[nb][0] * 0.125f + mk0;
            Sv[nb][1] = Sv[nb][1] * 0.125f + mk1;
            Sv[nb][2] = Sv[nb][2] * 0.125f + mk0;
            Sv[nb][3] = Sv[nb][3] * 0.125f + mk1;
            mt0 = fmaxf(mt0, fmaxf(Sv[nb][0], Sv[nb][1]));
            mt1 = fmaxf(mt1, fmaxf(Sv[nb][2], Sv[nb][3]));
        }
        mt0 = fmaxf(mt0, __shfl_xor_sync(0xffffffffu, mt0, 1));
        mt0 = fmaxf(mt0, __shfl_xor_sync(0xffffffffu, mt0, 2));
        mt1 = fmaxf(mt1, __shfl_xor_sync(0xffffffffu, mt1, 1));
        mt1 = fmaxf(mt1, __shfl_xor_sync(0xffffffffu, mt1, 2));

        float mn0 = fmaxf(m0, mt0), mn1 = fmaxf(m1, mt1);
        float al0 = __expf(m0 - mn0), al1 = __expf(m1 - mn1);
        float su0 = 0.f, su1 = 0.f;
        #pragma unroll
        for (int nb = 0; nb < 16; nb++) {
            Sv[nb][0] = __expf(Sv[nb][0] - mn0);
            Sv[nb][1] = __expf(Sv[nb][1] - mn0);
            Sv[nb][2] = __expf(Sv[nb][2] - mn1);
            Sv[nb][3] = __expf(Sv[nb][3] - mn1);
            su0 += Sv[nb][0] + Sv[nb][1];
            su1 += Sv[nb][2] + Sv[nb][3];
        }
        su0 += __shfl_xor_sync(0xffffffffu, su0, 1);
        su0 += __shfl_xor_sync(0xffffffffu, su0, 2);
        su1 += __shfl_xor_sync(0xffffffffu, su1, 1);
        su1 += __shfl_xor_sync(0xffffffffu, su1, 2);

        l0 = l0 * al0 + su0;
        l1 = l1 * al1 + su1;
        m0 = mn0; m1 = mn1;
        #pragma unroll
        for (int nf = 0; nf < 8; nf++) {
            O[nf][0] *= al0; O[nf][1] *= al0;
            O[nf][2] *= al1; O[nf][3] *= al1;
        }

        // ---- O += P V (split, 3 passes) ----
        #pragma unroll
        for (int j = 0; j < 8; j++) {
            float v00 = Sv[2*j][0],  v01 = Sv[2*j][1],  v02 = Sv[2*j][2],  v03 = Sv[2*j][3];
            float v10 = Sv[2*j+1][0],v11 = Sv[2*j+1][1],v12 = Sv[2*j+1][2],v13 = Sv[2*j+1][3];
            uint32_t pa_h[4], pa_l[4];
            pa_h[0] = pk2(v00, v01); pa_l[0] = pk2(v00 - bhi(v00), v01 - bhi(v01));
            pa_h[1] = pk2(v02, v03); pa_l[1] = pk2(v02 - bhi(v02), v03 - bhi(v03));
            pa_h[2] = pk2(v10, v11); pa_l[2] = pk2(v10 - bhi(v10), v11 - bhi(v11));
            pa_h[3] = pk2(v12, v13); pa_l[3] = pk2(v12 - bhi(v12), v13 - bhi(v13));
            #pragma unroll
            for (int ng = 0; ng < 4; ng++) {
                uint32_t bd = (ng * 16 + lrow) * 272 + (j * 16 + khalf * 8) * 2;
                uint32_t vh_[4], vl_[4];
                LDM_X4(vh_[0], vh_[1], vh_[2], vh_[3], sVh + bd);
                LDM_X4(vl_[0], vl_[1], vl_[2], vl_[3], sVl + bd);
                MMA_BF16(O[2*ng],   pa_h, vh_[0], vh_[2]);
                MMA_BF16(O[2*ng],   pa_h, vl_[0], vl_[2]);
                MMA_BF16(O[2*ng],   pa_l, vh_[0], vh_[2]);
                MMA_BF16(O[2*ng+1], pa_h, vh_[1], vh_[3]);
                MMA_BF16(O[2*ng+1], pa_h, vl_[1], vl_[3]);
                MMA_BF16(O[2*ng+1], pa_l, vh_[1], vh_[3]);
            }
        }
        __syncthreads();
    }
    #undef FA_FILL

    // ---- normalize + write ctx hi/lo ----
    float i0 = 1.f / l0, i1 = 1.f / l1;
    const int rgl = b * SS + q0 + wid * 16 + (lane >> 2);
    #pragma unroll
    for (int nf = 0; nf < 8; nf++) {
        int col = h * 64 + nf * 8 + cpos;
        float a0 = O[nf][0] * i0, a1 = O[nf][1] * i0;
        float a2 = O[nf][2] * i1, a3 = O[nf][3] * i1;
        size_t o0 = (size_t)rgl * HDD + col;
        size_t o1 = (size_t)(rgl + 8) * HDD + col;
        *(uint32_t*)(ch + o0) = pk2(a0, a1);
        *(uint32_t*)(ch + o1) = pk2(a2, a3);
        *(uint32_t*)(cl + o0) = pk2(a0 - bhi(a0), a1 - bhi(a1));
        *(uint32_t*)(cl + o1) = pk2(a2 - bhi(a2), a3 - bhi(a3));
    }
}

// ==================== embed + add_ln (emit fp32 and hi/lo) ====================
__global__ __launch_bounds__(256) void embed_kernel(
    const int* __restrict__ tok, const float* __restrict__ emb,
    float* __restrict__ x, __nv_bfloat16* __restrict__ xh, __nv_bfloat16* __restrict__ xl)
{
    int row = blockIdx.x;
    int s = row % SS;
    int t = tok[row];
    const float* e = emb + (size_t)t * DD;
    for (int d = threadIdx.x; d < DD; d += 256) {
        int i = d >> 1;
        float freq = expf(-((float)(2 * i) / (float)DD) * 9.210340371976184f);
        float a = (float)s * freq;
        float pe = (d & 1) ? cosf(a) : sinf(a);
        float v = e[d] + pe;
        size_t o = (size_t)row * DD + d;
        x[o] = v;
        __nv_bfloat16 hh = __float2bfloat16(v);
        xh[o] = hh;
        xl[o] = __float2bfloat16(v - __bfloat162float(hh));
    }
}

__device__ __forceinline__ float block_sum(float v, float* sh) {
    __syncthreads();
    #pragma unroll
    for (int o = 16; o > 0; o >>= 1) v += __shfl_xor_sync(0xffffffffu, v, o);
    int w = threadIdx.x >> 5;
    if ((threadIdx.x & 31) == 0) sh[w] = v;
    __syncthreads();
    float t = (threadIdx.x < 8) ? sh[threadIdx.x] : 0.0f;
    #pragma unroll
    for (int o = 4; o > 0; o >>= 1) t += __shfl_xor_sync(0xffffffffu, t, o);
    if (threadIdx.x == 0) sh[0] = t;
    __syncthreads();
    return sh[0];
}

__global__ __launch_bounds__(256) void add_ln(
    const float* __restrict__ xin, const float* __restrict__ delta,
    const float* __restrict__ g, const float* __restrict__ bta,
    float* __restrict__ out, __nv_bfloat16* __restrict__ oh, __nv_bfloat16* __restrict__ ol)
{
    size_t row = blockIdx.x;
    const float* xr = xin   + row * DD;
    const float* dr = delta + row * DD;
    int tid = threadIdx.x;
    __shared__ float red[8];

    float v[4];
    float s = 0.f;
    #pragma unroll
    for (int j = 0; j < 4; j++) {
        int c = tid + j * 256;
        v[j] = xr[c] + dr[c];
        s += v[j];
    }
    s = block_sum(s, red);
    float mu = s * (1.0f / 1024.0f);
    float var = 0.f;
    #pragma unroll
    for (int j = 0; j < 4; j++) { float t = v[j] - mu; var += t * t; }
    var = block_sum(var, red) * (1.0f / 1024.0f);
    float inv = rsqrtf(var + 1e-5f);
    #pragma unroll
    for (int j = 0; j < 4; j++) {
        int c = tid + j * 256;
        float o = (v[j] - mu) * inv * g[c] + bta[c];
        size_t idx = row * DD + c;
        out[idx] = o;
        __nv_bfloat16 hh = __float2bfloat16(o);
        oh[idx] = hh;
        ol[idx] = __float2bfloat16(o - __bfloat162float(hh));
    }
}

// ==================== host orchestration ====================
extern "C" void kernel_launch(void* const* d_in, const int* in_sizes, int n_in,
                              void* d_out, int out_size)
{
    (void)in_sizes; (void)n_in; (void)out_size;
    const int*   tok  = (const int*)  d_in[0];
    const float* emb  = (const float*)d_in[1];
    const float* Wq   = (const float*)d_in[2];
    const float* bq   = (const float*)d_in[3];
    const float* Wk   = (const float*)d_in[4];
    const float* bk   = (const float*)d_in[5];
    const float* Wv   = (const float*)d_in[6];
    const float* bv   = (const float*)d_in[7];
    const float* Wo   = (const float*)d_in[8];
    const float* bo   = (const float*)d_in[9];
    const float* ln1g = (const float*)d_in[10];
    const float* ln1b = (const float*)d_in[11];
    const float* W1   = (const float*)d_in[12];
    const float* W2   = (const float*)d_in[13];
    const float* ln2g = (const float*)d_in[14];
    const float* ln2b = (const float*)d_in[15];
    float* out = (float*)d_out;

    float *x, *v, *tmp;
    __nv_bfloat16 *xh, *xl, *qh, *ql, *kh, *kl, *vth, *vtl, *ch, *cl, *fh, *fl, *wh, *wl;
    cudaGetSymbolAddress((void**)&x,   g_x);
    cudaGetSymbolAddress((void**)&v,   g_v);
    cudaGetSymbolAddress((void**)&tmp, g_tmp);
    cudaGetSymbolAddress((void**)&xh,  g_xh);  cudaGetSymbolAddress((void**)&xl, g_xl);
    cudaGetSymbolAddress((void**)&qh,  g_qh);  cudaGetSymbolAddress((void**)&ql, g_ql);
    cudaGetSymbolAddress((void**)&kh,  g_kh);  cudaGetSymbolAddress((void**)&kl, g_kl);
    cudaGetSymbolAddress((void**)&vth, g_vth); cudaGetSymbolAddress((void**)&vtl, g_vtl);
    cudaGetSymbolAddress((void**)&ch,  g_ch);  cudaGetSymbolAddress((void**)&cl, g_cl);
    cudaGetSymbolAddress((void**)&fh,  g_fh);  cudaGetSymbolAddress((void**)&fl, g_fl);
    cudaGetSymbolAddress((void**)&wh,  g_wh);  cudaGetSymbolAddress((void**)&wl, g_wl);

    static int attr_done = 0;
    if (!attr_done) {
        cudaFuncSetAttribute(gemm_mma, cudaFuncAttributeMaxDynamicSharedMemorySize, GSM_BYTES);
        cudaFuncSetAttribute(flash_attn, cudaFuncAttributeMaxDynamicSharedMemorySize, FA_SMEM);
        attr_done = 1;
    }

    // ---- transpose-split weights ----
    dim3 tsB(256);
    for (int l = 0; l < LL; l++) {
        tsplit_kernel<<<dim3(HDD/32, DD/32), tsB>>>(Wq + (size_t)l*DD*HDD, wh + WQT_OFF + l*SZ_P, wl + WQT_OFF + l*SZ_P, DD, HDD);
        tsplit_kernel<<<dim3(HDD/32, DD/32), tsB>>>(Wk + (size_t)l*DD*HDD, wh + WKT_OFF + l*SZ_P, wl + WKT_OFF + l*SZ_P, DD, HDD);
        tsplit_kernel<<<dim3(HDD/32, DD/32), tsB>>>(Wv + (size_t)l*DD*HDD, wh + WVT_OFF + l*SZ_P, wl + WVT_OFF + l*SZ_P, DD, HDD);
        tsplit_kernel<<<dim3(DD/32, HDD/32), tsB>>>(Wo + (size_t)l*HDD*DD, wh + WOT_OFF + l*SZ_P, wl + WOT_OFF + l*SZ_P, HDD, DD);
        tsplit_kernel<<<dim3(FF/32,  DD/32), tsB>>>(W1 + (size_t)l*DD*FF,  wh + W1T_OFF + l*SZ_F, wl + W1T_OFF + l*SZ_F, DD, FF);
        tsplit_kernel<<<dim3(DD/32,  FF/32), tsB>>>(W2 + (size_t)l*FF*DD,  wh + W2T_OFF + l*SZ_F, wl + W2T_OFF + l*SZ_F, FF, DD);
    }

    embed_kernel<<<MR, 256>>>(tok, emb, x, xh, xl);

    dim3 gP(HDD/128, MR/128);
    dim3 gF1(FF/128, MR/128);
    dim3 gF2(DD/128, MR/128);
    dim3 gVT(2, 32, 32);
    dim3 gFA(SS/128, BB*HH);

    for (int l = 0; l < LL; l++) {
        const __nv_bfloat16* wqh = wh + WQT_OFF + l*SZ_P; const __nv_bfloat16* wql = wl + WQT_OFF + l*SZ_P;
        const __nv_bfloat16* wkh = wh + WKT_OFF + l*SZ_P; const __nv_bfloat16* wkl = wl + WKT_OFF + l*SZ_P;
        const __nv_bfloat16* wvh = wh + WVT_OFF + l*SZ_P; const __nv_bfloat16* wvl = wl + WVT_OFF + l*SZ_P;
        const __nv_bfloat16* woh = wh + WOT_OFF + l*SZ_P; const __nv_bfloat16* wol = wl + WOT_OFF + l*SZ_P;
        const __nv_bfloat16* w1h = wh + W1T_OFF + l*SZ_F; const __nv_bfloat16* w1l = wl + W1T_OFF + l*SZ_F;
        const __nv_bfloat16* w2h = wh + W2T_OFF + l*SZ_F; const __nv_bfloat16* w2l = wl + W2T_OFF + l*SZ_F;

        gemm_mma<<<gP, 256, GSM_BYTES>>>(xh, xl, wqh, wql, bq + (size_t)l*HDD,
                                         (float*)nullptr, qh, ql, DD, HDD, 0);
        gemm_mma<<<gP, 256, GSM_BYTES>>>(xh, xl, wkh, wkl, bk + (size_t)l*HDD,
                                         (float*)nullptr, kh, kl, DD, HDD, 0);
        gemm_mma<<<gP, 256, GSM_BYTES>>>(xh, xl, wvh, wvl, bv + (size_t)l*HDD,
                                         v, (__nv_bfloat16*)nullptr, (__nv_bfloat16*)nullptr, DD, HDD, 0);
        vtsplit<<<gVT, 256>>>(v, vth, vtl);

        flash_attn<<<gFA, 256, FA_SMEM>>>(qh, ql, kh, kl, vth, vtl, tok, ch, cl);

        gemm_mma<<<gF2, 256, GSM_BYTES>>>(ch, cl, woh, wol, bo + (size_t)l*DD,
                                          tmp, (__nv_bfloat16*)nullptr, (__nv_bfloat16*)nullptr, HDD, DD, 0);
        add_ln<<<MR, 256>>>(x, tmp, ln1g + (size_t)l*DD, ln1b + (size_t)l*DD, x, xh, xl);

        gemm_mma<<<gF1, 256, GSM_BYTES>>>(xh, xl, w1h, w1l, (const float*)nullptr,
                                          (float*)nullptr, fh, fl, DD, FF, 1);
        gemm_mma<<<gF2, 256, GSM_BYTES>>>(fh, fl, w2h, w2l, (const float*)nullptr,
                                          tmp, (__nv_bfloat16*)nullptr, (__nv_bfloat16*)nullptr, FF, DD, 0);

        float* dst = (l == LL - 1) ? out : x;
        add_ln<<<MR, 256>>>(x, tmp, ln2g + (size_t)l*DD, ln2b + (size_t)l*DD, dst, xh, xl);
    }
}

// round 7
// speedup vs baseline: 6.0511x; 2.2080x over previous
#include <cuda_runtime.h>
#include <cuda_fp16.h>
#include <math.h>
#include <stdint.h>

#define BB   2
#define SS   1024
#define DD   1024
#define HH   16
#define HDD  1024
#define FF   4096
#define LL   4
#define MR   (BB*SS)
#define NQKV 3072

// -------------------- scratch --------------------
__device__ float g_x  [MR * DD];
__device__ float g_tmp[MR * DD];
__device__ __half g_xh[MR * DD];
__device__ __half g_qkv[(size_t)MR * NQKV];
__device__ __half g_ch[MR * HDD];
__device__ __half g_fh[(size_t)MR * FF];
__device__ float g_bqkv[LL * NQKV];

#define SZ_P ((size_t)HDD * DD)
#define SZ_F ((size_t)DD * FF)
#define WQKV_OFF ((size_t)0)
#define WOT_OFF  ((size_t)LL * 3 * SZ_P)
#define W1T_OFF  (WOT_OFF + (size_t)LL * SZ_P)
#define W2T_OFF  (W1T_OFF + (size_t)LL * SZ_F)
#define WT_TOTAL (W2T_OFF + (size_t)LL * SZ_F)
__device__ __half g_wh[WT_TOTAL];

// ==================== helpers ====================
__device__ __forceinline__ uint32_t smem_to_u32(const void* p) {
    uint32_t a;
    asm("{ .reg .u64 t; cvta.to.shared.u64 t, %1; cvt.u32.u64 %0, t; }" : "=r"(a) : "l"(p));
    return a;
}
#define CP_ASYNC16(dst, src) \
    asm volatile("cp.async.cg.shared.global [%0], [%1], 16;" \
        :: "r"((uint32_t)(dst)), "l"(__cvta_generic_to_global(src)) : "memory")
#define CP_COMMIT() asm volatile("cp.async.commit_group;" ::: "memory")
#define CP_WAITG(n) asm volatile("cp.async.wait_group %0;" :: "n"(n) : "memory")
#define LDM_X4(r0, r1, r2, r3, addr) \
    asm volatile("ldmatrix.sync.aligned.m8n8.x4.shared.b16 {%0,%1,%2,%3}, [%4];" \
        : "=r"(r0), "=r"(r1), "=r"(r2), "=r"(r3) : "r"(addr))
#define LDM_X4_T(r0, r1, r2, r3, addr) \
    asm volatile("ldmatrix.sync.aligned.m8n8.x4.trans.shared.b16 {%0,%1,%2,%3}, [%4];" \
        : "=r"(r0), "=r"(r1), "=r"(r2), "=r"(r3) : "r"(addr))
#define MMA_F16(acc, a, b0, b1) \
    asm volatile("mma.sync.aligned.m16n8k16.row.col.f32.f16.f16.f32 " \
        "{%0,%1,%2,%3},{%4,%5,%6,%7},{%8,%9},{%0,%1,%2,%3};" \
        : "+f"((acc)[0]), "+f"((acc)[1]), "+f"((acc)[2]), "+f"((acc)[3]) \
        : "r"((a)[0]), "r"((a)[1]), "r"((a)[2]), "r"((a)[3]), "r"(b0), "r"(b1))

__device__ __forceinline__ uint32_t hpk2(float a, float b) {
    __half2 t = __floats2half2_rn(a, b);
    return *reinterpret_cast<uint32_t*>(&t);
}
__device__ __forceinline__ float gelu_f(float v) {
    float x = v * 0.70710678118654752f;
    float ax = fabsf(x);
    float t = __fdividef(1.0f, fmaf(0.3275911f, ax, 1.0f));
    float p = t * fmaf(t, fmaf(t, fmaf(t, fmaf(t, 1.061405429f, -1.453152027f),
                               1.421413741f), -0.284496736f), 0.254829592f);
    float erfv = 1.0f - p * __expf(-ax * ax);
    erfv = copysignf(erfv, x);
    return 0.5f * v * (1.0f + erfv);
}

// ==================== weight transpose ====================
// W [K,N] fp32 -> th [N,K] fp16. 64x64 tiles.
__global__ __launch_bounds__(256) void tsplit_kernel(
    const float* __restrict__ W, __half* __restrict__ th, int K, int N)
{
    __shared__ float ts[64][65];
    const int n0 = blockIdx.x * 64, k0 = blockIdx.y * 64;
    const int tid = threadIdx.x;
    #pragma unroll
    for (int i = 0; i < 4; i++) {
        int e = tid + i * 256;
        int r = e >> 4, c4 = (e & 15) * 4;
        float4 v = *(const float4*)&W[(size_t)(k0 + r) * N + n0 + c4];
        ts[r][c4]     = v.x; ts[r][c4 + 1] = v.y;
        ts[r][c4 + 2] = v.z; ts[r][c4 + 3] = v.w;
    }
    __syncthreads();
    const int w = tid >> 5, lane = tid & 31;
    #pragma unroll
    for (int rr = 0; rr < 8; rr++) {
        int n = w * 8 + rr;
        float a = ts[lane * 2][n], b = ts[lane * 2 + 1][n];
        size_t o = (size_t)(n0 + n) * K + k0 + lane * 2;
        *(uint32_t*)&th[o] = hpk2(a, b);
    }
}

__global__ void biascat_kernel(const float* __restrict__ bq, const float* __restrict__ bk,
                               const float* __restrict__ bv, float* __restrict__ o)
{
    int i = blockIdx.x * 256 + threadIdx.x;
    int l = i / NQKV, r = i % NQKV;
    int seg = r >> 10, n = r & 1023;
    const float* s = (seg == 0) ? bq : (seg == 1) ? bk : bv;
    o[i] = s[l * 1024 + n];
}

// ==================== fp16 HMMA GEMM, 4-stage pipeline, 2 CTAs/SM ====================
// C[M,N] = act(A·B^T + bias); A [M,K] K-major, B [N,K] K-major, fp16.
#define KC 32
#define ARR_B 10240
#define STGB  (2 * ARR_B)
#define GSM_BYTES (4 * STGB)   // 81920

__global__ __launch_bounds__(256, 2) void gemm_mma(
    const __half* __restrict__ A, const __half* __restrict__ B,
    const float* __restrict__ bias, float* __restrict__ C,
    __half* __restrict__ Ch, int K, int N, int act)
{
    extern __shared__ __align__(128) char smem_raw[];
    const uint32_t sbase = smem_to_u32(smem_raw);

    const int tid  = threadIdx.x;
    const int lane = tid & 31;
    const int wid  = tid >> 5;
    const int wm   = wid & 3;
    const int wn   = wid >> 2;
    const int m0 = blockIdx.y * 128, n0 = blockIdx.x * 128;

    float acc[2][8][4];
    #pragma unroll
    for (int i = 0; i < 2; i++)
        #pragma unroll
        for (int j = 0; j < 8; j++)
            #pragma unroll
            for (int q2 = 0; q2 < 4; q2++) acc[i][j][q2] = 0.f;

    const int nc = K >> 5;

    #define FILL_STAGE(stg, kk) do { \
        const uint32_t so_ = sbase + (uint32_t)(stg) * STGB; \
        _Pragma("unroll") \
        for (int i_ = 0; i_ < 4; i_++) { \
            const int arr_ = i_ >> 1; \
            int rem_ = ((i_ & 1) << 8) + tid; \
            int row_ = rem_ >> 2, seg_ = rem_ & 3; \
            const __half* p_ = (arr_ == 0) ? A : B; \
            int rb_ = (arr_ == 0) ? m0 : n0; \
            uint32_t dst_ = so_ + (uint32_t)arr_ * ARR_B + row_ * 80 + seg_ * 16; \
            CP_ASYNC16(dst_, p_ + (size_t)(rb_ + row_) * K + (kk) + seg_ * 8); \
        } \
        CP_COMMIT(); \
    } while (0)

    FILL_STAGE(0, 0);
    FILL_STAGE(1, KC);
    FILL_STAGE(2, 2 * KC);

    const uint32_t lrow  = lane & 15;
    const uint32_t khalf = lane >> 4;
    const uint32_t a_row_off = (wm * 32 + lrow) * 80;
    const uint32_t b_row_off = (wn * 64 + lrow) * 80;

    for (int c = 0; c < nc; c++) {
        if (c > 0) __syncthreads();
        if (c + 3 < nc) { FILL_STAGE((c + 3) & 3, (c + 3) * KC); CP_WAITG(3); }
        else if (c + 2 < nc) CP_WAITG(2);
        else if (c + 1 < nc) CP_WAITG(1);
        else CP_WAITG(0);
        __syncthreads();

        const uint32_t so = sbase + (uint32_t)(c & 3) * STGB;
        const uint32_t sA = so, sB = so + ARR_B;

        #pragma unroll
        for (int ks = 0; ks < 2; ks++) {
            const uint32_t kofs = (ks * 16 + khalf * 8) * 2;
            uint32_t af[2][4];
            #pragma unroll
            for (int mb = 0; mb < 2; mb++) {
                uint32_t ad = a_row_off + mb * 16 * 80 + kofs;
                LDM_X4(af[mb][0], af[mb][1], af[mb][2], af[mb][3], sA + ad);
            }
            #pragma unroll
            for (int nb = 0; nb < 4; nb++) {
                uint32_t bd = b_row_off + nb * 16 * 80 + kofs;
                uint32_t bf_[4];
                LDM_X4(bf_[0], bf_[1], bf_[2], bf_[3], sB + bd);
                #pragma unroll
                for (int mb = 0; mb < 2; mb++) {
                    MMA_F16(acc[mb][nb * 2],     af[mb], bf_[0], bf_[2]);
                    MMA_F16(acc[mb][nb * 2 + 1], af[mb], bf_[1], bf_[3]);
                }
            }
        }
    }
    #undef FILL_STAGE

    const int mrow = m0 + wm * 32 + (lane >> 2);
    const int ncol0 = n0 + wn * 64 + (lane & 3) * 2;
    #pragma unroll
    for (int mb = 0; mb < 2; mb++) {
        #pragma unroll
        for (int nf = 0; nf < 8; nf++) {
            int n = ncol0 + nf * 8;
            float b0v = bias ? bias[n]     : 0.f;
            float b1v = bias ? bias[n + 1] : 0.f;
            float v0 = acc[mb][nf][0] + b0v;
            float v1 = acc[mb][nf][1] + b1v;
            float v2 = acc[mb][nf][2] + b0v;
            float v3 = acc[mb][nf][3] + b1v;
            if (act) { v0 = gelu_f(v0); v1 = gelu_f(v1); v2 = gelu_f(v2); v3 = gelu_f(v3); }
            int m = mrow + mb * 16;
            if (C) {
                *(float2*)(C + (size_t)m * N + n)       = make_float2(v0, v1);
                *(float2*)(C + (size_t)(m + 8) * N + n) = make_float2(v2, v3);
            }
            if (Ch) {
                *(uint32_t*)(Ch + (size_t)m * N + n)       = hpk2(v0, v1);
                *(uint32_t*)(Ch + (size_t)(m + 8) * N + n) = hpk2(v2, v3);
            }
        }
    }
}

// ==================== flash attention (fp16 single-pass) ====================
#define FA_Q     0
#define FA_STG0  18432
#define FA_K     0
#define FA_V     18432
#define FA_MSK   36864
#define FA_STGSZ 37376
#define FA_SMEM  (18432 + 2 * 37376)

__global__ __launch_bounds__(256, 1) void flash_attn(
    const __half* __restrict__ qkv, const int* __restrict__ tok,
    __half* __restrict__ ch)
{
    extern __shared__ __align__(128) char smem_raw[];
    const uint32_t base = smem_to_u32(smem_raw);
    const uint32_t sQ = base + FA_Q;

    const int tid = threadIdx.x, lane = tid & 31, wid = tid >> 5;
    const int q0 = blockIdx.x * 128;
    const int z = blockIdx.y, b = z >> 4, h = z & 15;
    const uint32_t lrow = lane & 15, khalf = lane >> 4;
    const int cpos = (lane & 3) * 2;
    const int colQ = h * 64, colK = 1024 + h * 64, colV = 2048 + h * 64;

    #pragma unroll
    for (int i = 0; i < 2; i++) {
        int idx = tid + i * 256;
        int row = idx >> 2, seg2 = (idx & 3) * 2;
        size_t src = (size_t)(b * SS + q0 + row) * NQKV + colQ + seg2 * 8;
        CP_ASYNC16(sQ + row * 144 + seg2 * 16, qkv + src);
        CP_ASYNC16(sQ + row * 144 + seg2 * 16 + 16, qkv + src + 8);
    }
    CP_COMMIT();

    #define FA_FILL(kt_) do { \
        const int stg_ = (kt_) & 1; \
        const uint32_t sb_ = base + FA_STG0 + stg_ * FA_STGSZ; \
        const int k0_ = (kt_) * 128; \
        _Pragma("unroll") \
        for (int i_ = 0; i_ < 4; i_++) { \
            int idx_ = tid + i_ * 256; \
            int row_ = idx_ >> 3, seg_ = idx_ & 7; \
            int isv_ = seg_ >> 2; int s2_ = seg_ & 3; \
            size_t src_ = (size_t)(b * SS + k0_ + row_) * NQKV + (isv_ ? colV : colK) + s2_ * 16; \
            uint32_t dst_ = sb_ + (isv_ ? FA_V : FA_K) + row_ * 144 + s2_ * 32; \
            CP_ASYNC16(dst_, qkv + src_); \
            CP_ASYNC16(dst_ + 16, qkv + src_ + 8); \
        } \
        CP_COMMIT(); \
        if (tid < 128) \
            ((float*)(smem_raw + FA_STG0 + stg_ * FA_STGSZ + FA_MSK))[tid] = \
                (tok[b * SS + k0_ + tid] == 0) ? -1e9f : 0.f; \
    } while (0)

    FA_FILL(0);

    float m0 = -3.0e38f, m1 = -3.0e38f, l0 = 0.f, l1 = 0.f;
    float O[8][4];
    #pragma unroll
    for (int i = 0; i < 8; i++)
        #pragma unroll
        for (int j = 0; j < 4; j++) O[i][j] = 0.f;

    uint32_t qf[4][4];

    for (int kt = 0; kt < 8; kt++) {
        if (kt + 1 < 8) { FA_FILL(kt + 1); CP_WAITG(1); }
        else            { CP_WAITG(0); }
        __syncthreads();

        const uint32_t sb = base + FA_STG0 + (uint32_t)(kt & 1) * FA_STGSZ;
        const uint32_t sK = sb + FA_K, sV = sb + FA_V;
        const float* maskf = (const float*)(smem_raw + FA_STG0 + (kt & 1) * FA_STGSZ + FA_MSK);

        if (kt == 0) {
            #pragma unroll
            for (int ks = 0; ks < 4; ks++) {
                uint32_t ad = (wid * 16 + lrow) * 144 + (ks * 16 + khalf * 8) * 2;
                LDM_X4(qf[ks][0], qf[ks][1], qf[ks][2], qf[ks][3], sQ + ad);
            }
        }

        float Sv[16][4];
        #pragma unroll
        for (int i = 0; i < 16; i++)
            #pragma unroll
            for (int j = 0; j < 4; j++) Sv[i][j] = 0.f;

        #pragma unroll
        for (int ks = 0; ks < 4; ks++) {
            #pragma unroll
            for (int ng = 0; ng < 8; ng++) {
                uint32_t bd = (ng * 16 + lrow) * 144 + (ks * 16 + khalf * 8) * 2;
                uint32_t bh_[4];
                LDM_X4(bh_[0], bh_[1], bh_[2], bh_[3], sK + bd);
                MMA_F16(Sv[2 * ng],     qf[ks], bh_[0], bh_[2]);
                MMA_F16(Sv[2 * ng + 1], qf[ks], bh_[1], bh_[3]);
            }
        }

        float mt0 = -3.0e38f, mt1 = -3.0e38f;
        #pragma unroll
        for (int nb = 0; nb < 16; nb++) {
            float mk0 = maskf[nb * 8 + cpos], mk1 = maskf[nb * 8 + cpos + 1];
            Sv[nb][0] = Sv[nb][0] * 0.125f + mk0;
            Sv[nb][1] = Sv[nb][1] * 0.125f + mk1;
            Sv[nb][2] = Sv[nb][2] * 0.125f + mk0;
            Sv[nb][3] = Sv[nb][3] * 0.125f + mk1;
            mt0 = fmaxf(mt0, fmaxf(Sv[nb][0], Sv[nb][1]));
            mt1 = fmaxf(mt1, fmaxf(Sv[nb][2], Sv[nb][3]));
        }
        mt0 = fmaxf(mt0, __shfl_xor_sync(0xffffffffu, mt0, 1));
        mt0 = fmaxf(mt0, __shfl_xor_sync(0xffffffffu, mt0, 2));
        mt1 = fmaxf(mt1, __shfl_xor_sync(0xffffffffu, mt1, 1));
        mt1 = fmaxf(mt1, __shfl_xor_sync(0xffffffffu, mt1, 2));

        float mn0 = fmaxf(m0, mt0), mn1 = fmaxf(m1, mt1);
        float al0 = __expf(m0 - mn0), al1 = __expf(m1 - mn1);
        float su0 = 0.f, su1 = 0.f;
        #pragma unroll
        for (int nb = 0; nb < 16; nb++) {
            Sv[nb][0] = __expf(Sv[nb][0] - mn0);
            Sv[nb][1] = __expf(Sv[nb][1] - mn0);
            Sv[nb][2] = __expf(Sv[nb][2] - mn1);
            Sv[nb][3] = __expf(Sv[nb][3] - mn1);
            su0 += Sv[nb][0] + Sv[nb][1];
            su1 += Sv[nb][2] + Sv[nb][3];
        }
        su0 += __shfl_xor_sync(0xffffffffu, su0, 1);
        su0 += __shfl_xor_sync(0xffffffffu, su0, 2);
        su1 += __shfl_xor_sync(0xffffffffu, su1, 1);
        su1 += __shfl_xor_sync(0xffffffffu, su1, 2);

        l0 = l0 * al0 + su0;
        l1 = l1 * al1 + su1;
        m0 = mn0; m1 = mn1;
        #pragma unroll
        for (int nf = 0; nf < 8; nf++) {
            O[nf][0] *= al0; O[nf][1] *= al0;
            O[nf][2] *= al1; O[nf][3] *= al1;
        }

        #pragma unroll
        for (int j = 0; j < 8; j++) {
            uint32_t pa[4];
            pa[0] = hpk2(Sv[2*j][0],   Sv[2*j][1]);
            pa[1] = hpk2(Sv[2*j][2],   Sv[2*j][3]);
            pa[2] = hpk2(Sv[2*j+1][0], Sv[2*j+1][1]);
            pa[3] = hpk2(Sv[2*j+1][2], Sv[2*j+1][3]);
            #pragma unroll
            for (int ng = 0; ng < 4; ng++) {
                uint32_t bd = sV + (j * 16 + lrow) * 144 + (ng * 16 + khalf * 8) * 2;
                uint32_t v0, v1, v2, v3;
                LDM_X4_T(v0, v1, v2, v3, bd);
                MMA_F16(O[2 * ng],     pa, v0, v1);
                MMA_F16(O[2 * ng + 1], pa, v2, v3);
            }
        }
        __syncthreads();
    }
    #undef FA_FILL

    float i0 = 1.f / l0, i1 = 1.f / l1;
    const int rgl = b * SS + q0 + wid * 16 + (lane >> 2);
    #pragma unroll
    for (int nf = 0; nf < 8; nf++) {
        int col = h * 64 + nf * 8 + cpos;
        size_t o0 = (size_t)rgl * HDD + col;
        size_t o1 = (size_t)(rgl + 8) * HDD + col;
        *(uint32_t*)(ch + o0) = hpk2(O[nf][0] * i0, O[nf][1] * i0);
        *(uint32_t*)(ch + o1) = hpk2(O[nf][2] * i1, O[nf][3] * i1);
    }
}

// ==================== embed + add_ln ====================
__global__ __launch_bounds__(256) void embed_kernel(
    const int* __restrict__ tok, const float* __restrict__ emb,
    float* __restrict__ x, __half* __restrict__ xh)
{
    int row = blockIdx.x;
    int s = row % SS;
    int t = tok[row];
    const float* e = emb + (size_t)t * DD;
    for (int d = threadIdx.x; d < DD; d += 256) {
        int i = d >> 1;
        float freq = expf(-((float)(2 * i) / (float)DD) * 9.210340371976184f);
        float a = (float)s * freq;
        float pe = (d & 1) ? cosf(a) : sinf(a);
        float v = e[d] + pe;
        size_t o = (size_t)row * DD + d;
        x[o] = v;
        xh[o] = __float2half_rn(v);
    }
}

__device__ __forceinline__ float block_sum(float v, float* sh) {
    __syncthreads();
    #pragma unroll
    for (int o = 16; o > 0; o >>= 1) v += __shfl_xor_sync(0xffffffffu, v, o);
    int w = threadIdx.x >> 5;
    if ((threadIdx.x & 31) == 0) sh[w] = v;
    __syncthreads();
    float t = (threadIdx.x < 8) ? sh[threadIdx.x] : 0.0f;
    #pragma unroll
    for (int o = 4; o > 0; o >>= 1) t += __shfl_xor_sync(0xffffffffu, t, o);
    if (threadIdx.x == 0) sh[0] = t;
    __syncthreads();
    return sh[0];
}

__global__ __launch_bounds__(256) void add_ln(
    const float* __restrict__ xin, const float* __restrict__ delta,
    const float* __restrict__ g, const float* __restrict__ bta,
    float* __restrict__ out, __half* __restrict__ oh)
{
    size_t row = blockIdx.x;
    const float* xr = xin   + row * DD;
    const float* dr = delta + row * DD;
    int tid = threadIdx.x;
    __shared__ float red[8];

    float v[4];
    float s = 0.f;
    #pragma unroll
    for (int j = 0; j < 4; j++) {
        int c = tid + j * 256;
        v[j] = xr[c] + dr[c];
        s += v[j];
    }
    s = block_sum(s, red);
    float mu = s * (1.0f / 1024.0f);
    float var = 0.f;
    #pragma unroll
    for (int j = 0; j < 4; j++) { float t = v[j] - mu; var += t * t; }
    var = block_sum(var, red) * (1.0f / 1024.0f);
    float inv = rsqrtf(var + 1e-5f);
    #pragma unroll
    for (int j = 0; j < 4; j++) {
        int c = tid + j * 256;
        float o = (v[j] - mu) * inv * g[c] + bta[c];
        size_t idx = row * DD + c;
        out[idx] = o;
        oh[idx] = __float2half_rn(o);
    }
}

// ==================== host orchestration ====================
extern "C" void kernel_launch(void* const* d_in, const int* in_sizes, int n_in,
                              void* d_out, int out_size)
{
    (void)in_sizes; (void)n_in; (void)out_size;
    const int*   tok  = (const int*)  d_in[0];
    const float* emb  = (const float*)d_in[1];
    const float* Wq   = (const float*)d_in[2];
    const float* bq   = (const float*)d_in[3];
    const float* Wk   = (const float*)d_in[4];
    const float* bk   = (const float*)d_in[5];
    const float* Wv   = (const float*)d_in[6];
    const float* bv   = (const float*)d_in[7];
    const float* Wo   = (const float*)d_in[8];
    const float* bo   = (const float*)d_in[9];
    const float* ln1g = (const float*)d_in[10];
    const float* ln1b = (const float*)d_in[11];
    const float* W1   = (const float*)d_in[12];
    const float* W2   = (const float*)d_in[13];
    const float* ln2g = (const float*)d_in[14];
    const float* ln2b = (const float*)d_in[15];
    float* out = (float*)d_out;

    float *x, *tmp, *bqkv;
    __half *xh, *qkv, *ch, *fh, *wh;
    cudaGetSymbolAddress((void**)&x,    g_x);
    cudaGetSymbolAddress((void**)&tmp,  g_tmp);
    cudaGetSymbolAddress((void**)&xh,   g_xh);
    cudaGetSymbolAddress((void**)&qkv,  g_qkv);
    cudaGetSymbolAddress((void**)&ch,   g_ch);
    cudaGetSymbolAddress((void**)&fh,   g_fh);
    cudaGetSymbolAddress((void**)&wh,   g_wh);
    cudaGetSymbolAddress((void**)&bqkv, g_bqkv);

    static int attr_done = 0;
    if (!attr_done) {
        cudaFuncSetAttribute(gemm_mma, cudaFuncAttributeMaxDynamicSharedMemorySize, GSM_BYTES);
        cudaFuncSetAttribute(flash_attn, cudaFuncAttributeMaxDynamicSharedMemorySize, FA_SMEM);
        attr_done = 1;
    }

    // ---- weight prep ----
    for (int l = 0; l < LL; l++) {
        __half* qkvW = wh + WQKV_OFF + (size_t)l * 3 * SZ_P;
        tsplit_kernel<<<dim3(HDD/64, DD/64), 256>>>(Wq + (size_t)l*DD*HDD, qkvW,          DD, HDD);
        tsplit_kernel<<<dim3(HDD/64, DD/64), 256>>>(Wk + (size_t)l*DD*HDD, qkvW + SZ_P,   DD, HDD);
        tsplit_kernel<<<dim3(HDD/64, DD/64), 256>>>(Wv + (size_t)l*DD*HDD, qkvW + 2*SZ_P, DD, HDD);
        tsplit_kernel<<<dim3(DD/64, HDD/64), 256>>>(Wo + (size_t)l*HDD*DD, wh + WOT_OFF + l*SZ_P, HDD, DD);
        tsplit_kernel<<<dim3(FF/64,  DD/64), 256>>>(W1 + (size_t)l*DD*FF,  wh + W1T_OFF + l*SZ_F, DD, FF);
        tsplit_kernel<<<dim3(DD/64,  FF/64), 256>>>(W2 + (size_t)l*FF*DD,  wh + W2T_OFF + l*SZ_F, FF, DD);
    }
    biascat_kernel<<<LL * NQKV / 256, 256>>>(bq, bk, bv, bqkv);

    embed_kernel<<<MR, 256>>>(tok, emb, x, xh);

    dim3 gQKV(NQKV/128, MR/128);
    dim3 gWo(DD/128, MR/128);
    dim3 gF1(FF/128, MR/128);
    dim3 gF2(DD/128, MR/128);
    dim3 gFA(SS/128, BB*HH);

    for (int l = 0; l < LL; l++) {
        const __half* wqkv = wh + WQKV_OFF + (size_t)l * 3 * SZ_P;
        const __half* woh  = wh + WOT_OFF + (size_t)l * SZ_P;
        const __half* w1h  = wh + W1T_OFF + (size_t)l * SZ_F;
        const __half* w2h  = wh + W2T_OFF + (size_t)l * SZ_F;

        gemm_mma<<<gQKV, 256, GSM_BYTES>>>(xh, wqkv, bqkv + (size_t)l*NQKV,
                                           (float*)nullptr, qkv, DD, NQKV, 0);

        flash_attn<<<gFA, 256, FA_SMEM>>>(qkv, tok, ch);

        gemm_mma<<<gWo, 256, GSM_BYTES>>>(ch, woh, bo + (size_t)l*DD,
                                          tmp, (__half*)nullptr, HDD, DD, 0);
        add_ln<<<MR, 256>>>(x, tmp, ln1g + (size_t)l*DD, ln1b + (size_t)l*DD, x, xh);

        gemm_mma<<<gF1, 256, GSM_BYTES>>>(xh, w1h, (const float*)nullptr,
                                          (float*)nullptr, fh, DD, FF, 1);
        gemm_mma<<<gF2, 256, GSM_BYTES>>>(fh, w2h, (const float*)nullptr,
                                          tmp, (__half*)nullptr, FF, DD, 0);

        float* dst = (l == LL - 1) ? out : x;
        add_ln<<<MR, 256>>>(x, tmp, ln2g + (size_t)l*DD, ln2b + (size_t)l*DD, dst, xh);
    }
}

// round 8
// speedup vs baseline: 6.3969x; 1.0571x over previous
#include <cuda_runtime.h>
#include <cuda_fp16.h>
#include <math.h>
#include <stdint.h>

#define BB   2
#define SS   1024
#define DD   1024
#define HH   16
#define HDD  1024
#define FF   4096
#define LL   4
#define MR   (BB*SS)
#define NQKV 3072

// -------------------- scratch --------------------
__device__ float g_x  [MR * DD];
__device__ float g_tmp[MR * DD];
__device__ float g_maskf[MR];
__device__ __half g_xh[MR * DD];
__device__ __half g_qkv[(size_t)MR * NQKV];
__device__ __half g_ch[MR * HDD];
__device__ __half g_fh[(size_t)MR * FF];
__device__ float g_bqkv[LL * NQKV];

#define SZ_P ((size_t)HDD * DD)
#define SZ_F ((size_t)DD * FF)
#define WQKV_OFF ((size_t)0)
#define WOT_OFF  ((size_t)LL * 3 * SZ_P)
#define W1T_OFF  (WOT_OFF + (size_t)LL * SZ_P)
#define W2T_OFF  (W1T_OFF + (size_t)LL * SZ_F)
#define WT_TOTAL (W2T_OFF + (size_t)LL * SZ_F)
__device__ __half g_wh[WT_TOTAL];

// ==================== helpers ====================
__device__ __forceinline__ uint32_t smem_to_u32(const void* p) {
    uint32_t a;
    asm("{ .reg .u64 t; cvta.to.shared.u64 t, %1; cvt.u32.u64 %0, t; }" : "=r"(a) : "l"(p));
    return a;
}
#define CP_ASYNC16(dst, src) \
    asm volatile("cp.async.cg.shared.global [%0], [%1], 16;" \
        :: "r"((uint32_t)(dst)), "l"(__cvta_generic_to_global(src)) : "memory")
#define CP_COMMIT() asm volatile("cp.async.commit_group;" ::: "memory")
#define CP_WAITG(n) asm volatile("cp.async.wait_group %0;" :: "n"(n) : "memory")
#define LDM_X4(r0, r1, r2, r3, addr) \
    asm volatile("ldmatrix.sync.aligned.m8n8.x4.shared.b16 {%0,%1,%2,%3}, [%4];" \
        : "=r"(r0), "=r"(r1), "=r"(r2), "=r"(r3) : "r"(addr))
#define LDM_X4_T(r0, r1, r2, r3, addr) \
    asm volatile("ldmatrix.sync.aligned.m8n8.x4.trans.shared.b16 {%0,%1,%2,%3}, [%4];" \
        : "=r"(r0), "=r"(r1), "=r"(r2), "=r"(r3) : "r"(addr))
#define MMA_F16(acc, a, b0, b1) \
    asm volatile("mma.sync.aligned.m16n8k16.row.col.f32.f16.f16.f32 " \
        "{%0,%1,%2,%3},{%4,%5,%6,%7},{%8,%9},{%0,%1,%2,%3};" \
        : "+f"((acc)[0]), "+f"((acc)[1]), "+f"((acc)[2]), "+f"((acc)[3]) \
        : "r"((a)[0]), "r"((a)[1]), "r"((a)[2]), "r"((a)[3]), "r"(b0), "r"(b1))

__device__ __forceinline__ uint32_t hpk2(float a, float b) {
    __half2 t = __floats2half2_rn(a, b);
    return *reinterpret_cast<uint32_t*>(&t);
}
__device__ __forceinline__ float gelu_f(float v) {
    float x = v * 0.70710678118654752f;
    float ax = fabsf(x);
    float t = __fdividef(1.0f, fmaf(0.3275911f, ax, 1.0f));
    float p = t * fmaf(t, fmaf(t, fmaf(t, fmaf(t, 1.061405429f, -1.453152027f),
                               1.421413741f), -0.284496736f), 0.254829592f);
    float erfv = 1.0f - p * __expf(-ax * ax);
    erfv = copysignf(erfv, x);
    return 0.5f * v * (1.0f + erfv);
}

// ==================== batched weight transpose ====================
__device__ __forceinline__ void tsplit_body(
    const float* __restrict__ W, __half* __restrict__ th, int K, int N)
{
    __shared__ float ts[64][65];
    const int n0 = blockIdx.x * 64, k0 = blockIdx.y * 64;
    const int tid = threadIdx.x;
    #pragma unroll
    for (int i = 0; i < 4; i++) {
        int e = tid + i * 256;
        int r = e >> 4, c4 = (e & 15) * 4;
        float4 v = *(const float4*)&W[(size_t)(k0 + r) * N + n0 + c4];
        ts[r][c4]     = v.x; ts[r][c4 + 1] = v.y;
        ts[r][c4 + 2] = v.z; ts[r][c4 + 3] = v.w;
    }
    __syncthreads();
    const int w = tid >> 5, lane = tid & 31;
    #pragma unroll
    for (int rr = 0; rr < 8; rr++) {
        int n = w * 8 + rr;
        float a = ts[lane * 2][n], b = ts[lane * 2 + 1][n];
        size_t o = (size_t)(n0 + n) * K + k0 + lane * 2;
        *(uint32_t*)&th[o] = hpk2(a, b);
    }
}

__global__ __launch_bounds__(256) void tsplit_qkv(
    const float* __restrict__ Wq, const float* __restrict__ Wk,
    const float* __restrict__ Wv, __half* __restrict__ th)
{
    int z = blockIdx.z;
    int l = z / 3, j = z - l * 3;
    const float* W = ((j == 0) ? Wq : (j == 1) ? Wk : Wv) + (size_t)l * SZ_P;
    __half* dst = th + ((size_t)l * 3 + j) * SZ_P;
    tsplit_body(W, dst, DD, HDD);
}

__global__ __launch_bounds__(256) void tsplit_b(
    const float* __restrict__ W, __half* __restrict__ th, int K, int N)
{
    size_t off = (size_t)blockIdx.z * K * N;
    tsplit_body(W + off, th + off, K, N);
}

__global__ void biascat_kernel(const float* __restrict__ bq, const float* __restrict__ bk,
                               const float* __restrict__ bv, float* __restrict__ o)
{
    int i = blockIdx.x * 256 + threadIdx.x;
    int l = i / NQKV, r = i % NQKV;
    int seg = r >> 10, n = r & 1023;
    const float* s = (seg == 0) ? bq : (seg == 1) ? bk : bv;
    o[i] = s[l * 1024 + n];
}

__global__ void mask_kernel(const int* __restrict__ tok, float* __restrict__ m)
{
    int i = blockIdx.x * 256 + threadIdx.x;
    m[i] = (tok[i] == 0) ? -1e9f : 0.f;
}

// ==================== fp16 HMMA GEMM, templated M-tile ====================
// C[M,N] = act(A·B^T + bias); A [M,K] K-major, B [N,K] K-major, fp16.
// N-tile 128 always; M-tile = MT (128 or 64). 4-stage cp.async, 2 CTAs/SM.
#define KC 32
#define ARR_B 10240

template<int MT>
__global__ __launch_bounds__(256, 2) void gemm_mma(
    const __half* __restrict__ A, const __half* __restrict__ B,
    const float* __restrict__ bias, float* __restrict__ C,
    __half* __restrict__ Ch, int K, int N, int act)
{
    constexpr uint32_t ARR_A = (uint32_t)MT * 80;
    constexpr uint32_t STGB  = ARR_A + ARR_B;
    constexpr int AITER = MT / 64;          // 2 for 128, 1 for 64
    constexpr int NFRAG = (MT == 128) ? 8 : 4;
    constexpr int NB    = NFRAG / 2;
    constexpr int WNW   = (MT == 128) ? 64 : 32;   // n-cols per warp

    extern __shared__ __align__(128) char smem_raw[];
    const uint32_t sbase = smem_to_u32(smem_raw);

    const int tid  = threadIdx.x;
    const int lane = tid & 31;
    const int wid  = tid >> 5;
    const int wm   = (MT == 128) ? (wid & 3) : (wid & 1);
    const int wn   = (MT == 128) ? (wid >> 2) : (wid >> 1);
    const int m0 = blockIdx.y * MT, n0 = blockIdx.x * 128;

    float acc[2][NFRAG][4];
    #pragma unroll
    for (int i = 0; i < 2; i++)
        #pragma unroll
        for (int j = 0; j < NFRAG; j++)
            #pragma unroll
            for (int q2 = 0; q2 < 4; q2++) acc[i][j][q2] = 0.f;

    const int nc = K >> 5;

    #define FILL_STAGE(stg, kk) do { \
        const uint32_t so_ = sbase + (uint32_t)(stg) * STGB; \
        _Pragma("unroll") \
        for (int i_ = 0; i_ < AITER + 2; i_++) { \
            const int isA_ = (i_ < AITER); \
            int rem_ = (isA_ ? i_ : (i_ - AITER)) * 256 + tid; \
            int row_ = rem_ >> 2, seg_ = rem_ & 3; \
            const __half* p_ = isA_ ? A : B; \
            int rb_ = isA_ ? m0 : n0; \
            uint32_t dst_ = so_ + (isA_ ? 0u : ARR_A) + row_ * 80 + seg_ * 16; \
            CP_ASYNC16(dst_, p_ + (size_t)(rb_ + row_) * K + (kk) + seg_ * 8); \
        } \
        CP_COMMIT(); \
    } while (0)

    FILL_STAGE(0, 0);
    FILL_STAGE(1, KC);
    FILL_STAGE(2, 2 * KC);

    const uint32_t lrow  = lane & 15;
    const uint32_t khalf = lane >> 4;
    const uint32_t a_row_off = (wm * 32 + lrow) * 80;
    const uint32_t b_row_off = (wn * WNW + lrow) * 80;

    for (int c = 0; c < nc; c++) {
        if (c > 0) __syncthreads();
        if (c + 3 < nc) { FILL_STAGE((c + 3) & 3, (c + 3) * KC); CP_WAITG(3); }
        else if (c + 2 < nc) CP_WAITG(2);
        else if (c + 1 < nc) CP_WAITG(1);
        else CP_WAITG(0);
        __syncthreads();

        const uint32_t so = sbase + (uint32_t)(c & 3) * STGB;
        const uint32_t sA = so, sB = so + ARR_A;

        #pragma unroll
        for (int ks = 0; ks < 2; ks++) {
            const uint32_t kofs = (ks * 16 + khalf * 8) * 2;
            uint32_t af[2][4];
            #pragma unroll
            for (int mb = 0; mb < 2; mb++) {
                uint32_t ad = a_row_off + mb * 16 * 80 + kofs;
                LDM_X4(af[mb][0], af[mb][1], af[mb][2], af[mb][3], sA + ad);
            }
            #pragma unroll
            for (int nb = 0; nb < NB; nb++) {
                uint32_t bd = b_row_off + nb * 16 * 80 + kofs;
                uint32_t bf_[4];
                LDM_X4(bf_[0], bf_[1], bf_[2], bf_[3], sB + bd);
                #pragma unroll
                for (int mb = 0; mb < 2; mb++) {
                    MMA_F16(acc[mb][nb * 2],     af[mb], bf_[0], bf_[2]);
                    MMA_F16(acc[mb][nb * 2 + 1], af[mb], bf_[1], bf_[3]);
                }
            }
        }
    }
    #undef FILL_STAGE

    const int mrow = m0 + wm * 32 + (lane >> 2);
    const int ncol0 = n0 + wn * WNW + (lane & 3) * 2;
    #pragma unroll
    for (int mb = 0; mb < 2; mb++) {
        #pragma unroll
        for (int nf = 0; nf < NFRAG; nf++) {
            int n = ncol0 + nf * 8;
            float b0v = bias ? bias[n]     : 0.f;
            float b1v = bias ? bias[n + 1] : 0.f;
            float v0 = acc[mb][nf][0] + b0v;
            float v1 = acc[mb][nf][1] + b1v;
            float v2 = acc[mb][nf][2] + b0v;
            float v3 = acc[mb][nf][3] + b1v;
            if (act) { v0 = gelu_f(v0); v1 = gelu_f(v1); v2 = gelu_f(v2); v3 = gelu_f(v3); }
            int m = mrow + mb * 16;
            if (C) {
                *(float2*)(C + (size_t)m * N + n)       = make_float2(v0, v1);
                *(float2*)(C + (size_t)(m + 8) * N + n) = make_float2(v2, v3);
            }
            if (Ch) {
                *(uint32_t*)(Ch + (size_t)m * N + n)       = hpk2(v0, v1);
                *(uint32_t*)(Ch + (size_t)(m + 8) * N + n) = hpk2(v2, v3);
            }
        }
    }
}

// ==================== flash attention (fp16, 64-key tiles, 2 CTAs/SM) ====================
#define FA_Q     0
#define FA_STG0  18432
#define FA_K     0
#define FA_V     9216
#define FA_MSK   18432
#define FA_STGSZ 18688
#define FA_SMEM  (18432 + 2 * 18688)   // 55808

__global__ __launch_bounds__(256, 2) void flash_attn(
    const __half* __restrict__ qkv, const float* __restrict__ maskg,
    __half* __restrict__ ch)
{
    extern __shared__ __align__(128) char smem_raw[];
    const uint32_t base = smem_to_u32(smem_raw);
    const uint32_t sQ = base + FA_Q;

    const int tid = threadIdx.x, lane = tid & 31, wid = tid >> 5;
    const int q0 = blockIdx.x * 128;
    const int z = blockIdx.y, b = z >> 4, h = z & 15;
    const uint32_t lrow = lane & 15, khalf = lane >> 4;
    const int cpos = (lane & 3) * 2;
    const int colQ = h * 64, colK = 1024 + h * 64, colV = 2048 + h * 64;

    #pragma unroll
    for (int i = 0; i < 2; i++) {
        int idx = tid + i * 256;
        int row = idx >> 2, seg2 = (idx & 3) * 2;
        size_t src = (size_t)(b * SS + q0 + row) * NQKV + colQ + seg2 * 8;
        CP_ASYNC16(sQ + row * 144 + seg2 * 16, qkv + src);
        CP_ASYNC16(sQ + row * 144 + seg2 * 16 + 16, qkv + src + 8);
    }
    CP_COMMIT();

    #define FA_FILL(kt_) do { \
        const int stg_ = (kt_) & 1; \
        const uint32_t sb_ = base + FA_STG0 + stg_ * FA_STGSZ; \
        const int k0_ = (kt_) * 64; \
        { int row_ = tid >> 2, s2_ = tid & 3; \
          size_t srck_ = (size_t)(b * SS + k0_ + row_) * NQKV + colK + s2_ * 16; \
          uint32_t dstk_ = sb_ + FA_K + row_ * 144 + s2_ * 32; \
          CP_ASYNC16(dstk_, qkv + srck_); \
          CP_ASYNC16(dstk_ + 16, qkv + srck_ + 8); \
          size_t srcv_ = (size_t)(b * SS + k0_ + row_) * NQKV + colV + s2_ * 16; \
          uint32_t dstv_ = sb_ + FA_V + row_ * 144 + s2_ * 32; \
          CP_ASYNC16(dstv_, qkv + srcv_); \
          CP_ASYNC16(dstv_ + 16, qkv + srcv_ + 8); } \
        if (tid < 16) \
            CP_ASYNC16(sb_ + FA_MSK + tid * 16, maskg + b * SS + k0_ + tid * 4); \
        CP_COMMIT(); \
    } while (0)

    FA_FILL(0);

    float m0 = -3.0e38f, m1 = -3.0e38f, l0 = 0.f, l1 = 0.f;
    float O[8][4];
    #pragma unroll
    for (int i = 0; i < 8; i++)
        #pragma unroll
        for (int j = 0; j < 4; j++) O[i][j] = 0.f;

    uint32_t qf[4][4];

    for (int kt = 0; kt < 16; kt++) {
        if (kt + 1 < 16) { FA_FILL(kt + 1); CP_WAITG(1); }
        else             { CP_WAITG(0); }
        __syncthreads();

        const uint32_t sb = base + FA_STG0 + (uint32_t)(kt & 1) * FA_STGSZ;
        const uint32_t sK = sb + FA_K, sV = sb + FA_V;
        const float* maskf = (const float*)(smem_raw + FA_STG0 + (kt & 1) * FA_STGSZ + FA_MSK);

        if (kt == 0) {
            #pragma unroll
            for (int ks = 0; ks < 4; ks++) {
                uint32_t ad = (wid * 16 + lrow) * 144 + (ks * 16 + khalf * 8) * 2;
                LDM_X4(qf[ks][0], qf[ks][1], qf[ks][2], qf[ks][3], sQ + ad);
            }
        }

        float Sv[8][4];
        #pragma unroll
        for (int i = 0; i < 8; i++)
            #pragma unroll
            for (int j = 0; j < 4; j++) Sv[i][j] = 0.f;

        #pragma unroll
        for (int ks = 0; ks < 4; ks++) {
            #pragma unroll
            for (int ng = 0; ng < 4; ng++) {
                uint32_t bd = (ng * 16 + lrow) * 144 + (ks * 16 + khalf * 8) * 2;
                uint32_t bh_[4];
                LDM_X4(bh_[0], bh_[1], bh_[2], bh_[3], sK + bd);
                MMA_F16(Sv[2 * ng],     qf[ks], bh_[0], bh_[2]);
                MMA_F16(Sv[2 * ng + 1], qf[ks], bh_[1], bh_[3]);
            }
        }

        float mt0 = -3.0e38f, mt1 = -3.0e38f;
        #pragma unroll
        for (int nb = 0; nb < 8; nb++) {
            float mk0 = maskf[nb * 8 + cpos], mk1 = maskf[nb * 8 + cpos + 1];
            Sv[nb][0] = Sv[nb][0] * 0.125f + mk0;
            Sv[nb][1] = Sv[nb][1] * 0.125f + mk1;
            Sv[nb][2] = Sv[nb][2] * 0.125f + mk0;
            Sv[nb][3] = Sv[nb][3] * 0.125f + mk1;
            mt0 = fmaxf(mt0, fmaxf(Sv[nb][0], Sv[nb][1]));
            mt1 = fmaxf(mt1, fmaxf(Sv[nb][2], Sv[nb][3]));
        }
        mt0 = fmaxf(mt0, __shfl_xor_sync(0xffffffffu, mt0, 1));
        mt0 = fmaxf(mt0, __shfl_xor_sync(0xffffffffu, mt0, 2));
        mt1 = fmaxf(mt1, __shfl_xor_sync(0xffffffffu, mt1, 1));
        mt1 = fmaxf(mt1, __shfl_xor_sync(0xffffffffu, mt1, 2));

        float mn0 = fmaxf(m0, mt0), mn1 = fmaxf(m1, mt1);
        float al0 = __expf(m0 - mn0), al1 = __expf(m1 - mn1);
        float su0 = 0.f, su1 = 0.f;
        #pragma unroll
        for (int nb = 0; nb < 8; nb++) {
            Sv[nb][0] = __expf(Sv[nb][0] - mn0);
            Sv[nb][1] = __expf(Sv[nb][1] - mn0);
            Sv[nb][2] = __expf(Sv[nb][2] - mn1);
            Sv[nb][3] = __expf(Sv[nb][3] - mn1);
            su0 += Sv[nb][0] + Sv[nb][1];
            su1 += Sv[nb][2] + Sv[nb][3];
        }
        su0 += __shfl_xor_sync(0xffffffffu, su0, 1);
        su0 += __shfl_xor_sync(0xffffffffu, su0, 2);
        su1 += __shfl_xor_sync(0xffffffffu, su1, 1);
        su1 += __shfl_xor_sync(0xffffffffu, su1, 2);

        l0 = l0 * al0 + su0;
        l1 = l1 * al1 + su1;
        m0 = mn0; m1 = mn1;
        #pragma unroll
        for (int nf = 0; nf < 8; nf++) {
            O[nf][0] *= al0; O[nf][1] *= al0;
            O[nf][2] *= al1; O[nf][3] *= al1;
        }

        #pragma unroll
        for (int j = 0; j < 4; j++) {
            uint32_t pa[4];
            pa[0] = hpk2(Sv[2*j][0],   Sv[2*j][1]);
            pa[1] = hpk2(Sv[2*j][2],   Sv[2*j][3]);
            pa[2] = hpk2(Sv[2*j+1][0], Sv[2*j+1][1]);
            pa[3] = hpk2(Sv[2*j+1][2], Sv[2*j+1][3]);
            #pragma unroll
            for (int ng = 0; ng < 4; ng++) {
                uint32_t bd = sV + (j * 16 + lrow) * 144 + (ng * 16 + khalf * 8) * 2;
                uint32_t v0, v1, v2, v3;
                LDM_X4_T(v0, v1, v2, v3, bd);
                MMA_F16(O[2 * ng],     pa, v0, v1);
                MMA_F16(O[2 * ng + 1], pa, v2, v3);
            }
        }
        __syncthreads();
    }
    #undef FA_FILL

    float i0 = 1.f / l0, i1 = 1.f / l1;
    const int rgl = b * SS + q0 + wid * 16 + (lane >> 2);
    #pragma unroll
    for (int nf = 0; nf < 8; nf++) {
        int col = h * 64 + nf * 8 + cpos;
        size_t o0 = (size_t)rgl * HDD + col;
        size_t o1 = (size_t)(rgl + 8) * HDD + col;
        *(uint32_t*)(ch + o0) = hpk2(O[nf][0] * i0, O[nf][1] * i0);
        *(uint32_t*)(ch + o1) = hpk2(O[nf][2] * i1, O[nf][3] * i1);
    }
}

// ==================== embed + add_ln ====================
__global__ __launch_bounds__(256) void embed_kernel(
    const int* __restrict__ tok, const float* __restrict__ emb,
    float* __restrict__ x, __half* __restrict__ xh)
{
    int row = blockIdx.x;
    int s = row % SS;
    int t = tok[row];
    const float* e = emb + (size_t)t * DD;
    for (int d = threadIdx.x; d < DD; d += 256) {
        int i = d >> 1;
        float freq = expf(-((float)(2 * i) / (float)DD) * 9.210340371976184f);
        float a = (float)s * freq;
        float pe = (d & 1) ? cosf(a) : sinf(a);
        float v = e[d] + pe;
        size_t o = (size_t)row * DD + d;
        x[o] = v;
        xh[o] = __float2half_rn(v);
    }
}

__device__ __forceinline__ float block_sum(float v, float* sh) {
    __syncthreads();
    #pragma unroll
    for (int o = 16; o > 0; o >>= 1) v += __shfl_xor_sync(0xffffffffu, v, o);
    int w = threadIdx.x >> 5;
    if ((threadIdx.x & 31) == 0) sh[w] = v;
    __syncthreads();
    float t = (threadIdx.x < 8) ? sh[threadIdx.x] : 0.0f;
    #pragma unroll
    for (int o = 4; o > 0; o >>= 1) t += __shfl_xor_sync(0xffffffffu, t, o);
    if (threadIdx.x == 0) sh[0] = t;
    __syncthreads();
    return sh[0];
}

__global__ __launch_bounds__(256) void add_ln(
    const float* __restrict__ xin, const float* __restrict__ delta,
    const float* __restrict__ g, const float* __restrict__ bta,
    float* __restrict__ out, __half* __restrict__ oh)
{
    size_t row = blockIdx.x;
    const float* xr = xin   + row * DD;
    const float* dr = delta + row * DD;
    int tid = threadIdx.x;
    __shared__ float red[8];

    float v[4];
    float s = 0.f;
    #pragma unroll
    for (int j = 0; j < 4; j++) {
        int c = tid + j * 256;
        v[j] = xr[c] + dr[c];
        s += v[j];
    }
    s = block_sum(s, red);
    float mu = s * (1.0f / 1024.0f);
    float var = 0.f;
    #pragma unroll
    for (int j = 0; j < 4; j++) { float t = v[j] - mu; var += t * t; }
    var = block_sum(var, red) * (1.0f / 1024.0f);
    float inv = rsqrtf(var + 1e-5f);
    #pragma unroll
    for (int j = 0; j < 4; j++) {
        int c = tid + j * 256;
        float o = (v[j] - mu) * inv * g[c] + bta[c];
        size_t idx = row * DD + c;
        out[idx] = o;
        oh[idx] = __float2half_rn(o);
    }
}

// ==================== host orchestration ====================
extern "C" void kernel_launch(void* const* d_in, const int* in_sizes, int n_in,
                              void* d_out, int out_size)
{
    (void)in_sizes; (void)n_in; (void)out_size;
    const int*   tok  = (const int*)  d_in[0];
    const float* emb  = (const float*)d_in[1];
    const float* Wq   = (const float*)d_in[2];
    const float* bq   = (const float*)d_in[3];
    const float* Wk   = (const float*)d_in[4];
    const float* bk   = (const float*)d_in[5];
    const float* Wv   = (const float*)d_in[6];
    const float* bv   = (const float*)d_in[7];
    const float* Wo   = (const float*)d_in[8];
    const float* bo   = (const float*)d_in[9];
    const float* ln1g = (const float*)d_in[10];
    const float* ln1b = (const float*)d_in[11];
    const float* W1   = (const float*)d_in[12];
    const float* W2   = (const float*)d_in[13];
    const float* ln2g = (const float*)d_in[14];
    const float* ln2b = (const float*)d_in[15];
    float* out = (float*)d_out;

    float *x, *tmp, *bqkv, *maskg;
    __half *xh, *qkv, *ch, *fh, *wh;
    cudaGetSymbolAddress((void**)&x,     g_x);
    cudaGetSymbolAddress((void**)&tmp,   g_tmp);
    cudaGetSymbolAddress((void**)&maskg, g_maskf);
    cudaGetSymbolAddress((void**)&xh,    g_xh);
    cudaGetSymbolAddress((void**)&qkv,   g_qkv);
    cudaGetSymbolAddress((void**)&ch,    g_ch);
    cudaGetSymbolAddress((void**)&fh,    g_fh);
    cudaGetSymbolAddress((void**)&wh,    g_wh);
    cudaGetSymbolAddress((void**)&bqkv,  g_bqkv);

    const int GSM128 = 4 * (128 * 80 + ARR_B);   // 81920
    const int GSM64  = 4 * (64 * 80 + ARR_B);    // 61440

    static int attr_done = 0;
    if (!attr_done) {
        cudaFuncSetAttribute(gemm_mma<128>, cudaFuncAttributeMaxDynamicSharedMemorySize, GSM128);
        cudaFuncSetAttribute(gemm_mma<64>,  cudaFuncAttributeMaxDynamicSharedMemorySize, GSM64);
        cudaFuncSetAttribute(flash_attn, cudaFuncAttributeMaxDynamicSharedMemorySize, FA_SMEM);
        attr_done = 1;
    }

    // ---- weight/mask prep (batched) ----
    tsplit_qkv<<<dim3(HDD/64, DD/64, LL*3), 256>>>(Wq, Wk, Wv, wh + WQKV_OFF);
    tsplit_b<<<dim3(DD/64, HDD/64, LL), 256>>>(Wo, wh + WOT_OFF, HDD, DD);
    tsplit_b<<<dim3(FF/64,  DD/64, LL), 256>>>(W1, wh + W1T_OFF, DD, FF);
    tsplit_b<<<dim3(DD/64,  FF/64, LL), 256>>>(W2, wh + W2T_OFF, FF, DD);
    biascat_kernel<<<LL * NQKV / 256, 256>>>(bq, bk, bv, bqkv);
    mask_kernel<<<MR / 256, 256>>>(tok, maskg);

    embed_kernel<<<MR, 256>>>(tok, emb, x, xh);

    dim3 gQKV(NQKV/128, MR/128);   // 24 x 16 (MT=128)
    dim3 gWo(DD/128, MR/64);       // 8 x 32  (MT=64)
    dim3 gF1(FF/128, MR/128);      // 32 x 16 (MT=128)
    dim3 gF2(DD/128, MR/64);       // 8 x 32  (MT=64)
    dim3 gFA(SS/128, BB*HH);

    for (int l = 0; l < LL; l++) {
        const __half* wqkv = wh + WQKV_OFF + (size_t)l * 3 * SZ_P;
        const __half* woh  = wh + WOT_OFF + (size_t)l * SZ_P;
        const __half* w1h  = wh + W1T_OFF + (size_t)l * SZ_F;
        const __half* w2h  = wh + W2T_OFF + (size_t)l * SZ_F;

        gemm_mma<128><<<gQKV, 256, GSM128>>>(xh, wqkv, bqkv + (size_t)l*NQKV,
                                             (float*)nullptr, qkv, DD, NQKV, 0);

        flash_attn<<<gFA, 256, FA_SMEM>>>(qkv, maskg, ch);

        gemm_mma<64><<<gWo, 256, GSM64>>>(ch, woh, bo + (size_t)l*DD,
                                          tmp, (__half*)nullptr, HDD, DD, 0);
        add_ln<<<MR, 256>>>(x, tmp, ln1g + (size_t)l*DD, ln1b + (size_t)l*DD, x, xh);

        gemm_mma<128><<<gF1, 256, GSM128>>>(xh, w1h, (const float*)nullptr,
                                            (float*)nullptr, fh, DD, FF, 1);
        gemm_mma<64><<<gF2, 256, GSM64>>>(fh, w2h, (const float*)nullptr,
                                          tmp, (__half*)nullptr, FF, DD, 0);

        float* dst = (l == LL - 1) ? out : x;
        add_ln<<<MR, 256>>>(x, tmp, ln2g + (size_t)l*DD, ln2b + (size_t)l*DD, dst, xh);
    }
}

// round 9
// speedup vs baseline: 6.9193x; 1.0817x over previous
#include <cuda_runtime.h>
#include <cuda_fp16.h>
#include <math.h>
#include <stdint.h>

#define BB   2
#define SS   1024
#define DD   1024
#define HH   16
#define HDD  1024
#define FF   4096
#define LL   4
#define MR   (BB*SS)
#define NQKV 3072

// -------------------- scratch --------------------
__device__ float g_x  [MR * DD];
__device__ float g_maskf[MR];
__device__ __half g_tmph[MR * DD];
__device__ __half g_xh[MR * DD];
__device__ __half g_qkv[(size_t)MR * NQKV];
__device__ __half g_ch[MR * HDD];
__device__ __half g_fh[(size_t)MR * FF];
__device__ float g_bqkv[LL * NQKV];

#define SZ_P ((size_t)HDD * DD)
#define SZ_F ((size_t)DD * FF)
#define WQKV_OFF ((size_t)0)
#define WOT_OFF  ((size_t)LL * 3 * SZ_P)
#define W1T_OFF  (WOT_OFF + (size_t)LL * SZ_P)
#define W2T_OFF  (W1T_OFF + (size_t)LL * SZ_F)
#define WT_TOTAL (W2T_OFF + (size_t)LL * SZ_F)
__device__ __half g_wh[WT_TOTAL];

// ==================== helpers ====================
__device__ __forceinline__ uint32_t smem_to_u32(const void* p) {
    uint32_t a;
    asm("{ .reg .u64 t; cvta.to.shared.u64 t, %1; cvt.u32.u64 %0, t; }" : "=r"(a) : "l"(p));
    return a;
}
#define CP_ASYNC16(dst, src) \
    asm volatile("cp.async.cg.shared.global [%0], [%1], 16;" \
        :: "r"((uint32_t)(dst)), "l"(__cvta_generic_to_global(src)) : "memory")
#define CP_COMMIT() asm volatile("cp.async.commit_group;" ::: "memory")
#define CP_WAITG(n) asm volatile("cp.async.wait_group %0;" :: "n"(n) : "memory")
#define LDM_X4(r0, r1, r2, r3, addr) \
    asm volatile("ldmatrix.sync.aligned.m8n8.x4.shared.b16 {%0,%1,%2,%3}, [%4];" \
        : "=r"(r0), "=r"(r1), "=r"(r2), "=r"(r3) : "r"(addr))
#define LDM_X4_T(r0, r1, r2, r3, addr) \
    asm volatile("ldmatrix.sync.aligned.m8n8.x4.trans.shared.b16 {%0,%1,%2,%3}, [%4];" \
        : "=r"(r0), "=r"(r1), "=r"(r2), "=r"(r3) : "r"(addr))
#define MMA_F16(acc, a, b0, b1) \
    asm volatile("mma.sync.aligned.m16n8k16.row.col.f32.f16.f16.f32 " \
        "{%0,%1,%2,%3},{%4,%5,%6,%7},{%8,%9},{%0,%1,%2,%3};" \
        : "+f"((acc)[0]), "+f"((acc)[1]), "+f"((acc)[2]), "+f"((acc)[3]) \
        : "r"((a)[0]), "r"((a)[1]), "r"((a)[2]), "r"((a)[3]), "r"(b0), "r"(b1))

__device__ __forceinline__ uint32_t hpk2(float a, float b) {
    __half2 t = __floats2half2_rn(a, b);
    return *reinterpret_cast<uint32_t*>(&t);
}
__device__ __forceinline__ float gelu_f(float v) {
    float x = v * 0.70710678118654752f;
    float ax = fabsf(x);
    float t = __fdividef(1.0f, fmaf(0.3275911f, ax, 1.0f));
    float p = t * fmaf(t, fmaf(t, fmaf(t, fmaf(t, 1.061405429f, -1.453152027f),
                               1.421413741f), -0.284496736f), 0.254829592f);
    float erfv = 1.0f - p * __expf(-ax * ax);
    erfv = copysignf(erfv, x);
    return 0.5f * v * (1.0f + erfv);
}

// ==================== batched weight transpose ====================
__device__ __forceinline__ void tsplit_body(
    const float* __restrict__ W, __half* __restrict__ th, int K, int N)
{
    __shared__ float ts[64][65];
    const int n0 = blockIdx.x * 64, k0 = blockIdx.y * 64;
    const int tid = threadIdx.x;
    #pragma unroll
    for (int i = 0; i < 4; i++) {
        int e = tid + i * 256;
        int r = e >> 4, c4 = (e & 15) * 4;
        float4 v = *(const float4*)&W[(size_t)(k0 + r) * N + n0 + c4];
        ts[r][c4]     = v.x; ts[r][c4 + 1] = v.y;
        ts[r][c4 + 2] = v.z; ts[r][c4 + 3] = v.w;
    }
    __syncthreads();
    const int w = tid >> 5, lane = tid & 31;
    #pragma unroll
    for (int rr = 0; rr < 8; rr++) {
        int n = w * 8 + rr;
        float a = ts[lane * 2][n], b = ts[lane * 2 + 1][n];
        size_t o = (size_t)(n0 + n) * K + k0 + lane * 2;
        *(uint32_t*)&th[o] = hpk2(a, b);
    }
}

__global__ __launch_bounds__(256) void tsplit_qkv(
    const float* __restrict__ Wq, const float* __restrict__ Wk,
    const float* __restrict__ Wv, __half* __restrict__ th)
{
    int z = blockIdx.z;
    int l = z / 3, j = z - l * 3;
    const float* W = ((j == 0) ? Wq : (j == 1) ? Wk : Wv) + (size_t)l * SZ_P;
    __half* dst = th + ((size_t)l * 3 + j) * SZ_P;
    tsplit_body(W, dst, DD, HDD);
}

__global__ __launch_bounds__(256) void tsplit_b(
    const float* __restrict__ W, __half* __restrict__ th, int K, int N)
{
    size_t off = (size_t)blockIdx.z * K * N;
    tsplit_body(W + off, th + off, K, N);
}

__global__ void biascat_kernel(const float* __restrict__ bq, const float* __restrict__ bk,
                               const float* __restrict__ bv, float* __restrict__ o)
{
    int i = blockIdx.x * 256 + threadIdx.x;
    int l = i / NQKV, r = i % NQKV;
    int seg = r >> 10, n = r & 1023;
    const float* s = (seg == 0) ? bq : (seg == 1) ? bk : bv;
    o[i] = s[l * 1024 + n];
}

__global__ void mask_kernel(const int* __restrict__ tok, float* __restrict__ m)
{
    int i = blockIdx.x * 256 + threadIdx.x;
    m[i] = (tok[i] == 0) ? -1e9f : 0.f;
}

// ==================== fp16 HMMA GEMM, single-barrier 4-slot pipeline ====================
// Ch[M,N] = act(A·B^T + bias) in fp16; A [M,K] K-major, B [N,K] K-major.
#define KC 32
#define ARR_B 10240

template<int MT>
__global__ __launch_bounds__(256, 2) void gemm_mma(
    const __half* __restrict__ A, const __half* __restrict__ B,
    const float* __restrict__ bias, __half* __restrict__ Ch,
    int K, int N, int act)
{
    constexpr uint32_t ARR_A = (uint32_t)MT * 80;
    constexpr uint32_t STGB  = ARR_A + ARR_B;
    constexpr int AITER = MT / 64;
    constexpr int NFRAG = (MT == 128) ? 8 : 4;
    constexpr int NB    = NFRAG / 2;
    constexpr int WNW   = (MT == 128) ? 64 : 32;

    extern __shared__ __align__(128) char smem_raw[];
    const uint32_t sbase = smem_to_u32(smem_raw);

    const int tid  = threadIdx.x;
    const int lane = tid & 31;
    const int wid  = tid >> 5;
    const int wm   = (MT == 128) ? (wid & 3) : (wid & 1);
    const int wn   = (MT == 128) ? (wid >> 2) : (wid >> 1);
    const int m0 = blockIdx.y * MT, n0 = blockIdx.x * 128;

    float acc[2][NFRAG][4];
    #pragma unroll
    for (int i = 0; i < 2; i++)
        #pragma unroll
        for (int j = 0; j < NFRAG; j++)
            #pragma unroll
            for (int q2 = 0; q2 < 4; q2++) acc[i][j][q2] = 0.f;

    const int nc = K >> 5;

    #define FILL_STAGE(stg, kk) do { \
        const uint32_t so_ = sbase + (uint32_t)(stg) * STGB; \
        _Pragma("unroll") \
        for (int i_ = 0; i_ < AITER + 2; i_++) { \
            const int isA_ = (i_ < AITER); \
            int rem_ = (isA_ ? i_ : (i_ - AITER)) * 256 + tid; \
            int row_ = rem_ >> 2, seg_ = rem_ & 3; \
            const __half* p_ = isA_ ? A : B; \
            int rb_ = isA_ ? m0 : n0; \
            uint32_t dst_ = so_ + (isA_ ? 0u : ARR_A) + row_ * 80 + seg_ * 16; \
            CP_ASYNC16(dst_, p_ + (size_t)(rb_ + row_) * K + (kk) + seg_ * 8); \
        } \
        CP_COMMIT(); \
    } while (0)

    FILL_STAGE(0, 0);
    FILL_STAGE(1, KC);

    const uint32_t lrow  = lane & 15;
    const uint32_t khalf = lane >> 4;
    const uint32_t a_row_off = (wm * 32 + lrow) * 80;
    const uint32_t b_row_off = (wn * WNW + lrow) * 80;

    for (int c = 0; c < nc; c++) {
        if (c + 2 < nc) { FILL_STAGE((c + 2) & 3, (c + 2) * KC); CP_WAITG(2); }
        else if (c + 1 < nc) CP_WAITG(1);
        else CP_WAITG(0);
        __syncthreads();

        const uint32_t so = sbase + (uint32_t)(c & 3) * STGB;
        const uint32_t sA = so, sB = so + ARR_A;

        #pragma unroll
        for (int ks = 0; ks < 2; ks++) {
            const uint32_t kofs = (ks * 16 + khalf * 8) * 2;
            uint32_t af[2][4];
            #pragma unroll
            for (int mb = 0; mb < 2; mb++) {
                uint32_t ad = a_row_off + mb * 16 * 80 + kofs;
                LDM_X4(af[mb][0], af[mb][1], af[mb][2], af[mb][3], sA + ad);
            }
            #pragma unroll
            for (int nb = 0; nb < NB; nb++) {
                uint32_t bd = b_row_off + nb * 16 * 80 + kofs;
                uint32_t bf_[4];
                LDM_X4(bf_[0], bf_[1], bf_[2], bf_[3], sB + bd);
                #pragma unroll
                for (int mb = 0; mb < 2; mb++) {
                    MMA_F16(acc[mb][nb * 2],     af[mb], bf_[0], bf_[2]);
                    MMA_F16(acc[mb][nb * 2 + 1], af[mb], bf_[1], bf_[3]);
                }
            }
        }
    }
    #undef FILL_STAGE

    const int mrow = m0 + wm * 32 + (lane >> 2);
    const int ncol0 = n0 + wn * WNW + (lane & 3) * 2;
    #pragma unroll
    for (int mb = 0; mb < 2; mb++) {
        #pragma unroll
        for (int nf = 0; nf < NFRAG; nf++) {
            int n = ncol0 + nf * 8;
            float b0v = bias ? bias[n]     : 0.f;
            float b1v = bias ? bias[n + 1] : 0.f;
            float v0 = acc[mb][nf][0] + b0v;
            float v1 = acc[mb][nf][1] + b1v;
            float v2 = acc[mb][nf][2] + b0v;
            float v3 = acc[mb][nf][3] + b1v;
            if (act) { v0 = gelu_f(v0); v1 = gelu_f(v1); v2 = gelu_f(v2); v3 = gelu_f(v3); }
            int m = mrow + mb * 16;
            *(uint32_t*)(Ch + (size_t)m * N + n)       = hpk2(v0, v1);
            *(uint32_t*)(Ch + (size_t)(m + 8) * N + n) = hpk2(v2, v3);
        }
    }
}

// ==================== flash attention (fp16, 64-key tiles, 3-stage, 1 barrier/kt) ====================
#define FA_Q     0
#define FA_STG0  18432
#define FA_K     0
#define FA_V     9216
#define FA_MSK   18432
#define FA_STGSZ 18688
#define FA_SMEM  (18432 + 3 * 18688)   // 74496

__global__ __launch_bounds__(256, 2) void flash_attn(
    const __half* __restrict__ qkv, const float* __restrict__ maskg,
    __half* __restrict__ ch)
{
    extern __shared__ __align__(128) char smem_raw[];
    const uint32_t base = smem_to_u32(smem_raw);
    const uint32_t sQ = base + FA_Q;

    const int tid = threadIdx.x, lane = tid & 31, wid = tid >> 5;
    const int q0 = blockIdx.x * 128;
    const int z = blockIdx.y, b = z >> 4, h = z & 15;
    const uint32_t lrow = lane & 15, khalf = lane >> 4;
    const int cpos = (lane & 3) * 2;
    const int colQ = h * 64, colK = 1024 + h * 64, colV = 2048 + h * 64;

    #pragma unroll
    for (int i = 0; i < 2; i++) {
        int idx = tid + i * 256;
        int row = idx >> 2, seg2 = (idx & 3) * 2;
        size_t src = (size_t)(b * SS + q0 + row) * NQKV + colQ + seg2 * 8;
        CP_ASYNC16(sQ + row * 144 + seg2 * 16, qkv + src);
        CP_ASYNC16(sQ + row * 144 + seg2 * 16 + 16, qkv + src + 8);
    }
    CP_COMMIT();

    #define FA_FILL(kt_) do { \
        const int stg_ = (kt_) % 3; \
        const uint32_t sb_ = base + FA_STG0 + stg_ * FA_STGSZ; \
        const int k0_ = (kt_) * 64; \
        { int row_ = tid >> 2, s2_ = tid & 3; \
          size_t srck_ = (size_t)(b * SS + k0_ + row_) * NQKV + colK + s2_ * 16; \
          uint32_t dstk_ = sb_ + FA_K + row_ * 144 + s2_ * 32; \
          CP_ASYNC16(dstk_, qkv + srck_); \
          CP_ASYNC16(dstk_ + 16, qkv + srck_ + 8); \
          size_t srcv_ = (size_t)(b * SS + k0_ + row_) * NQKV + colV + s2_ * 16; \
          uint32_t dstv_ = sb_ + FA_V + row_ * 144 + s2_ * 32; \
          CP_ASYNC16(dstv_, qkv + srcv_); \
          CP_ASYNC16(dstv_ + 16, qkv + srcv_ + 8); } \
        if (tid < 16) \
            CP_ASYNC16(sb_ + FA_MSK + tid * 16, maskg + b * SS + k0_ + tid * 4); \
        CP_COMMIT(); \
    } while (0)

    FA_FILL(0);
    FA_FILL(1);

    float m0 = -3.0e38f, m1 = -3.0e38f, l0 = 0.f, l1 = 0.f;
    float O[8][4];
    #pragma unroll
    for (int i = 0; i < 8; i++)
        #pragma unroll
        for (int j = 0; j < 4; j++) O[i][j] = 0.f;

    uint32_t qf[4][4];

    for (int kt = 0; kt < 16; kt++) {
        if (kt + 2 < 16) { FA_FILL(kt + 2); CP_WAITG(2); }
        else if (kt + 1 < 16) CP_WAITG(1);
        else CP_WAITG(0);
        __syncthreads();

        const uint32_t sb = base + FA_STG0 + (uint32_t)(kt % 3) * FA_STGSZ;
        const uint32_t sK = sb + FA_K, sV = sb + FA_V;
        const float* maskf = (const float*)(smem_raw + FA_STG0 + (kt % 3) * FA_STGSZ + FA_MSK);

        if (kt == 0) {
            #pragma unroll
            for (int ks = 0; ks < 4; ks++) {
                uint32_t ad = (wid * 16 + lrow) * 144 + (ks * 16 + khalf * 8) * 2;
                LDM_X4(qf[ks][0], qf[ks][1], qf[ks][2], qf[ks][3], sQ + ad);
            }
        }

        float Sv[8][4];
        #pragma unroll
        for (int i = 0; i < 8; i++)
            #pragma unroll
            for (int j = 0; j < 4; j++) Sv[i][j] = 0.f;

        #pragma unroll
        for (int ks = 0; ks < 4; ks++) {
            #pragma unroll
            for (int ng = 0; ng < 4; ng++) {
                uint32_t bd = (ng * 16 + lrow) * 144 + (ks * 16 + khalf * 8) * 2;
                uint32_t bh_[4];
                LDM_X4(bh_[0], bh_[1], bh_[2], bh_[3], sK + bd);
                MMA_F16(Sv[2 * ng],     qf[ks], bh_[0], bh_[2]);
                MMA_F16(Sv[2 * ng + 1], qf[ks], bh_[1], bh_[3]);
            }
        }

        float mt0 = -3.0e38f, mt1 = -3.0e38f;
        #pragma unroll
        for (int nb = 0; nb < 8; nb++) {
            float mk0 = maskf[nb * 8 + cpos], mk1 = maskf[nb * 8 + cpos + 1];
            Sv[nb][0] = Sv[nb][0] * 0.125f + mk0;
            Sv[nb][1] = Sv[nb][1] * 0.125f + mk1;
            Sv[nb][2] = Sv[nb][2] * 0.125f + mk0;
            Sv[nb][3] = Sv[nb][3] * 0.125f + mk1;
            mt0 = fmaxf(mt0, fmaxf(Sv[nb][0], Sv[nb][1]));
            mt1 = fmaxf(mt1, fmaxf(Sv[nb][2], Sv[nb][3]));
        }
        mt0 = fmaxf(mt0, __shfl_xor_sync(0xffffffffu, mt0, 1));
        mt0 = fmaxf(mt0, __shfl_xor_sync(0xffffffffu, mt0, 2));
        mt1 = fmaxf(mt1, __shfl_xor_sync(0xffffffffu, mt1, 1));
        mt1 = fmaxf(mt1, __shfl_xor_sync(0xffffffffu, mt1, 2));

        float mn0 = fmaxf(m0, mt0), mn1 = fmaxf(m1, mt1);
        float al0 = __expf(m0 - mn0), al1 = __expf(m1 - mn1);
        float su0 = 0.f, su1 = 0.f;
        #pragma unroll
        for (int nb = 0; nb < 8; nb++) {
            Sv[nb][0] = __expf(Sv[nb][0] - mn0);
            Sv[nb][1] = __expf(Sv[nb][1] - mn0);
            Sv[nb][2] = __expf(Sv[nb][2] - mn1);
            Sv[nb][3] = __expf(Sv[nb][3] - mn1);
            su0 += Sv[nb][0] + Sv[nb][1];
            su1 += Sv[nb][2] + Sv[nb][3];
        }
        su0 += __shfl_xor_sync(0xffffffffu, su0, 1);
        su0 += __shfl_xor_sync(0xffffffffu, su0, 2);
        su1 += __shfl_xor_sync(0xffffffffu, su1, 1);
        su1 += __shfl_xor_sync(0xffffffffu, su1, 2);

        l0 = l0 * al0 + su0;
        l1 = l1 * al1 + su1;
        m0 = mn0; m1 = mn1;
        #pragma unroll
        for (int nf = 0; nf < 8; nf++) {
            O[nf][0] *= al0; O[nf][1] *= al0;
            O[nf][2] *= al1; O[nf][3] *= al1;
        }

        #pragma unroll
        for (int j = 0; j < 4; j++) {
            uint32_t pa[4];
            pa[0] = hpk2(Sv[2*j][0],   Sv[2*j][1]);
            pa[1] = hpk2(Sv[2*j][2],   Sv[2*j][3]);
            pa[2] = hpk2(Sv[2*j+1][0], Sv[2*j+1][1]);
            pa[3] = hpk2(Sv[2*j+1][2], Sv[2*j+1][3]);
            #pragma unroll
            for (int ng = 0; ng < 4; ng++) {
                uint32_t bd = sV + (j * 16 + lrow) * 144 + (ng * 16 + khalf * 8) * 2;
                uint32_t v0, v1, v2, v3;
                LDM_X4_T(v0, v1, v2, v3, bd);
                MMA_F16(O[2 * ng],     pa, v0, v1);
                MMA_F16(O[2 * ng + 1], pa, v2, v3);
            }
        }
    }
    #undef FA_FILL

    float i0 = 1.f / l0, i1 = 1.f / l1;
    const int rgl = b * SS + q0 + wid * 16 + (lane >> 2);
    #pragma unroll
    for (int nf = 0; nf < 8; nf++) {
        int col = h * 64 + nf * 8 + cpos;
        size_t o0 = (size_t)rgl * HDD + col;
        size_t o1 = (size_t)(rgl + 8) * HDD + col;
        *(uint32_t*)(ch + o0) = hpk2(O[nf][0] * i0, O[nf][1] * i0);
        *(uint32_t*)(ch + o1) = hpk2(O[nf][2] * i1, O[nf][3] * i1);
    }
}

// ==================== embed + add_ln ====================
__global__ __launch_bounds__(256) void embed_kernel(
    const int* __restrict__ tok, const float* __restrict__ emb,
    float* __restrict__ x, __half* __restrict__ xh)
{
    int row = blockIdx.x;
    int s = row % SS;
    int t = tok[row];
    const float* e = emb + (size_t)t * DD;
    for (int d = threadIdx.x; d < DD; d += 256) {
        int i = d >> 1;
        float freq = expf(-((float)(2 * i) / (float)DD) * 9.210340371976184f);
        float a = (float)s * freq;
        float pe = (d & 1) ? cosf(a) : sinf(a);
        float v = e[d] + pe;
        size_t o = (size_t)row * DD + d;
        x[o] = v;
        xh[o] = __float2half_rn(v);
    }
}

__device__ __forceinline__ float block_sum(float v, float* sh) {
    __syncthreads();
    #pragma unroll
    for (int o = 16; o > 0; o >>= 1) v += __shfl_xor_sync(0xffffffffu, v, o);
    int w = threadIdx.x >> 5;
    if ((threadIdx.x & 31) == 0) sh[w] = v;
    __syncthreads();
    float t = (threadIdx.x < 8) ? sh[threadIdx.x] : 0.0f;
    #pragma unroll
    for (int o = 4; o > 0; o >>= 1) t += __shfl_xor_sync(0xffffffffu, t, o);
    if (threadIdx.x == 0) sh[0] = t;
    __syncthreads();
    return sh[0];
}

__global__ __launch_bounds__(256) void add_ln(
    const float* __restrict__ xin, const __half* __restrict__ delta,
    const float* __restrict__ g, const float* __restrict__ bta,
    float* __restrict__ out, __half* __restrict__ oh)
{
    size_t row = blockIdx.x;
    const float* xr = xin + row * DD;
    const __half* dr = delta + row * DD;
    int tid = threadIdx.x;
    __shared__ float red[8];

    float v[4];
    float s = 0.f;
    #pragma unroll
    for (int j = 0; j < 4; j++) {
        int c = tid + j * 256;
        v[j] = xr[c] + __half2float(dr[c]);
        s += v[j];
    }
    s = block_sum(s, red);
    float mu = s * (1.0f / 1024.0f);
    float var = 0.f;
    #pragma unroll
    for (int j = 0; j < 4; j++) { float t = v[j] - mu; var += t * t; }
    var = block_sum(var, red) * (1.0f / 1024.0f);
    float inv = rsqrtf(var + 1e-5f);
    #pragma unroll
    for (int j = 0; j < 4; j++) {
        int c = tid + j * 256;
        float o = (v[j] - mu) * inv * g[c] + bta[c];
        size_t idx = row * DD + c;
        out[idx] = o;
        oh[idx] = __float2half_rn(o);
    }
}

// ==================== host orchestration ====================
extern "C" void kernel_launch(void* const* d_in, const int* in_sizes, int n_in,
                              void* d_out, int out_size)
{
    (void)in_sizes; (void)n_in; (void)out_size;
    const int*   tok  = (const int*)  d_in[0];
    const float* emb  = (const float*)d_in[1];
    const float* Wq   = (const float*)d_in[2];
    const float* bq   = (const float*)d_in[3];
    const float* Wk   = (const float*)d_in[4];
    const float* bk   = (const float*)d_in[5];
    const float* Wv   = (const float*)d_in[6];
    const float* bv   = (const float*)d_in[7];
    const float* Wo   = (const float*)d_in[8];
    const float* bo   = (const float*)d_in[9];
    const float* ln1g = (const float*)d_in[10];
    const float* ln1b = (const float*)d_in[11];
    const float* W1   = (const float*)d_in[12];
    const float* W2   = (const float*)d_in[13];
    const float* ln2g = (const float*)d_in[14];
    const float* ln2b = (const float*)d_in[15];
    float* out = (float*)d_out;

    float *x, *bqkv, *maskg;
    __half *xh, *qkv, *ch, *fh, *wh, *tmph;
    cudaGetSymbolAddress((void**)&x,     g_x);
    cudaGetSymbolAddress((void**)&maskg, g_maskf);
    cudaGetSymbolAddress((void**)&tmph,  g_tmph);
    cudaGetSymbolAddress((void**)&xh,    g_xh);
    cudaGetSymbolAddress((void**)&qkv,   g_qkv);
    cudaGetSymbolAddress((void**)&ch,    g_ch);
    cudaGetSymbolAddress((void**)&fh,    g_fh);
    cudaGetSymbolAddress((void**)&wh,    g_wh);
    cudaGetSymbolAddress((void**)&bqkv,  g_bqkv);

    const int GSM128 = 4 * (128 * 80 + ARR_B);   // 81920
    const int GSM64  = 4 * (64 * 80 + ARR_B);    // 61440

    static int attr_done = 0;
    if (!attr_done) {
        cudaFuncSetAttribute(gemm_mma<128>, cudaFuncAttributeMaxDynamicSharedMemorySize, GSM128);
        cudaFuncSetAttribute(gemm_mma<64>,  cudaFuncAttributeMaxDynamicSharedMemorySize, GSM64);
        cudaFuncSetAttribute(flash_attn, cudaFuncAttributeMaxDynamicSharedMemorySize, FA_SMEM);
        attr_done = 1;
    }

    // prep ordered so launch #6 is gemm_mma<128> (ncu -s 5 -c 1 target)
    mask_kernel<<<MR / 256, 256>>>(tok, maskg);                                  // 1
    biascat_kernel<<<LL * NQKV / 256, 256>>>(bq, bk, bv, bqkv);                  // 2
    embed_kernel<<<MR, 256>>>(tok, emb, x, xh);                                  // 3
    tsplit_qkv<<<dim3(HDD/64, DD/64, LL*3), 256>>>(Wq, Wk, Wv, wh + WQKV_OFF);   // 4
    tsplit_b<<<dim3(DD/64, HDD/64, LL), 256>>>(Wo, wh + WOT_OFF, HDD, DD);       // 5

    dim3 gQKV(NQKV/128, MR/128);
    dim3 gWo(DD/128, MR/64);
    dim3 gF1(FF/128, MR/128);
    dim3 gF2(DD/128, MR/64);
    dim3 gFA(SS/128, BB*HH);

    for (int l = 0; l < LL; l++) {
        const __half* wqkv = wh + WQKV_OFF + (size_t)l * 3 * SZ_P;
        const __half* woh  = wh + WOT_OFF + (size_t)l * SZ_P;
        const __half* w1h  = wh + W1T_OFF + (size_t)l * SZ_F;
        const __half* w2h  = wh + W2T_OFF + (size_t)l * SZ_F;

        gemm_mma<128><<<gQKV, 256, GSM128>>>(xh, wqkv, bqkv + (size_t)l*NQKV,
                                             qkv, DD, NQKV, 0);                  // 6 on l==0

        if (l == 0) {
            tsplit_b<<<dim3(FF/64, DD/64, LL), 256>>>(W1, wh + W1T_OFF, DD, FF);
            tsplit_b<<<dim3(DD/64, FF/64, LL), 256>>>(W2, wh + W2T_OFF, FF, DD);
        }

        flash_attn<<<gFA, 256, FA_SMEM>>>(qkv, maskg, ch);

        gemm_mma<64><<<gWo, 256, GSM64>>>(ch, woh, bo + (size_t)l*DD,
                                          tmph, HDD, DD, 0);
        add_ln<<<MR, 256>>>(x, tmph, ln1g + (size_t)l*DD, ln1b + (size_t)l*DD, x, xh);

        gemm_mma<128><<<gF1, 256, GSM128>>>(xh, w1h, (const float*)nullptr,
                                            fh, DD, FF, 1);
        gemm_mma<64><<<gF2, 256, GSM64>>>(fh, w2h, (const float*)nullptr,
                                          tmph, FF, DD, 0);

        float* dst = (l == LL - 1) ? out : x;
        add_ln<<<MR, 256>>>(x, tmph, ln2g + (size_t)l*DD, ln2b + (size_t)l*DD, dst, xh);
    }
}

// round 10
// speedup vs baseline: 6.9355x; 1.0023x over previous
#include <cuda_runtime.h>
#include <cuda_fp16.h>
#include <math.h>
#include <stdint.h>

#define BB   2
#define SS   1024
#define DD   1024
#define HH   16
#define HDD  1024
#define FF   4096
#define LL   4
#define MR   (BB*SS)
#define NQKV 3072

// -------------------- scratch --------------------
__device__ float g_x  [MR * DD];
__device__ float g_maskf[MR];
__device__ __half g_tmph[MR * DD];
__device__ __half g_xh[MR * DD];
__device__ __half g_qkv[(size_t)MR * NQKV];
__device__ __half g_ch[MR * HDD];
__device__ __half g_fh[(size_t)MR * FF];
__device__ float g_bqkv[LL * NQKV];

#define SZ_P ((size_t)HDD * DD)
#define SZ_F ((size_t)DD * FF)
#define WQKV_OFF ((size_t)0)
#define WOT_OFF  ((size_t)LL * 3 * SZ_P)
#define W1T_OFF  (WOT_OFF + (size_t)LL * SZ_P)
#define W2T_OFF  (W1T_OFF + (size_t)LL * SZ_F)
#define WT_TOTAL (W2T_OFF + (size_t)LL * SZ_F)
__device__ __half g_wh[WT_TOTAL];

// ==================== helpers ====================
__device__ __forceinline__ uint32_t smem_to_u32(const void* p) {
    uint32_t a;
    asm("{ .reg .u64 t; cvta.to.shared.u64 t, %1; cvt.u32.u64 %0, t; }" : "=r"(a) : "l"(p));
    return a;
}
#define CP_ASYNC16(dst, src) \
    asm volatile("cp.async.cg.shared.global [%0], [%1], 16;" \
        :: "r"((uint32_t)(dst)), "l"(__cvta_generic_to_global(src)) : "memory")
#define CP_COMMIT() asm volatile("cp.async.commit_group;" ::: "memory")
#define CP_WAITG(n) asm volatile("cp.async.wait_group %0;" :: "n"(n) : "memory")
#define LDM_X4(r0, r1, r2, r3, addr) \
    asm volatile("ldmatrix.sync.aligned.m8n8.x4.shared.b16 {%0,%1,%2,%3}, [%4];" \
        : "=r"(r0), "=r"(r1), "=r"(r2), "=r"(r3) : "r"(addr))
#define LDM_X4_T(r0, r1, r2, r3, addr) \
    asm volatile("ldmatrix.sync.aligned.m8n8.x4.trans.shared.b16 {%0,%1,%2,%3}, [%4];" \
        : "=r"(r0), "=r"(r1), "=r"(r2), "=r"(r3) : "r"(addr))
#define MMA_F16(acc, a, b0, b1) \
    asm volatile("mma.sync.aligned.m16n8k16.row.col.f32.f16.f16.f32 " \
        "{%0,%1,%2,%3},{%4,%5,%6,%7},{%8,%9},{%0,%1,%2,%3};" \
        : "+f"((acc)[0]), "+f"((acc)[1]), "+f"((acc)[2]), "+f"((acc)[3]) \
        : "r"((a)[0]), "r"((a)[1]), "r"((a)[2]), "r"((a)[3]), "r"(b0), "r"(b1))

__device__ __forceinline__ uint32_t hpk2(float a, float b) {
    __half2 t = __floats2half2_rn(a, b);
    return *reinterpret_cast<uint32_t*>(&t);
}
__device__ __forceinline__ float gelu_f(float v) {
    float x = v * 0.70710678118654752f;
    float ax = fabsf(x);
    float t = __fdividef(1.0f, fmaf(0.3275911f, ax, 1.0f));
    float p = t * fmaf(t, fmaf(t, fmaf(t, fmaf(t, 1.061405429f, -1.453152027f),
                               1.421413741f), -0.284496736f), 0.254829592f);
    float erfv = 1.0f - p * __expf(-ax * ax);
    erfv = copysignf(erfv, x);
    return 0.5f * v * (1.0f + erfv);
}

// ==================== batched weight transpose ====================
__device__ __forceinline__ void tsplit_body(
    const float* __restrict__ W, __half* __restrict__ th, int K, int N)
{
    __shared__ float ts[64][65];
    const int n0 = blockIdx.x * 64, k0 = blockIdx.y * 64;
    const int tid = threadIdx.x;
    #pragma unroll
    for (int i = 0; i < 4; i++) {
        int e = tid + i * 256;
        int r = e >> 4, c4 = (e & 15) * 4;
        float4 v = *(const float4*)&W[(size_t)(k0 + r) * N + n0 + c4];
        ts[r][c4]     = v.x; ts[r][c4 + 1] = v.y;
        ts[r][c4 + 2] = v.z; ts[r][c4 + 3] = v.w;
    }
    __syncthreads();
    const int w = tid >> 5, lane = tid & 31;
    #pragma unroll
    for (int rr = 0; rr < 8; rr++) {
        int n = w * 8 + rr;
        float a = ts[lane * 2][n], b = ts[lane * 2 + 1][n];
        size_t o = (size_t)(n0 + n) * K + k0 + lane * 2;
        *(uint32_t*)&th[o] = hpk2(a, b);
    }
}

__global__ __launch_bounds__(256) void tsplit_qkv(
    const float* __restrict__ Wq, const float* __restrict__ Wk,
    const float* __restrict__ Wv, __half* __restrict__ th)
{
    int z = blockIdx.z;
    int l = z / 3, j = z - l * 3;
    const float* W = ((j == 0) ? Wq : (j == 1) ? Wk : Wv) + (size_t)l * SZ_P;
    __half* dst = th + ((size_t)l * 3 + j) * SZ_P;
    tsplit_body(W, dst, DD, HDD);
}

__global__ __launch_bounds__(256) void tsplit_b(
    const float* __restrict__ W, __half* __restrict__ th, int K, int N)
{
    size_t off = (size_t)blockIdx.z * K * N;
    tsplit_body(W + off, th + off, K, N);
}

__global__ void biascat_kernel(const float* __restrict__ bq, const float* __restrict__ bk,
                               const float* __restrict__ bv, float* __restrict__ o)
{
    int i = blockIdx.x * 256 + threadIdx.x;
    int l = i / NQKV, r = i % NQKV;
    int seg = r >> 10, n = r & 1023;
    const float* s = (seg == 0) ? bq : (seg == 1) ? bk : bv;
    o[i] = s[l * 1024 + n];
}

__global__ void mask_kernel(const int* __restrict__ tok, float* __restrict__ m)
{
    int i = blockIdx.x * 256 + threadIdx.x;
    m[i] = (tok[i] == 0) ? -1e9f : 0.f;
}

// ==================== fp16 HMMA GEMM, single-barrier 4-slot pipeline ====================
#define KC 32
#define ARR_B 10240

template<int MT>
__global__ __launch_bounds__(256, 2) void gemm_mma(
    const __half* __restrict__ A, const __half* __restrict__ B,
    const float* __restrict__ bias, __half* __restrict__ Ch,
    int K, int N, int act)
{
    constexpr uint32_t ARR_A = (uint32_t)MT * 80;
    constexpr uint32_t STGB  = ARR_A + ARR_B;
    constexpr int AITER = MT / 64;
    constexpr int NFRAG = (MT == 128) ? 8 : 4;
    constexpr int NB    = NFRAG / 2;
    constexpr int WNW   = (MT == 128) ? 64 : 32;

    extern __shared__ __align__(128) char smem_raw[];
    const uint32_t sbase = smem_to_u32(smem_raw);

    const int tid  = threadIdx.x;
    const int lane = tid & 31;
    const int wid  = tid >> 5;
    const int wm   = (MT == 128) ? (wid & 3) : (wid & 1);
    const int wn   = (MT == 128) ? (wid >> 2) : (wid >> 1);
    const int m0 = blockIdx.y * MT, n0 = blockIdx.x * 128;

    float acc[2][NFRAG][4];
    #pragma unroll
    for (int i = 0; i < 2; i++)
        #pragma unroll
        for (int j = 0; j < NFRAG; j++)
            #pragma unroll
            for (int q2 = 0; q2 < 4; q2++) acc[i][j][q2] = 0.f;

    const int nc = K >> 5;

    #define FILL_STAGE(stg, kk) do { \
        const uint32_t so_ = sbase + (uint32_t)(stg) * STGB; \
        _Pragma("unroll") \
        for (int i_ = 0; i_ < AITER + 2; i_++) { \
            const int isA_ = (i_ < AITER); \
            int rem_ = (isA_ ? i_ : (i_ - AITER)) * 256 + tid; \
            int row_ = rem_ >> 2, seg_ = rem_ & 3; \
            const __half* p_ = isA_ ? A : B; \
            int rb_ = isA_ ? m0 : n0; \
            uint32_t dst_ = so_ + (isA_ ? 0u : ARR_A) + row_ * 80 + seg_ * 16; \
            CP_ASYNC16(dst_, p_ + (size_t)(rb_ + row_) * K + (kk) + seg_ * 8); \
        } \
        CP_COMMIT(); \
    } while (0)

    FILL_STAGE(0, 0);
    FILL_STAGE(1, KC);

    const uint32_t lrow  = lane & 15;
    const uint32_t khalf = lane >> 4;
    const uint32_t a_row_off = (wm * 32 + lrow) * 80;
    const uint32_t b_row_off = (wn * WNW + lrow) * 80;

    for (int c = 0; c < nc; c++) {
        if (c + 2 < nc) { FILL_STAGE((c + 2) & 3, (c + 2) * KC); CP_WAITG(2); }
        else if (c + 1 < nc) CP_WAITG(1);
        else CP_WAITG(0);
        __syncthreads();

        const uint32_t so = sbase + (uint32_t)(c & 3) * STGB;
        const uint32_t sA = so, sB = so + ARR_A;

        #pragma unroll
        for (int ks = 0; ks < 2; ks++) {
            const uint32_t kofs = (ks * 16 + khalf * 8) * 2;
            uint32_t af[2][4];
            #pragma unroll
            for (int mb = 0; mb < 2; mb++) {
                uint32_t ad = a_row_off + mb * 16 * 80 + kofs;
                LDM_X4(af[mb][0], af[mb][1], af[mb][2], af[mb][3], sA + ad);
            }
            #pragma unroll
            for (int nb = 0; nb < NB; nb++) {
                uint32_t bd = b_row_off + nb * 16 * 80 + kofs;
                uint32_t bf_[4];
                LDM_X4(bf_[0], bf_[1], bf_[2], bf_[3], sB + bd);
                #pragma unroll
                for (int mb = 0; mb < 2; mb++) {
                    MMA_F16(acc[mb][nb * 2],     af[mb], bf_[0], bf_[2]);
                    MMA_F16(acc[mb][nb * 2 + 1], af[mb], bf_[1], bf_[3]);
                }
            }
        }
    }
    #undef FILL_STAGE

    const int mrow = m0 + wm * 32 + (lane >> 2);
    const int ncol0 = n0 + wn * WNW + (lane & 3) * 2;
    #pragma unroll
    for (int mb = 0; mb < 2; mb++) {
        #pragma unroll
        for (int nf = 0; nf < NFRAG; nf++) {
            int n = ncol0 + nf * 8;
            float b0v = bias ? bias[n]     : 0.f;
            float b1v = bias ? bias[n + 1] : 0.f;
            float v0 = acc[mb][nf][0] + b0v;
            float v1 = acc[mb][nf][1] + b1v;
            float v2 = acc[mb][nf][2] + b0v;
            float v3 = acc[mb][nf][3] + b1v;
            if (act) { v0 = gelu_f(v0); v1 = gelu_f(v1); v2 = gelu_f(v2); v3 = gelu_f(v3); }
            int m = mrow + mb * 16;
            *(uint32_t*)(Ch + (size_t)m * N + n)       = hpk2(v0, v1);
            *(uint32_t*)(Ch + (size_t)(m + 8) * N + n) = hpk2(v2, v3);
        }
    }
}

// ==================== flash attention (fp16, 64-key tiles, 3-stage, 1 barrier/kt) ====================
#define FA_Q     0
#define FA_STG0  18432
#define FA_K     0
#define FA_V     9216
#define FA_MSK   18432
#define FA_STGSZ 18688
#define FA_SMEM  (18432 + 3 * 18688)   // 74496

__global__ __launch_bounds__(256, 2) void flash_attn(
    const __half* __restrict__ qkv, const float* __restrict__ maskg,
    __half* __restrict__ ch)
{
    extern __shared__ __align__(128) char smem_raw[];
    const uint32_t base = smem_to_u32(smem_raw);
    const uint32_t sQ = base + FA_Q;

    const int tid = threadIdx.x, lane = tid & 31, wid = tid >> 5;
    const int q0 = blockIdx.x * 128;
    const int z = blockIdx.y, b = z >> 4, h = z & 15;
    const uint32_t lrow = lane & 15, khalf = lane >> 4;
    const int cpos = (lane & 3) * 2;
    const int colQ = h * 64, colK = 1024 + h * 64, colV = 2048 + h * 64;

    #pragma unroll
    for (int i = 0; i < 2; i++) {
        int idx = tid + i * 256;
        int row = idx >> 2, seg2 = (idx & 3) * 2;
        size_t src = (size_t)(b * SS + q0 + row) * NQKV + colQ + seg2 * 8;
        CP_ASYNC16(sQ + row * 144 + seg2 * 16, qkv + src);
        CP_ASYNC16(sQ + row * 144 + seg2 * 16 + 16, qkv + src + 8);
    }
    CP_COMMIT();

    #define FA_FILL(kt_) do { \
        const int stg_ = (kt_) % 3; \
        const uint32_t sb_ = base + FA_STG0 + stg_ * FA_STGSZ; \
        const int k0_ = (kt_) * 64; \
        { int row_ = tid >> 2, s2_ = tid & 3; \
          size_t srck_ = (size_t)(b * SS + k0_ + row_) * NQKV + colK + s2_ * 16; \
          uint32_t dstk_ = sb_ + FA_K + row_ * 144 + s2_ * 32; \
          CP_ASYNC16(dstk_, qkv + srck_); \
          CP_ASYNC16(dstk_ + 16, qkv + srck_ + 8); \
          size_t srcv_ = (size_t)(b * SS + k0_ + row_) * NQKV + colV + s2_ * 16; \
          uint32_t dstv_ = sb_ + FA_V + row_ * 144 + s2_ * 32; \
          CP_ASYNC16(dstv_, qkv + srcv_); \
          CP_ASYNC16(dstv_ + 16, qkv + srcv_ + 8); } \
        if (tid < 16) \
            CP_ASYNC16(sb_ + FA_MSK + tid * 16, maskg + b * SS + k0_ + tid * 4); \
        CP_COMMIT(); \
    } while (0)

    FA_FILL(0);
    FA_FILL(1);

    float m0 = -3.0e38f, m1 = -3.0e38f, l0 = 0.f, l1 = 0.f;
    float O[8][4];
    #pragma unroll
    for (int i = 0; i < 8; i++)
        #pragma unroll
        for (int j = 0; j < 4; j++) O[i][j] = 0.f;

    uint32_t qf[4][4];

    for (int kt = 0; kt < 16; kt++) {
        if (kt + 2 < 16) { FA_FILL(kt + 2); CP_WAITG(2); }
        else if (kt + 1 < 16) CP_WAITG(1);
        else CP_WAITG(0);
        __syncthreads();

        const uint32_t sb = base + FA_STG0 + (uint32_t)(kt % 3) * FA_STGSZ;
        const uint32_t sK = sb + FA_K, sV = sb + FA_V;
        const float* maskf = (const float*)(smem_raw + FA_STG0 + (kt % 3) * FA_STGSZ + FA_MSK);

        if (kt == 0) {
            #pragma unroll
            for (int ks = 0; ks < 4; ks++) {
                uint32_t ad = (wid * 16 + lrow) * 144 + (ks * 16 + khalf * 8) * 2;
                LDM_X4(qf[ks][0], qf[ks][1], qf[ks][2], qf[ks][3], sQ + ad);
            }
        }

        float Sv[8][4];
        #pragma unroll
        for (int i = 0; i < 8; i++)
            #pragma unroll
            for (int j = 0; j < 4; j++) Sv[i][j] = 0.f;

        #pragma unroll
        for (int ks = 0; ks < 4; ks++) {
            #pragma unroll
            for (int ng = 0; ng < 4; ng++) {
                uint32_t bd = (ng * 16 + lrow) * 144 + (ks * 16 + khalf * 8) * 2;
                uint32_t bh_[4];
                LDM_X4(bh_[0], bh_[1], bh_[2], bh_[3], sK + bd);
                MMA_F16(Sv[2 * ng],     qf[ks], bh_[0], bh_[2]);
                MMA_F16(Sv[2 * ng + 1], qf[ks], bh_[1], bh_[3]);
            }
        }

        float mt0 = -3.0e38f, mt1 = -3.0e38f;
        #pragma unroll
        for (int nb = 0; nb < 8; nb++) {
            float mk0 = maskf[nb * 8 + cpos], mk1 = maskf[nb * 8 + cpos + 1];
            Sv[nb][0] = Sv[nb][0] * 0.125f + mk0;
            Sv[nb][1] = Sv[nb][1] * 0.125f + mk1;
            Sv[nb][2] = Sv[nb][2] * 0.125f + mk0;
            Sv[nb][3] = Sv[nb][3] * 0.125f + mk1;
            mt0 = fmaxf(mt0, fmaxf(Sv[nb][0], Sv[nb][1]));
            mt1 = fmaxf(mt1, fmaxf(Sv[nb][2], Sv[nb][3]));
        }
        mt0 = fmaxf(mt0, __shfl_xor_sync(0xffffffffu, mt0, 1));
        mt0 = fmaxf(mt0, __shfl_xor_sync(0xffffffffu, mt0, 2));
        mt1 = fmaxf(mt1, __shfl_xor_sync(0xffffffffu, mt1, 1));
        mt1 = fmaxf(mt1, __shfl_xor_sync(0xffffffffu, mt1, 2));

        float mn0 = fmaxf(m0, mt0), mn1 = fmaxf(m1, mt1);
        float al0 = __expf(m0 - mn0), al1 = __expf(m1 - mn1);
        float su0 = 0.f, su1 = 0.f;
        #pragma unroll
        for (int nb = 0; nb < 8; nb++) {
            Sv[nb][0] = __expf(Sv[nb][0] - mn0);
            Sv[nb][1] = __expf(Sv[nb][1] - mn0);
            Sv[nb][2] = __expf(Sv[nb][2] - mn1);
            Sv[nb][3] = __expf(Sv[nb][3] - mn1);
            su0 += Sv[nb][0] + Sv[nb][1];
            su1 += Sv[nb][2] + Sv[nb][3];
        }
        su0 += __shfl_xor_sync(0xffffffffu, su0, 1);
        su0 += __shfl_xor_sync(0xffffffffu, su0, 2);
        su1 += __shfl_xor_sync(0xffffffffu, su1, 1);
        su1 += __shfl_xor_sync(0xffffffffu, su1, 2);

        l0 = l0 * al0 + su0;
        l1 = l1 * al1 + su1;
        m0 = mn0; m1 = mn1;
        #pragma unroll
        for (int nf = 0; nf < 8; nf++) {
            O[nf][0] *= al0; O[nf][1] *= al0;
            O[nf][2] *= al1; O[nf][3] *= al1;
        }

        #pragma unroll
        for (int j = 0; j < 4; j++) {
            uint32_t pa[4];
            pa[0] = hpk2(Sv[2*j][0],   Sv[2*j][1]);
            pa[1] = hpk2(Sv[2*j][2],   Sv[2*j][3]);
            pa[2] = hpk2(Sv[2*j+1][0], Sv[2*j+1][1]);
            pa[3] = hpk2(Sv[2*j+1][2], Sv[2*j+1][3]);
            #pragma unroll
            for (int ng = 0; ng < 4; ng++) {
                uint32_t bd = sV + (j * 16 + lrow) * 144 + (ng * 16 + khalf * 8) * 2;
                uint32_t v0, v1, v2, v3;
                LDM_X4_T(v0, v1, v2, v3, bd);
                MMA_F16(O[2 * ng],     pa, v0, v1);
                MMA_F16(O[2 * ng + 1], pa, v2, v3);
            }
        }
    }
    #undef FA_FILL

    float i0 = 1.f / l0, i1 = 1.f / l1;
    const int rgl = b * SS + q0 + wid * 16 + (lane >> 2);
    #pragma unroll
    for (int nf = 0; nf < 8; nf++) {
        int col = h * 64 + nf * 8 + cpos;
        size_t o0 = (size_t)rgl * HDD + col;
        size_t o1 = (size_t)(rgl + 8) * HDD + col;
        *(uint32_t*)(ch + o0) = hpk2(O[nf][0] * i0, O[nf][1] * i0);
        *(uint32_t*)(ch + o1) = hpk2(O[nf][2] * i1, O[nf][3] * i1);
    }
}

// ==================== embed + add_ln ====================
__global__ __launch_bounds__(256) void embed_kernel(
    const int* __restrict__ tok, const float* __restrict__ emb,
    float* __restrict__ x, __half* __restrict__ xh)
{
    int row = blockIdx.x;
    int s = row % SS;
    int t = tok[row];
    const float* e = emb + (size_t)t * DD;
    for (int d = threadIdx.x; d < DD; d += 256) {
        int i = d >> 1;
        float freq = expf(-((float)(2 * i) / (float)DD) * 9.210340371976184f);
        float a = (float)s * freq;
        float pe = (d & 1) ? cosf(a) : sinf(a);
        float v = e[d] + pe;
        size_t o = (size_t)row * DD + d;
        x[o] = v;
        xh[o] = __float2half_rn(v);
    }
}

__device__ __forceinline__ float block_sum(float v, float* sh) {
    __syncthreads();
    #pragma unroll
    for (int o = 16; o > 0; o >>= 1) v += __shfl_xor_sync(0xffffffffu, v, o);
    int w = threadIdx.x >> 5;
    if ((threadIdx.x & 31) == 0) sh[w] = v;
    __syncthreads();
    float t = (threadIdx.x < 8) ? sh[threadIdx.x] : 0.0f;
    #pragma unroll
    for (int o = 4; o > 0; o >>= 1) t += __shfl_xor_sync(0xffffffffu, t, o);
    if (threadIdx.x == 0) sh[0] = t;
    __syncthreads();
    return sh[0];
}

__global__ __launch_bounds__(256) void add_ln(
    const float* __restrict__ xin, const __half* __restrict__ delta,
    const float* __restrict__ g, const float* __restrict__ bta,
    float* __restrict__ out, __half* __restrict__ oh)
{
    size_t row = blockIdx.x;
    const float* xr = xin + row * DD;
    const __half* dr = delta + row * DD;
    int tid = threadIdx.x;
    __shared__ float red[8];

    float v[4];
    float s = 0.f;
    #pragma unroll
    for (int j = 0; j < 4; j++) {
        int c = tid + j * 256;
        v[j] = xr[c] + __half2float(dr[c]);
        s += v[j];
    }
    s = block_sum(s, red);
    float mu = s * (1.0f / 1024.0f);
    float var = 0.f;
    #pragma unroll
    for (int j = 0; j < 4; j++) { float t = v[j] - mu; var += t * t; }
    var = block_sum(var, red) * (1.0f / 1024.0f);
    float inv = rsqrtf(var + 1e-5f);
    #pragma unroll
    for (int j = 0; j < 4; j++) {
        int c = tid + j * 256;
        float o = (v[j] - mu) * inv * g[c] + bta[c];
        size_t idx = row * DD + c;
        out[idx] = o;
        oh[idx] = __float2half_rn(o);
    }
}

// ==================== host orchestration ====================
extern "C" void kernel_launch(void* const* d_in, const int* in_sizes, int n_in,
                              void* d_out, int out_size)
{
    (void)in_sizes; (void)n_in; (void)out_size;
    const int*   tok  = (const int*)  d_in[0];
    const float* emb  = (const float*)d_in[1];
    const float* Wq   = (const float*)d_in[2];
    const float* bq   = (const float*)d_in[3];
    const float* Wk   = (const float*)d_in[4];
    const float* bk   = (const float*)d_in[5];
    const float* Wv   = (const float*)d_in[6];
    const float* bv   = (const float*)d_in[7];
    const float* Wo   = (const float*)d_in[8];
    const float* bo   = (const float*)d_in[9];
    const float* ln1g = (const float*)d_in[10];
    const float* ln1b = (const float*)d_in[11];
    const float* W1   = (const float*)d_in[12];
    const float* W2   = (const float*)d_in[13];
    const float* ln2g = (const float*)d_in[14];
    const float* ln2b = (const float*)d_in[15];
    float* out = (float*)d_out;

    float *x, *bqkv, *maskg;
    __half *xh, *qkv, *ch, *fh, *wh, *tmph;
    cudaGetSymbolAddress((void**)&x,     g_x);
    cudaGetSymbolAddress((void**)&maskg, g_maskf);
    cudaGetSymbolAddress((void**)&tmph,  g_tmph);
    cudaGetSymbolAddress((void**)&xh,    g_xh);
    cudaGetSymbolAddress((void**)&qkv,   g_qkv);
    cudaGetSymbolAddress((void**)&ch,    g_ch);
    cudaGetSymbolAddress((void**)&fh,    g_fh);
    cudaGetSymbolAddress((void**)&wh,    g_wh);
    cudaGetSymbolAddress((void**)&bqkv,  g_bqkv);

    const int GSM128 = 4 * (128 * 80 + ARR_B);   // 81920
    const int GSM64  = 4 * (64 * 80 + ARR_B);    // 61440

    static int attr_done = 0;
    static cudaStream_t s2;
    static cudaEvent_t evFork, evJoin;
    if (!attr_done) {
        cudaFuncSetAttribute(gemm_mma<128>, cudaFuncAttributeMaxDynamicSharedMemorySize, GSM128);
        cudaFuncSetAttribute(gemm_mma<64>,  cudaFuncAttributeMaxDynamicSharedMemorySize, GSM64);
        cudaFuncSetAttribute(flash_attn, cudaFuncAttributeMaxDynamicSharedMemorySize, FA_SMEM);
        cudaStreamCreateWithFlags(&s2, cudaStreamNonBlocking);
        cudaEventCreateWithFlags(&evFork, cudaEventDisableTiming);
        cudaEventCreateWithFlags(&evJoin, cudaEventDisableTiming);
        attr_done = 1;
    }

    // prep on main stream (needed before first QKV gemm)
    mask_kernel<<<MR / 256, 256>>>(tok, maskg);
    biascat_kernel<<<LL * NQKV / 256, 256>>>(bq, bk, bv, bqkv);
    embed_kernel<<<MR, 256>>>(tok, emb, x, xh);
    tsplit_qkv<<<dim3(HDD/64, DD/64, LL*3), 256>>>(Wq, Wk, Wv, wh + WQKV_OFF);

    // fork: Wo/W1/W2 transposes overlap with layer-0 QKV gemm + flash
    cudaEventRecord(evFork, 0);
    cudaStreamWaitEvent(s2, evFork, 0);
    tsplit_b<<<dim3(DD/64, HDD/64, LL), 256, 0, s2>>>(Wo, wh + WOT_OFF, HDD, DD);
    tsplit_b<<<dim3(FF/64, DD/64, LL), 256, 0, s2>>>(W1, wh + W1T_OFF, DD, FF);
    tsplit_b<<<dim3(DD/64, FF/64, LL), 256, 0, s2>>>(W2, wh + W2T_OFF, FF, DD);
    cudaEventRecord(evJoin, s2);

    dim3 gQKV(NQKV/128, MR/64);    // 24 x 32 (MT=64 -> 768 CTAs, better wave fill)
    dim3 gWo(DD/128, MR/64);
    dim3 gF1(FF/128, MR/128);
    dim3 gF2(DD/128, MR/64);
    dim3 gFA(SS/128, BB*HH);

    for (int l = 0; l < LL; l++) {
        const __half* wqkv = wh + WQKV_OFF + (size_t)l * 3 * SZ_P;
        const __half* woh  = wh + WOT_OFF + (size_t)l * SZ_P;
        const __half* w1h  = wh + W1T_OFF + (size_t)l * SZ_F;
        const __half* w2h  = wh + W2T_OFF + (size_t)l * SZ_F;

        gemm_mma<64><<<gQKV, 256, GSM64>>>(xh, wqkv, bqkv + (size_t)l*NQKV,
                                           qkv, DD, NQKV, 0);

        flash_attn<<<gFA, 256, FA_SMEM>>>(qkv, maskg, ch);

        if (l == 0) cudaStreamWaitEvent(0, evJoin, 0);   // join before first Wo use

        gemm_mma<64><<<gWo, 256, GSM64>>>(ch, woh, bo + (size_t)l*DD,
                                          tmph, HDD, DD, 0);
        add_ln<<<MR, 256>>>(x, tmph, ln1g + (size_t)l*DD, ln1b + (size_t)l*DD, x, xh);

        gemm_mma<128><<<gF1, 256, GSM128>>>(xh, w1h, (const float*)nullptr,
                                            fh, DD, FF, 1);
        gemm_mma<64><<<gF2, 256, GSM64>>>(fh, w2h, (const float*)nullptr,
                                          tmph, FF, DD, 0);

        float* dst = (l == LL - 1) ? out : x;
        add_ln<<<MR, 256>>>(x, tmph, ln2g + (size_t)l*DD, ln2b + (size_t)l*DD, dst, xh);
    }
}

// round 11
// speedup vs baseline: 6.9397x; 1.0006x over previous
#include <cuda_runtime.h>
#include <cuda_fp16.h>
#include <math.h>
#include <stdint.h>

#define BB   2
#define SS   1024
#define DD   1024
#define HH   16
#define HDD  1024
#define FF   4096
#define LL   4
#define MR   (BB*SS)
#define NQKV 3072

// -------------------- scratch --------------------
__device__ float g_x  [MR * DD];
__device__ float g_tmp[MR * DD];
__device__ float g_maskf[MR];
__device__ __half g_xh[MR * DD];
__device__ __half g_qkv[(size_t)MR * NQKV];
__device__ __half g_ch[MR * HDD];
__device__ __half g_fh[(size_t)MR * FF];
__device__ float g_bqkv[LL * NQKV];

#define SZ_P ((size_t)HDD * DD)
#define SZ_F ((size_t)DD * FF)
#define WQKV_OFF ((size_t)0)
#define WOT_OFF  ((size_t)LL * 3 * SZ_P)
#define W1T_OFF  (WOT_OFF + (size_t)LL * SZ_P)
#define W2T_OFF  (W1T_OFF + (size_t)LL * SZ_F)
#define WT_TOTAL (W2T_OFF + (size_t)LL * SZ_F)
__device__ __half g_wh[WT_TOTAL];

// ==================== helpers ====================
__device__ __forceinline__ uint32_t smem_to_u32(const void* p) {
    uint32_t a;
    asm("{ .reg .u64 t; cvta.to.shared.u64 t, %1; cvt.u32.u64 %0, t; }" : "=r"(a) : "l"(p));
    return a;
}
#define CP_ASYNC16(dst, src) \
    asm volatile("cp.async.cg.shared.global [%0], [%1], 16;" \
        :: "r"((uint32_t)(dst)), "l"(__cvta_generic_to_global(src)) : "memory")
#define CP_COMMIT() asm volatile("cp.async.commit_group;" ::: "memory")
#define CP_WAITG(n) asm volatile("cp.async.wait_group %0;" :: "n"(n) : "memory")
#define LDM_X4(r0, r1, r2, r3, addr) \
    asm volatile("ldmatrix.sync.aligned.m8n8.x4.shared.b16 {%0,%1,%2,%3}, [%4];" \
        : "=r"(r0), "=r"(r1), "=r"(r2), "=r"(r3) : "r"(addr))
#define LDM_X4_T(r0, r1, r2, r3, addr) \
    asm volatile("ldmatrix.sync.aligned.m8n8.x4.trans.shared.b16 {%0,%1,%2,%3}, [%4];" \
        : "=r"(r0), "=r"(r1), "=r"(r2), "=r"(r3) : "r"(addr))
#define MMA_F16(acc, a, b0, b1) \
    asm volatile("mma.sync.aligned.m16n8k16.row.col.f32.f16.f16.f32 " \
        "{%0,%1,%2,%3},{%4,%5,%6,%7},{%8,%9},{%0,%1,%2,%3};" \
        : "+f"((acc)[0]), "+f"((acc)[1]), "+f"((acc)[2]), "+f"((acc)[3]) \
        : "r"((a)[0]), "r"((a)[1]), "r"((a)[2]), "r"((a)[3]), "r"(b0), "r"(b1))

__device__ __forceinline__ uint32_t hpk2(float a, float b) {
    __half2 t = __floats2half2_rn(a, b);
    return *reinterpret_cast<uint32_t*>(&t);
}
__device__ __forceinline__ float gelu_f(float v) {
    float x = v * 0.70710678118654752f;
    float ax = fabsf(x);
    float t = __fdividef(1.0f, fmaf(0.3275911f, ax, 1.0f));
    float p = t * fmaf(t, fmaf(t, fmaf(t, fmaf(t, 1.061405429f, -1.453152027f),
                               1.421413741f), -0.284496736f), 0.254829592f);
    float erfv = 1.0f - p * __expf(-ax * ax);
    erfv = copysignf(erfv, x);
    return 0.5f * v * (1.0f + erfv);
}

// ==================== batched weight transpose ====================
__device__ __forceinline__ void tsplit_body(
    const float* __restrict__ W, __half* __restrict__ th, int K, int N)
{
    __shared__ float ts[64][65];
    const int n0 = blockIdx.x * 64, k0 = blockIdx.y * 64;
    const int tid = threadIdx.x;
    #pragma unroll
    for (int i = 0; i < 4; i++) {
        int e = tid + i * 256;
        int r = e >> 4, c4 = (e & 15) * 4;
        float4 v = *(const float4*)&W[(size_t)(k0 + r) * N + n0 + c4];
        ts[r][c4]     = v.x; ts[r][c4 + 1] = v.y;
        ts[r][c4 + 2] = v.z; ts[r][c4 + 3] = v.w;
    }
    __syncthreads();
    const int w = tid >> 5, lane = tid & 31;
    #pragma unroll
    for (int rr = 0; rr < 8; rr++) {
        int n = w * 8 + rr;
        float a = ts[lane * 2][n], b = ts[lane * 2 + 1][n];
        size_t o = (size_t)(n0 + n) * K + k0 + lane * 2;
        *(uint32_t*)&th[o] = hpk2(a, b);
    }
}

__global__ __launch_bounds__(256) void tsplit_qkv(
    const float* __restrict__ Wq, const float* __restrict__ Wk,
    const float* __restrict__ Wv, __half* __restrict__ th)
{
    int z = blockIdx.z;
    int l = z / 3, j = z - l * 3;
    const float* W = ((j == 0) ? Wq : (j == 1) ? Wk : Wv) + (size_t)l * SZ_P;
    __half* dst = th + ((size_t)l * 3 + j) * SZ_P;
    tsplit_body(W, dst, DD, HDD);
}

__global__ __launch_bounds__(256) void tsplit_b(
    const float* __restrict__ W, __half* __restrict__ th, int K, int N)
{
    size_t off = (size_t)blockIdx.z * K * N;
    tsplit_body(W + off, th + off, K, N);
}

__global__ void biascat_kernel(const float* __restrict__ bq, const float* __restrict__ bk,
                               const float* __restrict__ bv, float* __restrict__ o)
{
    int i = blockIdx.x * 256 + threadIdx.x;
    int l = i / NQKV, r = i % NQKV;
    int seg = r >> 10, n = r & 1023;
    const float* s = (seg == 0) ? bq : (seg == 1) ? bk : bv;
    o[i] = s[l * 1024 + n];
}

__global__ void mask_kernel(const int* __restrict__ tok, float* __restrict__ m)
{
    int i = blockIdx.x * 256 + threadIdx.x;
    m[i] = (tok[i] == 0) ? -1e9f : 0.f;
}

// ==================== fp16 HMMA GEMM, single-barrier 4-slot pipeline ====================
#define KC 32
#define ARR_B 10240

template<int MT>
__global__ __launch_bounds__(256, 2) void gemm_mma(
    const __half* __restrict__ A, const __half* __restrict__ B,
    const float* __restrict__ bias, float* __restrict__ C,
    __half* __restrict__ Ch, int K, int N, int act)
{
    constexpr uint32_t ARR_A = (uint32_t)MT * 80;
    constexpr uint32_t STGB  = ARR_A + ARR_B;
    constexpr int AITER = MT / 64;
    constexpr int NFRAG = (MT == 128) ? 8 : 4;
    constexpr int NB    = NFRAG / 2;
    constexpr int WNW   = (MT == 128) ? 64 : 32;

    extern __shared__ __align__(128) char smem_raw[];
    const uint32_t sbase = smem_to_u32(smem_raw);

    const int tid  = threadIdx.x;
    const int lane = tid & 31;
    const int wid  = tid >> 5;
    const int wm   = (MT == 128) ? (wid & 3) : (wid & 1);
    const int wn   = (MT == 128) ? (wid >> 2) : (wid >> 1);
    const int m0 = blockIdx.y * MT, n0 = blockIdx.x * 128;

    float acc[2][NFRAG][4];
    #pragma unroll
    for (int i = 0; i < 2; i++)
        #pragma unroll
        for (int j = 0; j < NFRAG; j++)
            #pragma unroll
            for (int q2 = 0; q2 < 4; q2++) acc[i][j][q2] = 0.f;

    const int nc = K >> 5;

    #define FILL_STAGE(stg, kk) do { \
        const uint32_t so_ = sbase + (uint32_t)(stg) * STGB; \
        _Pragma("unroll") \
        for (int i_ = 0; i_ < AITER + 2; i_++) { \
            const int isA_ = (i_ < AITER); \
            int rem_ = (isA_ ? i_ : (i_ - AITER)) * 256 + tid; \
            int row_ = rem_ >> 2, seg_ = rem_ & 3; \
            const __half* p_ = isA_ ? A : B; \
            int rb_ = isA_ ? m0 : n0; \
            uint32_t dst_ = so_ + (isA_ ? 0u : ARR_A) + row_ * 80 + seg_ * 16; \
            CP_ASYNC16(dst_, p_ + (size_t)(rb_ + row_) * K + (kk) + seg_ * 8); \
        } \
        CP_COMMIT(); \
    } while (0)

    FILL_STAGE(0, 0);
    FILL_STAGE(1, KC);

    const uint32_t lrow  = lane & 15;
    const uint32_t khalf = lane >> 4;
    const uint32_t a_row_off = (wm * 32 + lrow) * 80;
    const uint32_t b_row_off = (wn * WNW + lrow) * 80;

    for (int c = 0; c < nc; c++) {
        if (c + 2 < nc) { FILL_STAGE((c + 2) & 3, (c + 2) * KC); CP_WAITG(2); }
        else if (c + 1 < nc) CP_WAITG(1);
        else CP_WAITG(0);
        __syncthreads();

        const uint32_t so = sbase + (uint32_t)(c & 3) * STGB;
        const uint32_t sA = so, sB = so + ARR_A;

        #pragma unroll
        for (int ks = 0; ks < 2; ks++) {
            const uint32_t kofs = (ks * 16 + khalf * 8) * 2;
            uint32_t af[2][4];
            #pragma unroll
            for (int mb = 0; mb < 2; mb++) {
                uint32_t ad = a_row_off + mb * 16 * 80 + kofs;
                LDM_X4(af[mb][0], af[mb][1], af[mb][2], af[mb][3], sA + ad);
            }
            #pragma unroll
            for (int nb = 0; nb < NB; nb++) {
                uint32_t bd = b_row_off + nb * 16 * 80 + kofs;
                uint32_t bf_[4];
                LDM_X4(bf_[0], bf_[1], bf_[2], bf_[3], sB + bd);
                #pragma unroll
                for (int mb = 0; mb < 2; mb++) {
                    MMA_F16(acc[mb][nb * 2],     af[mb], bf_[0], bf_[2]);
                    MMA_F16(acc[mb][nb * 2 + 1], af[mb], bf_[1], bf_[3]);
                }
            }
        }
    }
    #undef FILL_STAGE

    const int mrow = m0 + wm * 32 + (lane >> 2);
    const int ncol0 = n0 + wn * WNW + (lane & 3) * 2;
    #pragma unroll
    for (int mb = 0; mb < 2; mb++) {
        #pragma unroll
        for (int nf = 0; nf < NFRAG; nf++) {
            int n = ncol0 + nf * 8;
            float b0v = bias ? bias[n]     : 0.f;
            float b1v = bias ? bias[n + 1] : 0.f;
            float v0 = acc[mb][nf][0] + b0v;
            float v1 = acc[mb][nf][1] + b1v;
            float v2 = acc[mb][nf][2] + b0v;
            float v3 = acc[mb][nf][3] + b1v;
            if (act) { v0 = gelu_f(v0); v1 = gelu_f(v1); v2 = gelu_f(v2); v3 = gelu_f(v3); }
            int m = mrow + mb * 16;
            if (C) {
                *(float2*)(C + (size_t)m * N + n)       = make_float2(v0, v1);
                *(float2*)(C + (size_t)(m + 8) * N + n) = make_float2(v2, v3);
            }
            if (Ch) {
                *(uint32_t*)(Ch + (size_t)m * N + n)       = hpk2(v0, v1);
                *(uint32_t*)(Ch + (size_t)(m + 8) * N + n) = hpk2(v2, v3);
            }
        }
    }
}

// ==================== flash attention (fp16, 64-key tiles, 3-stage, 1 barrier/kt) ====================
#define FA_Q     0
#define FA_STG0  18432
#define FA_K     0
#define FA_V     9216
#define FA_MSK   18432
#define FA_STGSZ 18688
#define FA_SMEM  (18432 + 3 * 18688)   // 74496

__global__ __launch_bounds__(256, 2) void flash_attn(
    const __half* __restrict__ qkv, const float* __restrict__ maskg,
    __half* __restrict__ ch)
{
    extern __shared__ __align__(128) char smem_raw[];
    const uint32_t base = smem_to_u32(smem_raw);
    const uint32_t sQ = base + FA_Q;

    const int tid = threadIdx.x, lane = tid & 31, wid = tid >> 5;
    const int q0 = blockIdx.x * 128;
    const int z = blockIdx.y, b = z >> 4, h = z & 15;
    const uint32_t lrow = lane & 15, khalf = lane >> 4;
    const int cpos = (lane & 3) * 2;
    const int colQ = h * 64, colK = 1024 + h * 64, colV = 2048 + h * 64;

    #pragma unroll
    for (int i = 0; i < 2; i++) {
        int idx = tid + i * 256;
        int row = idx >> 2, seg2 = (idx & 3) * 2;
        size_t src = (size_t)(b * SS + q0 + row) * NQKV + colQ + seg2 * 8;
        CP_ASYNC16(sQ + row * 144 + seg2 * 16, qkv + src);
        CP_ASYNC16(sQ + row * 144 + seg2 * 16 + 16, qkv + src + 8);
    }
    CP_COMMIT();

    #define FA_FILL(kt_) do { \
        const int stg_ = (kt_) % 3; \
        const uint32_t sb_ = base + FA_STG0 + stg_ * FA_STGSZ; \
        const int k0_ = (kt_) * 64; \
        { int row_ = tid >> 2, s2_ = tid & 3; \
          size_t srck_ = (size_t)(b * SS + k0_ + row_) * NQKV + colK + s2_ * 16; \
          uint32_t dstk_ = sb_ + FA_K + row_ * 144 + s2_ * 32; \
          CP_ASYNC16(dstk_, qkv + srck_); \
          CP_ASYNC16(dstk_ + 16, qkv + srck_ + 8); \
          size_t srcv_ = (size_t)(b * SS + k0_ + row_) * NQKV + colV + s2_ * 16; \
          uint32_t dstv_ = sb_ + FA_V + row_ * 144 + s2_ * 32; \
          CP_ASYNC16(dstv_, qkv + srcv_); \
          CP_ASYNC16(dstv_ + 16, qkv + srcv_ + 8); } \
        if (tid < 16) \
            CP_ASYNC16(sb_ + FA_MSK + tid * 16, maskg + b * SS + k0_ + tid * 4); \
        CP_COMMIT(); \
    } while (0)

    FA_FILL(0);
    FA_FILL(1);

    float m0 = -3.0e38f, m1 = -3.0e38f, l0 = 0.f, l1 = 0.f;
    float O[8][4];
    #pragma unroll
    for (int i = 0; i < 8; i++)
        #pragma unroll
        for (int j = 0; j < 4; j++) O[i][j] = 0.f;

    uint32_t qf[4][4];

    for (int kt = 0; kt < 16; kt++) {
        if (kt + 2 < 16) { FA_FILL(kt + 2); CP_WAITG(2); }
        else if (kt + 1 < 16) CP_WAITG(1);
        else CP_WAITG(0);
        __syncthreads();

        const uint32_t sb = base + FA_STG0 + (uint32_t)(kt % 3) * FA_STGSZ;
        const uint32_t sK = sb + FA_K, sV = sb + FA_V;
        const float* maskf = (const float*)(smem_raw + FA_STG0 + (kt % 3) * FA_STGSZ + FA_MSK);

        if (kt == 0) {
            #pragma unroll
            for (int ks = 0; ks < 4; ks++) {
                uint32_t ad = (wid * 16 + lrow) * 144 + (ks * 16 + khalf * 8) * 2;
                LDM_X4(qf[ks][0], qf[ks][1], qf[ks][2], qf[ks][3], sQ + ad);
            }
        }

        float Sv[8][4];
        #pragma unroll
        for (int i = 0; i < 8; i++)
            #pragma unroll
            for (int j = 0; j < 4; j++) Sv[i][j] = 0.f;

        #pragma unroll
        for (int ks = 0; ks < 4; ks++) {
            #pragma unroll
            for (int ng = 0; ng < 4; ng++) {
                uint32_t bd = (ng * 16 + lrow) * 144 + (ks * 16 + khalf * 8) * 2;
                uint32_t bh_[4];
                LDM_X4(bh_[0], bh_[1], bh_[2], bh_[3], sK + bd);
                MMA_F16(Sv[2 * ng],     qf[ks], bh_[0], bh_[2]);
                MMA_F16(Sv[2 * ng + 1], qf[ks], bh_[1], bh_[3]);
            }
        }

        float mt0 = -3.0e38f, mt1 = -3.0e38f;
        #pragma unroll
        for (int nb = 0; nb < 8; nb++) {
            float mk0 = maskf[nb * 8 + cpos], mk1 = maskf[nb * 8 + cpos + 1];
            Sv[nb][0] = Sv[nb][0] * 0.125f + mk0;
            Sv[nb][1] = Sv[nb][1] * 0.125f + mk1;
            Sv[nb][2] = Sv[nb][2] * 0.125f + mk0;
            Sv[nb][3] = Sv[nb][3] * 0.125f + mk1;
            mt0 = fmaxf(mt0, fmaxf(Sv[nb][0], Sv[nb][1]));
            mt1 = fmaxf(mt1, fmaxf(Sv[nb][2], Sv[nb][3]));
        }
        mt0 = fmaxf(mt0, __shfl_xor_sync(0xffffffffu, mt0, 1));
        mt0 = fmaxf(mt0, __shfl_xor_sync(0xffffffffu, mt0, 2));
        mt1 = fmaxf(mt1, __shfl_xor_sync(0xffffffffu, mt1, 1));
        mt1 = fmaxf(mt1, __shfl_xor_sync(0xffffffffu, mt1, 2));

        float mn0 = fmaxf(m0, mt0), mn1 = fmaxf(m1, mt1);
        float al0 = __expf(m0 - mn0), al1 = __expf(m1 - mn1);
        float su0 = 0.f, su1 = 0.f;
        #pragma unroll
        for (int nb = 0; nb < 8; nb++) {
            Sv[nb][0] = __expf(Sv[nb][0] - mn0);
            Sv[nb][1] = __expf(Sv[nb][1] - mn0);
            Sv[nb][2] = __expf(Sv[nb][2] - mn1);
            Sv[nb][3] = __expf(Sv[nb][3] - mn1);
            su0 += Sv[nb][0] + Sv[nb][1];
            su1 += Sv[nb][2] + Sv[nb][3];
        }
        su0 += __shfl_xor_sync(0xffffffffu, su0, 1);
        su0 += __shfl_xor_sync(0xffffffffu, su0, 2);
        su1 += __shfl_xor_sync(0xffffffffu, su1, 1);
        su1 += __shfl_xor_sync(0xffffffffu, su1, 2);

        l0 = l0 * al0 + su0;
        l1 = l1 * al1 + su1;
        m0 = mn0; m1 = mn1;
        #pragma unroll
        for (int nf = 0; nf < 8; nf++) {
            O[nf][0] *= al0; O[nf][1] *= al0;
            O[nf][2] *= al1; O[nf][3] *= al1;
        }

        #pragma unroll
        for (int j = 0; j < 4; j++) {
            uint32_t pa[4];
            pa[0] = hpk2(Sv[2*j][0],   Sv[2*j][1]);
            pa[1] = hpk2(Sv[2*j][2],   Sv[2*j][3]);
            pa[2] = hpk2(Sv[2*j+1][0], Sv[2*j+1][1]);
            pa[3] = hpk2(Sv[2*j+1][2], Sv[2*j+1][3]);
            #pragma unroll
            for (int ng = 0; ng < 4; ng++) {
                uint32_t bd = sV + (j * 16 + lrow) * 144 + (ng * 16 + khalf * 8) * 2;
                uint32_t v0, v1, v2, v3;
                LDM_X4_T(v0, v1, v2, v3, bd);
                MMA_F16(O[2 * ng],     pa, v0, v1);
                MMA_F16(O[2 * ng + 1], pa, v2, v3);
            }
        }
    }
    #undef FA_FILL

    float i0 = 1.f / l0, i1 = 1.f / l1;
    const int rgl = b * SS + q0 + wid * 16 + (lane >> 2);
    #pragma unroll
    for (int nf = 0; nf < 8; nf++) {
        int col = h * 64 + nf * 8 + cpos;
        size_t o0 = (size_t)rgl * HDD + col;
        size_t o1 = (size_t)(rgl + 8) * HDD + col;
        *(uint32_t*)(ch + o0) = hpk2(O[nf][0] * i0, O[nf][1] * i0);
        *(uint32_t*)(ch + o1) = hpk2(O[nf][2] * i1, O[nf][3] * i1);
    }
}

// ==================== embed + add_ln ====================
__global__ __launch_bounds__(256) void embed_kernel(
    const int* __restrict__ tok, const float* __restrict__ emb,
    float* __restrict__ x, __half* __restrict__ xh)
{
    int row = blockIdx.x;
    int s = row % SS;
    int t = tok[row];
    const float* e = emb + (size_t)t * DD;
    for (int d = threadIdx.x; d < DD; d += 256) {
        int i = d >> 1;
        float freq = expf(-((float)(2 * i) / (float)DD) * 9.210340371976184f);
        float a = (float)s * freq;
        float pe = (d & 1) ? cosf(a) : sinf(a);
        float v = e[d] + pe;
        size_t o = (size_t)row * DD + d;
        x[o] = v;
        xh[o] = __float2half_rn(v);
    }
}

__device__ __forceinline__ float block_sum(float v, float* sh) {
    __syncthreads();
    #pragma unroll
    for (int o = 16; o > 0; o >>= 1) v += __shfl_xor_sync(0xffffffffu, v, o);
    int w = threadIdx.x >> 5;
    if ((threadIdx.x & 31) == 0) sh[w] = v;
    __syncthreads();
    float t = (threadIdx.x < 8) ? sh[threadIdx.x] : 0.0f;
    #pragma unroll
    for (int o = 4; o > 0; o >>= 1) t += __shfl_xor_sync(0xffffffffu, t, o);
    if (threadIdx.x == 0) sh[0] = t;
    __syncthreads();
    return sh[0];
}

__global__ __launch_bounds__(256) void add_ln(
    const float* __restrict__ xin, const float* __restrict__ delta,
    const float* __restrict__ g, const float* __restrict__ bta,
    float* __restrict__ out, __half* __restrict__ oh)
{
    size_t row = blockIdx.x;
    const float* xr = xin   + row * DD;
    const float* dr = delta + row * DD;
    int tid = threadIdx.x;
    __shared__ float red[8];

    float v[4];
    float s = 0.f;
    #pragma unroll
    for (int j = 0; j < 4; j++) {
        int c = tid + j * 256;
        v[j] = xr[c] + dr[c];
        s += v[j];
    }
    s = block_sum(s, red);
    float mu = s * (1.0f / 1024.0f);
    float var = 0.f;
    #pragma unroll
    for (int j = 0; j < 4; j++) { float t = v[j] - mu; var += t * t; }
    var = block_sum(var, red) * (1.0f / 1024.0f);
    float inv = rsqrtf(var + 1e-5f);
    #pragma unroll
    for (int j = 0; j < 4; j++) {
        int c = tid + j * 256;
        float o = (v[j] - mu) * inv * g[c] + bta[c];
        size_t idx = row * DD + c;
        out[idx] = o;
        oh[idx] = __float2half_rn(o);
    }
}

// ==================== host orchestration ====================
extern "C" void kernel_launch(void* const* d_in, const int* in_sizes, int n_in,
                              void* d_out, int out_size)
{
    (void)in_sizes; (void)n_in; (void)out_size;
    const int*   tok  = (const int*)  d_in[0];
    const float* emb  = (const float*)d_in[1];
    const float* Wq   = (const float*)d_in[2];
    const float* bq   = (const float*)d_in[3];
    const float* Wk   = (const float*)d_in[4];
    const float* bk   = (const float*)d_in[5];
    const float* Wv   = (const float*)d_in[6];
    const float* bv   = (const float*)d_in[7];
    const float* Wo   = (const float*)d_in[8];
    const float* bo   = (const float*)d_in[9];
    const float* ln1g = (const float*)d_in[10];
    const float* ln1b = (const float*)d_in[11];
    const float* W1   = (const float*)d_in[12];
    const float* W2   = (const float*)d_in[13];
    const float* ln2g = (const float*)d_in[14];
    const float* ln2b = (const float*)d_in[15];
    float* out = (float*)d_out;

    float *x, *tmp, *bqkv, *maskg;
    __half *xh, *qkv, *ch, *fh, *wh;
    cudaGetSymbolAddress((void**)&x,     g_x);
    cudaGetSymbolAddress((void**)&tmp,   g_tmp);
    cudaGetSymbolAddress((void**)&maskg, g_maskf);
    cudaGetSymbolAddress((void**)&xh,    g_xh);
    cudaGetSymbolAddress((void**)&qkv,   g_qkv);
    cudaGetSymbolAddress((void**)&ch,    g_ch);
    cudaGetSymbolAddress((void**)&fh,    g_fh);
    cudaGetSymbolAddress((void**)&wh,    g_wh);
    cudaGetSymbolAddress((void**)&bqkv,  g_bqkv);

    const int GSM128 = 4 * (128 * 80 + ARR_B);   // 81920
    const int GSM64  = 4 * (64 * 80 + ARR_B);    // 61440

    static int attr_done = 0;
    static cudaStream_t s2;
    static cudaEvent_t evFork, evJoin;
    if (!attr_done) {
        cudaFuncSetAttribute(gemm_mma<128>, cudaFuncAttributeMaxDynamicSharedMemorySize, GSM128);
        cudaFuncSetAttribute(gemm_mma<64>,  cudaFuncAttributeMaxDynamicSharedMemorySize, GSM64);
        cudaFuncSetAttribute(flash_attn, cudaFuncAttributeMaxDynamicSharedMemorySize, FA_SMEM);
        cudaStreamCreateWithFlags(&s2, cudaStreamNonBlocking);
        cudaEventCreateWithFlags(&evFork, cudaEventDisableTiming);
        cudaEventCreateWithFlags(&evJoin, cudaEventDisableTiming);
        attr_done = 1;
    }

    // prep on main stream (needed before first QKV gemm)
    mask_kernel<<<MR / 256, 256>>>(tok, maskg);
    biascat_kernel<<<LL * NQKV / 256, 256>>>(bq, bk, bv, bqkv);
    embed_kernel<<<MR, 256>>>(tok, emb, x, xh);
    tsplit_qkv<<<dim3(HDD/64, DD/64, LL*3), 256>>>(Wq, Wk, Wv, wh + WQKV_OFF);

    // fork: Wo/W1/W2 transposes overlap with layer-0 QKV gemm + flash
    cudaEventRecord(evFork, 0);
    cudaStreamWaitEvent(s2, evFork, 0);
    tsplit_b<<<dim3(DD/64, HDD/64, LL), 256, 0, s2>>>(Wo, wh + WOT_OFF, HDD, DD);
    tsplit_b<<<dim3(FF/64, DD/64, LL), 256, 0, s2>>>(W1, wh + W1T_OFF, DD, FF);
    tsplit_b<<<dim3(DD/64, FF/64, LL), 256, 0, s2>>>(W2, wh + W2T_OFF, FF, DD);
    cudaEventRecord(evJoin, s2);

    dim3 gQKV(NQKV/128, MR/64);    // 24 x 32 (MT=64)
    dim3 gWo(DD/128, MR/64);
    dim3 gF1(FF/128, MR/128);
    dim3 gF2(DD/128, MR/64);
    dim3 gFA(SS/128, BB*HH);

    for (int l = 0; l < LL; l++) {
        const __half* wqkv = wh + WQKV_OFF + (size_t)l * 3 * SZ_P;
        const __half* woh  = wh + WOT_OFF + (size_t)l * SZ_P;
        const __half* w1h  = wh + W1T_OFF + (size_t)l * SZ_F;
        const __half* w2h  = wh + W2T_OFF + (size_t)l * SZ_F;

        gemm_mma<64><<<gQKV, 256, GSM64>>>(xh, wqkv, bqkv + (size_t)l*NQKV,
                                           (float*)nullptr, qkv, DD, NQKV, 0);

        flash_attn<<<gFA, 256, FA_SMEM>>>(qkv, maskg, ch);

        if (l == 0) cudaStreamWaitEvent(0, evJoin, 0);

        gemm_mma<64><<<gWo, 256, GSM64>>>(ch, woh, bo + (size_t)l*DD,
                                          tmp, (__half*)nullptr, HDD, DD, 0);
        add_ln<<<MR, 256>>>(x, tmp, ln1g + (size_t)l*DD, ln1b + (size_t)l*DD, x, xh);

        gemm_mma<128><<<gF1, 256, GSM128>>>(xh, w1h, (const float*)nullptr,
                                            (float*)nullptr, fh, DD, FF, 1);
        gemm_mma<64><<<gF2, 256, GSM64>>>(fh, w2h, (const float*)nullptr,
                                          tmp, (__half*)nullptr, FF, DD, 0);

        float* dst = (l == LL - 1) ? out : x;
        add_ln<<<MR, 256>>>(x, tmp, ln2g + (size_t)l*DD, ln2b + (size_t)l*DD, dst, xh);
    }
}

// round 12
// speedup vs baseline: 7.0593x; 1.0172x over previous
#include <cuda_runtime.h>
#include <cuda_fp16.h>
#include <math.h>
#include <stdint.h>

#define BB   2
#define SS   1024
#define DD   1024
#define HH   16
#define HDD  1024
#define FF   4096
#define LL   4
#define MR   (BB*SS)
#define NQKV 3072

// -------------------- scratch --------------------
__device__ float g_x  [MR * DD];
__device__ float g_tmp[MR * DD];
__device__ float g_maskf[MR];
__device__ __half g_xh[MR * DD];
__device__ __half g_qkv[(size_t)MR * NQKV];
__device__ __half g_ch[MR * HDD];
__device__ __half g_fh[(size_t)MR * FF];
__device__ float g_bqkv[LL * NQKV];

#define SZ_P ((size_t)HDD * DD)
#define SZ_F ((size_t)DD * FF)
#define WQKV_OFF ((size_t)0)
#define WOT_OFF  ((size_t)LL * 3 * SZ_P)
#define W1T_OFF  (WOT_OFF + (size_t)LL * SZ_P)
#define W2T_OFF  (W1T_OFF + (size_t)LL * SZ_F)
#define WT_TOTAL (W2T_OFF + (size_t)LL * SZ_F)
__device__ __half g_wh[WT_TOTAL];

// ==================== helpers ====================
__device__ __forceinline__ uint32_t smem_to_u32(const void* p) {
    uint32_t a;
    asm("{ .reg .u64 t; cvta.to.shared.u64 t, %1; cvt.u32.u64 %0, t; }" : "=r"(a) : "l"(p));
    return a;
}
#define CP_ASYNC16(dst, src) \
    asm volatile("cp.async.cg.shared.global [%0], [%1], 16;" \
        :: "r"((uint32_t)(dst)), "l"(__cvta_generic_to_global(src)) : "memory")
#define CP_COMMIT() asm volatile("cp.async.commit_group;" ::: "memory")
#define CP_WAITG(n) asm volatile("cp.async.wait_group %0;" :: "n"(n) : "memory")
#define LDM_X4(r0, r1, r2, r3, addr) \
    asm volatile("ldmatrix.sync.aligned.m8n8.x4.shared.b16 {%0,%1,%2,%3}, [%4];" \
        : "=r"(r0), "=r"(r1), "=r"(r2), "=r"(r3) : "r"(addr))
#define LDM_X4_T(r0, r1, r2, r3, addr) \
    asm volatile("ldmatrix.sync.aligned.m8n8.x4.trans.shared.b16 {%0,%1,%2,%3}, [%4];" \
        : "=r"(r0), "=r"(r1), "=r"(r2), "=r"(r3) : "r"(addr))
#define MMA_F16(acc, a, b0, b1) \
    asm volatile("mma.sync.aligned.m16n8k16.row.col.f32.f16.f16.f32 " \
        "{%0,%1,%2,%3},{%4,%5,%6,%7},{%8,%9},{%0,%1,%2,%3};" \
        : "+f"((acc)[0]), "+f"((acc)[1]), "+f"((acc)[2]), "+f"((acc)[3]) \
        : "r"((a)[0]), "r"((a)[1]), "r"((a)[2]), "r"((a)[3]), "r"(b0), "r"(b1))

__device__ __forceinline__ uint32_t hpk2(float a, float b) {
    __half2 t = __floats2half2_rn(a, b);
    return *reinterpret_cast<uint32_t*>(&t);
}
__device__ __forceinline__ float gelu_f(float v) {
    float x = v * 0.70710678118654752f;
    float ax = fabsf(x);
    float t = __fdividef(1.0f, fmaf(0.3275911f, ax, 1.0f));
    float p = t * fmaf(t, fmaf(t, fmaf(t, fmaf(t, 1.061405429f, -1.453152027f),
                               1.421413741f), -0.284496736f), 0.254829592f);
    float erfv = 1.0f - p * __expf(-ax * ax);
    erfv = copysignf(erfv, x);
    return 0.5f * v * (1.0f + erfv);
}

// ==================== batched weight transpose ====================
__device__ __forceinline__ void tsplit_body(
    const float* __restrict__ W, __half* __restrict__ th, int K, int N)
{
    __shared__ float ts[64][65];
    const int n0 = blockIdx.x * 64, k0 = blockIdx.y * 64;
    const int tid = threadIdx.x;
    #pragma unroll
    for (int i = 0; i < 4; i++) {
        int e = tid + i * 256;
        int r = e >> 4, c4 = (e & 15) * 4;
        float4 v = *(const float4*)&W[(size_t)(k0 + r) * N + n0 + c4];
        ts[r][c4]     = v.x; ts[r][c4 + 1] = v.y;
        ts[r][c4 + 2] = v.z; ts[r][c4 + 3] = v.w;
    }
    __syncthreads();
    const int w = tid >> 5, lane = tid & 31;
    #pragma unroll
    for (int rr = 0; rr < 8; rr++) {
        int n = w * 8 + rr;
        float a = ts[lane * 2][n], b = ts[lane * 2 + 1][n];
        size_t o = (size_t)(n0 + n) * K + k0 + lane * 2;
        *(uint32_t*)&th[o] = hpk2(a, b);
    }
}

__global__ __launch_bounds__(256) void tsplit_qkv(
    const float* __restrict__ Wq, const float* __restrict__ Wk,
    const float* __restrict__ Wv, __half* __restrict__ th)
{
    int z = blockIdx.z;
    int l = z / 3, j = z - l * 3;
    const float* W = ((j == 0) ? Wq : (j == 1) ? Wk : Wv) + (size_t)l * SZ_P;
    __half* dst = th + ((size_t)l * 3 + j) * SZ_P;
    tsplit_body(W, dst, DD, HDD);
}

__global__ __launch_bounds__(256) void tsplit_b(
    const float* __restrict__ W, __half* __restrict__ th, int K, int N)
{
    size_t off = (size_t)blockIdx.z * K * N;
    tsplit_body(W + off, th + off, K, N);
}

__global__ void biascat_kernel(const float* __restrict__ bq, const float* __restrict__ bk,
                               const float* __restrict__ bv, float* __restrict__ o)
{
    int i = blockIdx.x * 256 + threadIdx.x;
    int l = i / NQKV, r = i % NQKV;
    int seg = r >> 10, n = r & 1023;
    const float* s = (seg == 0) ? bq : (seg == 1) ? bk : bv;
    o[i] = s[l * 1024 + n];
}

__global__ void mask_kernel(const int* __restrict__ tok, float* __restrict__ m)
{
    int i = blockIdx.x * 256 + threadIdx.x;
    m[i] = (tok[i] == 0) ? -1e9f : 0.f;
}

// ==================== fp16 HMMA GEMM, single-barrier 4-slot pipeline ====================
#define KC 32
#define ARR_B 10240

template<int MT>
__global__ __launch_bounds__(256, 2) void gemm_mma(
    const __half* __restrict__ A, const __half* __restrict__ B,
    const float* __restrict__ bias, float* __restrict__ C,
    __half* __restrict__ Ch, int K, int N, int act)
{
    constexpr uint32_t ARR_A = (uint32_t)MT * 80;
    constexpr uint32_t STGB  = ARR_A + ARR_B;
    constexpr int AITER = MT / 64;
    constexpr int NFRAG = (MT == 128) ? 8 : 4;
    constexpr int NB    = NFRAG / 2;
    constexpr int WNW   = (MT == 128) ? 64 : 32;

    extern __shared__ __align__(128) char smem_raw[];
    const uint32_t sbase = smem_to_u32(smem_raw);

    const int tid  = threadIdx.x;
    const int lane = tid & 31;
    const int wid  = tid >> 5;
    const int wm   = (MT == 128) ? (wid & 3) : (wid & 1);
    const int wn   = (MT == 128) ? (wid >> 2) : (wid >> 1);
    const int m0 = blockIdx.y * MT, n0 = blockIdx.x * 128;

    float acc[2][NFRAG][4];
    #pragma unroll
    for (int i = 0; i < 2; i++)
        #pragma unroll
        for (int j = 0; j < NFRAG; j++)
            #pragma unroll
            for (int q2 = 0; q2 < 4; q2++) acc[i][j][q2] = 0.f;

    const int nc = K >> 5;

    #define FILL_STAGE(stg, kk) do { \
        const uint32_t so_ = sbase + (uint32_t)(stg) * STGB; \
        _Pragma("unroll") \
        for (int i_ = 0; i_ < AITER + 2; i_++) { \
            const int isA_ = (i_ < AITER); \
            int rem_ = (isA_ ? i_ : (i_ - AITER)) * 256 + tid; \
            int row_ = rem_ >> 2, seg_ = rem_ & 3; \
            const __half* p_ = isA_ ? A : B; \
            int rb_ = isA_ ? m0 : n0; \
            uint32_t dst_ = so_ + (isA_ ? 0u : ARR_A) + row_ * 80 + seg_ * 16; \
            CP_ASYNC16(dst_, p_ + (size_t)(rb_ + row_) * K + (kk) + seg_ * 8); \
        } \
        CP_COMMIT(); \
    } while (0)

    FILL_STAGE(0, 0);
    FILL_STAGE(1, KC);

    const uint32_t lrow  = lane & 15;
    const uint32_t khalf = lane >> 4;
    const uint32_t a_row_off = (wm * 32 + lrow) * 80;
    const uint32_t b_row_off = (wn * WNW + lrow) * 80;

    for (int c = 0; c < nc; c++) {
        if (c + 2 < nc) { FILL_STAGE((c + 2) & 3, (c + 2) * KC); CP_WAITG(2); }
        else if (c + 1 < nc) CP_WAITG(1);
        else CP_WAITG(0);
        __syncthreads();

        const uint32_t so = sbase + (uint32_t)(c & 3) * STGB;
        const uint32_t sA = so, sB = so + ARR_A;

        #pragma unroll
        for (int ks = 0; ks < 2; ks++) {
            const uint32_t kofs = (ks * 16 + khalf * 8) * 2;
            uint32_t af[2][4];
            #pragma unroll
            for (int mb = 0; mb < 2; mb++) {
                uint32_t ad = a_row_off + mb * 16 * 80 + kofs;
                LDM_X4(af[mb][0], af[mb][1], af[mb][2], af[mb][3], sA + ad);
            }
            #pragma unroll
            for (int nb = 0; nb < NB; nb++) {
                uint32_t bd = b_row_off + nb * 16 * 80 + kofs;
                uint32_t bf_[4];
                LDM_X4(bf_[0], bf_[1], bf_[2], bf_[3], sB + bd);
                #pragma unroll
                for (int mb = 0; mb < 2; mb++) {
                    MMA_F16(acc[mb][nb * 2],     af[mb], bf_[0], bf_[2]);
                    MMA_F16(acc[mb][nb * 2 + 1], af[mb], bf_[1], bf_[3]);
                }
            }
        }
    }
    #undef FILL_STAGE

    const int mrow = m0 + wm * 32 + (lane >> 2);
    const int ncol0 = n0 + wn * WNW + (lane & 3) * 2;
    #pragma unroll
    for (int mb = 0; mb < 2; mb++) {
        #pragma unroll
        for (int nf = 0; nf < NFRAG; nf++) {
            int n = ncol0 + nf * 8;
            float b0v = bias ? bias[n]     : 0.f;
            float b1v = bias ? bias[n + 1] : 0.f;
            float v0 = acc[mb][nf][0] + b0v;
            float v1 = acc[mb][nf][1] + b1v;
            float v2 = acc[mb][nf][2] + b0v;
            float v3 = acc[mb][nf][3] + b1v;
            if (act) { v0 = gelu_f(v0); v1 = gelu_f(v1); v2 = gelu_f(v2); v3 = gelu_f(v3); }
            int m = mrow + mb * 16;
            if (C) {
                *(float2*)(C + (size_t)m * N + n)       = make_float2(v0, v1);
                *(float2*)(C + (size_t)(m + 8) * N + n) = make_float2(v2, v3);
            }
            if (Ch) {
                *(uint32_t*)(Ch + (size_t)m * N + n)       = hpk2(v0, v1);
                *(uint32_t*)(Ch + (size_t)(m + 8) * N + n) = hpk2(v2, v3);
            }
        }
    }
}

// ==================== flash attention (fp16, 64-key tiles, 3-stage, 1 barrier/kt) ====================
#define FA_Q     0
#define FA_STG0  18432
#define FA_K     0
#define FA_V     9216
#define FA_MSK   18432
#define FA_STGSZ 18688
#define FA_SMEM  (18432 + 3 * 18688)   // 74496

__global__ __launch_bounds__(256, 2) void flash_attn(
    const __half* __restrict__ qkv, const float* __restrict__ maskg,
    __half* __restrict__ ch)
{
    extern __shared__ __align__(128) char smem_raw[];
    const uint32_t base = smem_to_u32(smem_raw);
    const uint32_t sQ = base + FA_Q;

    const int tid = threadIdx.x, lane = tid & 31, wid = tid >> 5;
    const int q0 = blockIdx.x * 128;
    const int z = blockIdx.y, b = z >> 4, h = z & 15;
    const uint32_t lrow = lane & 15, khalf = lane >> 4;
    const int cpos = (lane & 3) * 2;
    const int colQ = h * 64, colK = 1024 + h * 64, colV = 2048 + h * 64;

    #pragma unroll
    for (int i = 0; i < 2; i++) {
        int idx = tid + i * 256;
        int row = idx >> 2, seg2 = (idx & 3) * 2;
        size_t src = (size_t)(b * SS + q0 + row) * NQKV + colQ + seg2 * 8;
        CP_ASYNC16(sQ + row * 144 + seg2 * 16, qkv + src);
        CP_ASYNC16(sQ + row * 144 + seg2 * 16 + 16, qkv + src + 8);
    }
    CP_COMMIT();

    #define FA_FILL(kt_) do { \
        const int stg_ = (kt_) % 3; \
        const uint32_t sb_ = base + FA_STG0 + stg_ * FA_STGSZ; \
        const int k0_ = (kt_) * 64; \
        { int row_ = tid >> 2, s2_ = tid & 3; \
          size_t srck_ = (size_t)(b * SS + k0_ + row_) * NQKV + colK + s2_ * 16; \
          uint32_t dstk_ = sb_ + FA_K + row_ * 144 + s2_ * 32; \
          CP_ASYNC16(dstk_, qkv + srck_); \
          CP_ASYNC16(dstk_ + 16, qkv + srck_ + 8); \
          size_t srcv_ = (size_t)(b * SS + k0_ + row_) * NQKV + colV + s2_ * 16; \
          uint32_t dstv_ = sb_ + FA_V + row_ * 144 + s2_ * 32; \
          CP_ASYNC16(dstv_, qkv + srcv_); \
          CP_ASYNC16(dstv_ + 16, qkv + srcv_ + 8); } \
        if (tid < 16) \
            CP_ASYNC16(sb_ + FA_MSK + tid * 16, maskg + b * SS + k0_ + tid * 4); \
        CP_COMMIT(); \
    } while (0)

    FA_FILL(0);
    FA_FILL(1);

    float m0 = -3.0e38f, m1 = -3.0e38f, l0 = 0.f, l1 = 0.f;
    float O[8][4];
    #pragma unroll
    for (int i = 0; i < 8; i++)
        #pragma unroll
        for (int j = 0; j < 4; j++) O[i][j] = 0.f;

    uint32_t qf[4][4];

    for (int kt = 0; kt < 16; kt++) {
        if (kt + 2 < 16) { FA_FILL(kt + 2); CP_WAITG(2); }
        else if (kt + 1 < 16) CP_WAITG(1);
        else CP_WAITG(0);
        __syncthreads();

        const uint32_t sb = base + FA_STG0 + (uint32_t)(kt % 3) * FA_STGSZ;
        const uint32_t sK = sb + FA_K, sV = sb + FA_V;
        const float* maskf = (const float*)(smem_raw + FA_STG0 + (kt % 3) * FA_STGSZ + FA_MSK);

        if (kt == 0) {
            #pragma unroll
            for (int ks = 0; ks < 4; ks++) {
                uint32_t ad = (wid * 16 + lrow) * 144 + (ks * 16 + khalf * 8) * 2;
                LDM_X4(qf[ks][0], qf[ks][1], qf[ks][2], qf[ks][3], sQ + ad);
            }
        }

        float Sv[8][4];
        #pragma unroll
        for (int i = 0; i < 8; i++)
            #pragma unroll
            for (int j = 0; j < 4; j++) Sv[i][j] = 0.f;

        #pragma unroll
        for (int ks = 0; ks < 4; ks++) {
            #pragma unroll
            for (int ng = 0; ng < 4; ng++) {
                uint32_t bd = (ng * 16 + lrow) * 144 + (ks * 16 + khalf * 8) * 2;
                uint32_t bh_[4];
                LDM_X4(bh_[0], bh_[1], bh_[2], bh_[3], sK + bd);
                MMA_F16(Sv[2 * ng],     qf[ks], bh_[0], bh_[2]);
                MMA_F16(Sv[2 * ng + 1], qf[ks], bh_[1], bh_[3]);
            }
        }

        float mt0 = -3.0e38f, mt1 = -3.0e38f;
        #pragma unroll
        for (int nb = 0; nb < 8; nb++) {
            float mk0 = maskf[nb * 8 + cpos], mk1 = maskf[nb * 8 + cpos + 1];
            Sv[nb][0] = Sv[nb][0] * 0.125f + mk0;
            Sv[nb][1] = Sv[nb][1] * 0.125f + mk1;
            Sv[nb][2] = Sv[nb][2] * 0.125f + mk0;
            Sv[nb][3] = Sv[nb][3] * 0.125f + mk1;
            mt0 = fmaxf(mt0, fmaxf(Sv[nb][0], Sv[nb][1]));
            mt1 = fmaxf(mt1, fmaxf(Sv[nb][2], Sv[nb][3]));
        }
        mt0 = fmaxf(mt0, __shfl_xor_sync(0xffffffffu, mt0, 1));
        mt0 = fmaxf(mt0, __shfl_xor_sync(0xffffffffu, mt0, 2));
        mt1 = fmaxf(mt1, __shfl_xor_sync(0xffffffffu, mt1, 1));
        mt1 = fmaxf(mt1, __shfl_xor_sync(0xffffffffu, mt1, 2));

        float mn0 = fmaxf(m0, mt0), mn1 = fmaxf(m1, mt1);
        float al0 = __expf(m0 - mn0), al1 = __expf(m1 - mn1);
        float su0 = 0.f, su1 = 0.f;
        #pragma unroll
        for (int nb = 0; nb < 8; nb++) {
            Sv[nb][0] = __expf(Sv[nb][0] - mn0);
            Sv[nb][1] = __expf(Sv[nb][1] - mn0);
            Sv[nb][2] = __expf(Sv[nb][2] - mn1);
            Sv[nb][3] = __expf(Sv[nb][3] - mn1);
            su0 += Sv[nb][0] + Sv[nb][1];
            su1 += Sv[nb][2] + Sv[nb][3];
        }
        su0 += __shfl_xor_sync(0xffffffffu, su0, 1);
        su0 += __shfl_xor_sync(0xffffffffu, su0, 2);
        su1 += __shfl_xor_sync(0xffffffffu, su1, 1);
        su1 += __shfl_xor_sync(0xffffffffu, su1, 2);

        l0 = l0 * al0 + su0;
        l1 = l1 * al1 + su1;
        m0 = mn0; m1 = mn1;
        #pragma unroll
        for (int nf = 0; nf < 8; nf++) {
            O[nf][0] *= al0; O[nf][1] *= al0;
            O[nf][2] *= al1; O[nf][3] *= al1;
        }

        #pragma unroll
        for (int j = 0; j < 4; j++) {
            uint32_t pa[4];
            pa[0] = hpk2(Sv[2*j][0],   Sv[2*j][1]);
            pa[1] = hpk2(Sv[2*j][2],   Sv[2*j][3]);
            pa[2] = hpk2(Sv[2*j+1][0], Sv[2*j+1][1]);
            pa[3] = hpk2(Sv[2*j+1][2], Sv[2*j+1][3]);
            #pragma unroll
            for (int ng = 0; ng < 4; ng++) {
                uint32_t bd = sV + (j * 16 + lrow) * 144 + (ng * 16 + khalf * 8) * 2;
                uint32_t v0, v1, v2, v3;
                LDM_X4_T(v0, v1, v2, v3, bd);
                MMA_F16(O[2 * ng],     pa, v0, v1);
                MMA_F16(O[2 * ng + 1], pa, v2, v3);
            }
        }
    }
    #undef FA_FILL

    float i0 = 1.f / l0, i1 = 1.f / l1;
    const int rgl = b * SS + q0 + wid * 16 + (lane >> 2);
    #pragma unroll
    for (int nf = 0; nf < 8; nf++) {
        int col = h * 64 + nf * 8 + cpos;
        size_t o0 = (size_t)rgl * HDD + col;
        size_t o1 = (size_t)(rgl + 8) * HDD + col;
        *(uint32_t*)(ch + o0) = hpk2(O[nf][0] * i0, O[nf][1] * i0);
        *(uint32_t*)(ch + o1) = hpk2(O[nf][2] * i1, O[nf][3] * i1);
    }
}

// ==================== embed + add_ln ====================
__global__ __launch_bounds__(256) void embed_kernel(
    const int* __restrict__ tok, const float* __restrict__ emb,
    float* __restrict__ x, __half* __restrict__ xh)
{
    int row = blockIdx.x;
    int s = row % SS;
    int t = tok[row];
    const float* e = emb + (size_t)t * DD;
    for (int d = threadIdx.x; d < DD; d += 256) {
        int i = d >> 1;
        float freq = expf(-((float)(2 * i) / (float)DD) * 9.210340371976184f);
        float a = (float)s * freq;
        float pe = (d & 1) ? cosf(a) : sinf(a);
        float v = e[d] + pe;
        size_t o = (size_t)row * DD + d;
        x[o] = v;
        xh[o] = __float2half_rn(v);
    }
}

__device__ __forceinline__ float block_sum(float v, float* sh) {
    __syncthreads();
    #pragma unroll
    for (int o = 16; o > 0; o >>= 1) v += __shfl_xor_sync(0xffffffffu, v, o);
    int w = threadIdx.x >> 5;
    if ((threadIdx.x & 31) == 0) sh[w] = v;
    __syncthreads();
    float t = (threadIdx.x < 8) ? sh[threadIdx.x] : 0.0f;
    #pragma unroll
    for (int o = 4; o > 0; o >>= 1) t += __shfl_xor_sync(0xffffffffu, t, o);
    if (threadIdx.x == 0) sh[0] = t;
    __syncthreads();
    return sh[0];
}

__global__ __launch_bounds__(256) void add_ln(
    const float* __restrict__ xin, const float* __restrict__ delta,
    const float* __restrict__ g, const float* __restrict__ bta,
    float* __restrict__ out, __half* __restrict__ oh)
{
    size_t row = blockIdx.x;
    const float* xr = xin   + row * DD;
    const float* dr = delta + row * DD;
    int tid = threadIdx.x;
    __shared__ float red[8];

    float v[4];
    float s = 0.f;
    #pragma unroll
    for (int j = 0; j < 4; j++) {
        int c = tid + j * 256;
        v[j] = xr[c] + dr[c];
        s += v[j];
    }
    s = block_sum(s, red);
    float mu = s * (1.0f / 1024.0f);
    float var = 0.f;
    #pragma unroll
    for (int j = 0; j < 4; j++) { float t = v[j] - mu; var += t * t; }
    var = block_sum(var, red) * (1.0f / 1024.0f);
    float inv = rsqrtf(var + 1e-5f);
    #pragma unroll
    for (int j = 0; j < 4; j++) {
        int c = tid + j * 256;
        float o = (v[j] - mu) * inv * g[c] + bta[c];
        size_t idx = row * DD + c;
        out[idx] = o;
        if (oh) oh[idx] = __float2half_rn(o);
    }
}

// ==================== host orchestration ====================
extern "C" void kernel_launch(void* const* d_in, const int* in_sizes, int n_in,
                              void* d_out, int out_size)
{
    (void)in_sizes; (void)n_in; (void)out_size;
    const int*   tok  = (const int*)  d_in[0];
    const float* emb  = (const float*)d_in[1];
    const float* Wq   = (const float*)d_in[2];
    const float* bq   = (const float*)d_in[3];
    const float* Wk   = (const float*)d_in[4];
    const float* bk   = (const float*)d_in[5];
    const float* Wv   = (const float*)d_in[6];
    const float* bv   = (const float*)d_in[7];
    const float* Wo   = (const float*)d_in[8];
    const float* bo   = (const float*)d_in[9];
    const float* ln1g = (const float*)d_in[10];
    const float* ln1b = (const float*)d_in[11];
    const float* W1   = (const float*)d_in[12];
    const float* W2   = (const float*)d_in[13];
    const float* ln2g = (const float*)d_in[14];
    const float* ln2b = (const float*)d_in[15];
    float* out = (float*)d_out;

    float *x, *tmp, *bqkv, *maskg;
    __half *xh, *qkv, *ch, *fh, *wh;
    cudaGetSymbolAddress((void**)&x,     g_x);
    cudaGetSymbolAddress((void**)&tmp,   g_tmp);
    cudaGetSymbolAddress((void**)&maskg, g_maskf);
    cudaGetSymbolAddress((void**)&xh,    g_xh);
    cudaGetSymbolAddress((void**)&qkv,   g_qkv);
    cudaGetSymbolAddress((void**)&ch,    g_ch);
    cudaGetSymbolAddress((void**)&fh,    g_fh);
    cudaGetSymbolAddress((void**)&wh,    g_wh);
    cudaGetSymbolAddress((void**)&bqkv,  g_bqkv);

    const int GSM128 = 4 * (128 * 80 + ARR_B);   // 81920
    const int GSM64  = 4 * (64 * 80 + ARR_B);    // 61440

    static int attr_done = 0;
    static cudaStream_t s2;
    static cudaEvent_t evFork, evJoin;
    if (!attr_done) {
        cudaFuncSetAttribute(gemm_mma<128>, cudaFuncAttributeMaxDynamicSharedMemorySize, GSM128);
        cudaFuncSetAttribute(gemm_mma<64>,  cudaFuncAttributeMaxDynamicSharedMemorySize, GSM64);
        cudaFuncSetAttribute(flash_attn, cudaFuncAttributeMaxDynamicSharedMemorySize, FA_SMEM);
        cudaStreamCreateWithFlags(&s2, cudaStreamNonBlocking);
        cudaEventCreateWithFlags(&evFork, cudaEventDisableTiming);
        cudaEventCreateWithFlags(&evJoin, cudaEventDisableTiming);
        attr_done = 1;
    }

    // prep on main stream (needed before first QKV gemm)
    mask_kernel<<<MR / 256, 256>>>(tok, maskg);
    biascat_kernel<<<LL * NQKV / 256, 256>>>(bq, bk, bv, bqkv);
    embed_kernel<<<MR, 256>>>(tok, emb, x, xh);
    tsplit_qkv<<<dim3(HDD/64, DD/64, LL*3), 256>>>(Wq, Wk, Wv, wh + WQKV_OFF);

    // fork: Wo/W1/W2 transposes overlap with layer-0 QKV gemm + flash
    cudaEventRecord(evFork, 0);
    cudaStreamWaitEvent(s2, evFork, 0);
    tsplit_b<<<dim3(DD/64, HDD/64, LL), 256, 0, s2>>>(Wo, wh + WOT_OFF, HDD, DD);
    tsplit_b<<<dim3(FF/64, DD/64, LL), 256, 0, s2>>>(W1, wh + W1T_OFF, DD, FF);
    tsplit_b<<<dim3(DD/64, FF/64, LL), 256, 0, s2>>>(W2, wh + W2T_OFF, FF, DD);
    cudaEventRecord(evJoin, s2);

    dim3 gQKV(NQKV/128, MR/128);   // 24 x 16 (MT=128)
    dim3 gWo(DD/128, MR/64);       // MT=64
    dim3 gF1(FF/128, MR/128);      // MT=128
    dim3 gF2(DD/128, MR/64);       // MT=64
    dim3 gFA(SS/128, BB*HH);

    for (int l = 0; l < LL; l++) {
        const __half* wqkv = wh + WQKV_OFF + (size_t)l * 3 * SZ_P;
        const __half* woh  = wh + WOT_OFF + (size_t)l * SZ_P;
        const __half* w1h  = wh + W1T_OFF + (size_t)l * SZ_F;
        const __half* w2h  = wh + W2T_OFF + (size_t)l * SZ_F;

        gemm_mma<128><<<gQKV, 256, GSM128>>>(xh, wqkv, bqkv + (size_t)l*NQKV,
                                             (float*)nullptr, qkv, DD, NQKV, 0);

        flash_attn<<<gFA, 256, FA_SMEM>>>(qkv, maskg, ch);

        if (l == 0) cudaStreamWaitEvent(0, evJoin, 0);

        gemm_mma<64><<<gWo, 256, GSM64>>>(ch, woh, bo + (size_t)l*DD,
                                          tmp, (__half*)nullptr, HDD, DD, 0);
        add_ln<<<MR, 256>>>(x, tmp, ln1g + (size_t)l*DD, ln1b + (size_t)l*DD, x, xh);

        gemm_mma<128><<<gF1, 256, GSM128>>>(xh, w1h, (const float*)nullptr,
                                            (float*)nullptr, fh, DD, FF, 1);
        gemm_mma<64><<<gF2, 256, GSM64>>>(fh, w2h, (const float*)nullptr,
                                          tmp, (__half*)nullptr, FF, DD, 0);

        float* dst = (l == LL - 1) ? out : x;
        __half* dsth = (l == LL - 1) ? (__half*)nullptr : xh;
        add_ln<<<MR, 256>>>(x, tmp, ln2g + (size_t)l*DD, ln2b + (size_t)l*DD, dst, dsth);
    }
}